// round 2
// baseline (speedup 1.0000x reference)
#include <cuda_runtime.h>
#include <math.h>

#define Bq    4
#define Cc    64
#define Hh    256
#define Ww    256
#define W2    128
#define NPIX  65536   // Hh*Ww
#define NS    32768   // Hh*W2
#define NHEAD 4
#define Dd    16
#define C2    128
#define C4    256

typedef unsigned long long u64;

// ---------------- scratch (device globals; no runtime allocation) ----------------
__device__ float g_qpre[(size_t)Bq*Cc*NPIX];
__device__ float g_kpre[(size_t)Bq*Cc*NPIX];
__device__ float g_vpre[(size_t)Bq*Cc*NPIX];
__device__ float g_qs  [(size_t)Bq*Cc*NS];
__device__ float g_ks  [(size_t)Bq*Cc*NS];
__device__ float g_vs  [(size_t)Bq*Cc*NS];
__device__ float g_atts[(size_t)Bq*Cc*NS];
__device__ float g_ctx_part[16*32*16*16];
__device__ float g_ctx[16*256];
__device__ float g_ma[(size_t)Bq*C4*NPIX];
__device__ float g_mb[(size_t)Bq*C4*NPIX];

__device__ __forceinline__ float gelu_f(float x){
    return 0.5f * x * (1.0f + erff(x * 0.70710678118654752f));
}

// ---- packed fp32x2 helpers (Blackwell FFMA2 path; only reachable via PTX) ----
__device__ __forceinline__ u64 pack2(float v){
    u64 r;
    asm("mov.b64 %0, {%1, %2};" : "=l"(r) : "f"(v), "f"(v));
    return r;
}
__device__ __forceinline__ void unpack2(u64 v, float &lo, float &hi){
    asm("mov.b64 {%0, %1}, %2;" : "=f"(lo), "=f"(hi) : "l"(v));
}
__device__ __forceinline__ void ffma2(u64 &acc, u64 a, u64 b){
    asm("fma.rn.f32x2 %0, %1, %2, %0;" : "+l"(acc) : "l"(a), "l"(b));
}
// one LDS.128 -> two packed b64 weight pairs (addr must be 16B aligned)
__device__ __forceinline__ void lds2(u64 &a, u64 &b, unsigned saddr){
    asm("ld.shared.v2.b64 {%0, %1}, [%2];" : "=l"(a), "=l"(b) : "r"(saddr));
}

// ---------------- K1: 1x1 conv (64->64) with checkerboard input mask ----------------
// mode 0: keep nonanchor ((y+x)%2==0)  [q];  mode 1: keep anchor [k];  mode 2: keep all [v]
__global__ void k_conv1x1_qkv(const float* __restrict__ x, const float* __restrict__ w,
                              const float* __restrict__ bias, float* __restrict__ out, int mode)
{
    __shared__ __align__(16) float wsm[64*64];      // [ci][co], co contiguous
    int tid = threadIdx.x;
    for (int i = tid; i < 4096; i += 256){
        int co = i & 63, ci = i >> 6;
        wsm[ci*64 + co] = w[co*64 + ci];
    }
    __syncthreads();
    unsigned wb = (unsigned)__cvta_generic_to_shared(wsm);
    int b   = blockIdx.y;
    int pos = blockIdx.x*256 + tid;
    const float* xp = x + (size_t)b*Cc*NPIX + pos;

    u64 acc[32];
#pragma unroll
    for (int i = 0; i < 32; i++) acc[i] = 0ull;

    for (int ci = 0; ci < 64; ci++){
        u64 xv = pack2(xp[(size_t)ci*NPIX]);
        unsigned base = wb + ci*256;
#pragma unroll
        for (int k = 0; k < 16; k++){
            u64 w0, w1;
            lds2(w0, w1, base + k*16);
            ffma2(acc[2*k+0], w0, xv);
            ffma2(acc[2*k+1], w1, xv);
        }
    }
    int y = pos >> 8, xc = pos & 255;
    int par = (y ^ xc) & 1;                        // 0 = nonanchor, 1 = anchor
    bool keep = (mode == 2) || (mode == 0 ? par == 0 : par == 1);
    float* op = out + (size_t)b*Cc*NPIX + pos;
#pragma unroll
    for (int i = 0; i < 32; i++){
        float lo, hi; unpack2(acc[i], lo, hi);
        int co = 2*i;
        op[(size_t)(co+0)*NPIX] = keep ? lo + bias[co+0] : bias[co+0];
        op[(size_t)(co+1)*NPIX] = keep ? hi + bias[co+1] : bias[co+1];
    }
}

// ---------------- K2: depthwise 3x3 (pad 1) evaluated only at one parity, stored squeezed ----------------
__global__ void k_dw3x3_squeeze(const float* __restrict__ in, const float* __restrict__ w,
                                const float* __restrict__ bias, float* __restrict__ out, int anchorSel)
{
    int idx = blockIdx.x*256 + threadIdx.x;        // over B*C*H*W2
    int j = idx & (W2-1);
    int r = (idx >> 7) & (Hh-1);
    int c = (idx >> 15) & (Cc-1);
    int b = idx >> 21;
    int col = 2*j + (anchorSel ? (1 - (r & 1)) : (r & 1));
    const float* ip = in + ((size_t)(b*Cc + c))*NPIX;
    const float* wp = w + c*9;
    float s = bias[c];
#pragma unroll
    for (int dy = -1; dy <= 1; dy++){
        int rr = r + dy;
        if ((unsigned)rr < Hh){
#pragma unroll
            for (int dx = -1; dx <= 1; dx++){
                int cc = col + dx;
                if ((unsigned)cc < Ww)
                    s += wp[(dy+1)*3 + (dx+1)] * ip[rr*Ww + cc];
            }
        }
    }
    out[idx] = s;
}

// ---------------- K3: q softmax over d=16 (within head), in-place on squeezed q ----------------
__global__ void k_softmax_d(float* __restrict__ q)
{
    int idx = blockIdx.x*256 + threadIdx.x;        // over B*NHEAD*NS
    int n  = idx & (NS-1);
    int hd = (idx >> 15) & (NHEAD-1);
    int b  = idx >> 17;
    float* p = q + ((size_t)(b*Cc + hd*Dd))*NS + n;
    float v[16];
    float mx = -1e30f;
#pragma unroll
    for (int d = 0; d < 16; d++){ v[d] = p[(size_t)d*NS]; mx = fmaxf(mx, v[d]); }
    float s = 0.f;
#pragma unroll
    for (int d = 0; d < 16; d++){ v[d] = __expf(v[d]-mx); s += v[d]; }
    float inv = 1.f/s;
#pragma unroll
    for (int d = 0; d < 16; d++) p[(size_t)d*NS] = v[d]*inv;
}

// ---------------- K4: k softmax over N=32768 per (b,c) row, in-place ----------------
__global__ void k_softmax_n(float* __restrict__ kk)
{
    int row = blockIdx.x;                          // B*C = 256 rows
    float* p = kk + (size_t)row*NS;
    int tid = threadIdx.x;
    __shared__ float red[256];
    float mx = -1e30f;
    for (int i = tid; i < NS; i += 256) mx = fmaxf(mx, p[i]);
    red[tid] = mx; __syncthreads();
    for (int s = 128; s > 0; s >>= 1){ if (tid < s) red[tid] = fmaxf(red[tid], red[tid+s]); __syncthreads(); }
    mx = red[0]; __syncthreads();
    float sum = 0.f;
    for (int i = tid; i < NS; i += 256) sum += __expf(p[i]-mx);
    red[tid] = sum; __syncthreads();
    for (int s = 128; s > 0; s >>= 1){ if (tid < s) red[tid] += red[tid+s]; __syncthreads(); }
    float inv = 1.f/red[0];
    for (int i = tid; i < NS; i += 256) p[i] = __expf(p[i]-mx)*inv;
}

// ---------------- K5: ctx partials: ctx[d][e] = sum_n ksm[d,n]*vs[e,n] ----------------
__global__ void k_ctx_part(const float* __restrict__ ks, const float* __restrict__ vs,
                           float* __restrict__ part)
{
    int bh = blockIdx.y;                           // 16
    int chunk = blockIdx.x;                        // 32 chunks of 1024
    int e    = threadIdx.x >> 5;                   // warp id = e
    int lane = threadIdx.x & 31;
    int b = bh >> 2, hd = bh & 3;
    const float* kp = ks + ((size_t)(b*Cc + hd*Dd))*NS;
    const float* vp = vs + ((size_t)(b*Cc + hd*Dd + e))*NS;
    float acc[16];
#pragma unroll
    for (int d = 0; d < 16; d++) acc[d] = 0.f;
    int n0 = chunk*1024;
    for (int n = n0 + lane; n < n0 + 1024; n += 32){
        float vv = vp[n];
#pragma unroll
        for (int d = 0; d < 16; d++) acc[d] += kp[(size_t)d*NS + n]*vv;
    }
#pragma unroll
    for (int d = 0; d < 16; d++){
#pragma unroll
        for (int off = 16; off; off >>= 1) acc[d] += __shfl_xor_sync(0xffffffffu, acc[d], off);
    }
    if (lane == 0){
#pragma unroll
        for (int d = 0; d < 16; d++)
            part[(((size_t)bh*32 + chunk)*16 + e)*16 + d] = acc[d];
    }
}

__global__ void k_ctx_reduce(const float* __restrict__ part, float* __restrict__ ctx)
{
    int bh = blockIdx.x, t = threadIdx.x;          // t = e*16+d
    int e = t >> 4, d = t & 15;
    float s = 0.f;
    for (int ch = 0; ch < 32; ch++) s += part[(((size_t)bh*32 + ch)*16 + e)*16 + d];
    ctx[bh*256 + d*16 + e] = s;                    // stored [d][e]
}

// ---------------- K6: att[e,n] = sum_d ctx[d,e]*qsm[d,n] ----------------
__global__ void k_att(const float* __restrict__ q, const float* __restrict__ ctx,
                      float* __restrict__ atts)
{
    int bh = blockIdx.y;
    __shared__ float csm[256];
    for (int i = threadIdx.x; i < 256; i += 128) csm[i] = ctx[bh*256 + i];
    __syncthreads();
    int n = blockIdx.x*128 + threadIdx.x;
    int b = bh >> 2, hd = bh & 3;
    const float* qp = q + ((size_t)(b*Cc + hd*Dd))*NS + n;
    float qv[16];
#pragma unroll
    for (int d = 0; d < 16; d++) qv[d] = qp[(size_t)d*NS];
    float o[16];
#pragma unroll
    for (int e = 0; e < 16; e++) o[e] = 0.f;
#pragma unroll
    for (int d = 0; d < 16; d++){
        float qd = qv[d];
#pragma unroll
        for (int e = 0; e < 16; e++) o[e] += csm[d*16 + e]*qd;
    }
    float* op = atts + ((size_t)(b*Cc + hd*Dd))*NS + n;
#pragma unroll
    for (int e = 0; e < 16; e++) op[(size_t)e*NS] = o[e];
}

// ---------------- K7: 5x5 conv 64->128 (pad 2) reading compact checkerboard input ----------------
// att full-image is zero at anchor; nonanchor value at (iy,ix) lives at atts[.., iy, ix>>1].
// Each thread owns an (even,odd) output column pair; tap parity t=(ky+kx)&1 routes to aU/aV.
__global__ void k_conv5x5(const float* __restrict__ atts, const float* __restrict__ rw,
                          const float* __restrict__ rb, float* __restrict__ out)
{
    int z = blockIdx.z;  int b = z >> 3;  int coBase = (z & 7)*16;
    int wBase = blockIdx.x*32;
    int hBase = blockIdx.y*16;
    int tid = threadIdx.x;                          // 256
    int px = tid & 15, yl = tid >> 4;
    int y  = hBase + yl;
    int x0 = wBase + 2*px;                          // even
    int py = y & 1;

    __shared__ __align__(16) float insm[20*18];
    __shared__ __align__(16) float wsm[25*16];      // [tap][co]
    unsigned wb  = (unsigned)__cvta_generic_to_shared(wsm);
    int jBase = (wBase >> 1) - 1;

    u64 aU[8], aV[8];
#pragma unroll
    for (int i = 0; i < 8; i++){ aU[i] = 0ull; aV[i] = 0ull; }

    for (int ci = 0; ci < 64; ci++){
        __syncthreads();
        for (int i = tid; i < 360; i += 256){
            int rr = i/18, jj = i - rr*18;
            int gy = hBase - 2 + rr;
            int gj = jBase + jj;
            float v = 0.f;
            if ((unsigned)gy < Hh && (unsigned)gj < W2)
                v = atts[(((size_t)(b*Cc + ci))*Hh + gy)*W2 + gj];
            insm[rr*18 + jj] = v;
        }
        for (int i = tid; i < 400; i += 256){
            int tap = i >> 4, co = i & 15;
            wsm[tap*16 + co] = rw[((size_t)(coBase + co)*64 + ci)*25 + tap];
        }
        __syncthreads();
#pragma unroll
        for (int ky = 0; ky < 5; ky++){
#pragma unroll
            for (int kx = 0; kx < 5; kx++){
                const int t = (ky + kx) & 1;        // compile-time
                int s  = t ^ py;
                int ix = x0 + s + kx - 2;
                int rr = yl + ky;
                int jj = (ix >> 1) - jBase;
                u64 iv = pack2(insm[rr*18 + jj]);
                unsigned base = wb + (ky*5 + kx)*64;
                if (t == 0){
#pragma unroll
                    for (int k = 0; k < 4; k++){
                        u64 w0, w1;
                        lds2(w0, w1, base + k*16);
                        ffma2(aU[2*k+0], w0, iv);
                        ffma2(aU[2*k+1], w1, iv);
                    }
                } else {
#pragma unroll
                    for (int k = 0; k < 4; k++){
                        u64 w0, w1;
                        lds2(w0, w1, base + k*16);
                        ffma2(aV[2*k+0], w0, iv);
                        ffma2(aV[2*k+1], w1, iv);
                    }
                }
            }
        }
    }
    // aU -> column x0+py, aV -> column x0+1-py
#pragma unroll
    for (int i = 0; i < 8; i++){
        float u0, u1, v0, v1;
        unpack2(aU[i], u0, u1);
        unpack2(aV[i], v0, v1);
        int co = 2*i;
        float b0 = rb[coBase + co], b1 = rb[coBase + co + 1];
        size_t base0 = (((size_t)(b*C2 + coBase + co    ))*Hh + y)*Ww;
        size_t base1 = (((size_t)(b*C2 + coBase + co + 1))*Hh + y)*Ww;
        out[base0 + x0 + py]     = u0 + b0;
        out[base0 + x0 + 1 - py] = v0 + b0;
        out[base1 + x0 + py]     = u1 + b1;
        out[base1 + x0 + 1 - py] = v1 + b1;
    }
}

// ---------------- K8: m1 1x1 conv 128->256 + exact gelu ----------------
__global__ void k_m1(const float* __restrict__ in, const float* __restrict__ w,
                     const float* __restrict__ bias, float* __restrict__ out)
{
    __shared__ __align__(16) float wsm[128*64];     // [ci][co]
    int z = blockIdx.y;  int b = z >> 2;  int coBase = (z & 3)*64;
    int tid = threadIdx.x;
    for (int i = tid; i < 8192; i += 256){
        int co = i & 63, ci = i >> 6;
        wsm[ci*64 + co] = w[(size_t)(coBase + co)*C2 + ci];
    }
    __syncthreads();
    unsigned wb = (unsigned)__cvta_generic_to_shared(wsm);
    int pos = blockIdx.x*256 + tid;
    const float* xp = in + (size_t)b*C2*NPIX + pos;
    u64 acc[32];
#pragma unroll
    for (int i = 0; i < 32; i++) acc[i] = 0ull;
    for (int ci = 0; ci < 128; ci++){
        u64 xv = pack2(xp[(size_t)ci*NPIX]);
        unsigned base = wb + ci*256;
#pragma unroll
        for (int k = 0; k < 16; k++){
            u64 w0, w1;
            lds2(w0, w1, base + k*16);
            ffma2(acc[2*k+0], w0, xv);
            ffma2(acc[2*k+1], w1, xv);
        }
    }
    float* op = out + (size_t)b*C4*NPIX + pos;
#pragma unroll
    for (int i = 0; i < 32; i++){
        float lo, hi; unpack2(acc[i], lo, hi);
        int co = 2*i;
        op[(size_t)(coBase + co    )*NPIX] = gelu_f(lo + bias[coBase + co    ]);
        op[(size_t)(coBase + co + 1)*NPIX] = gelu_f(hi + bias[coBase + co + 1]);
    }
}

// ---------------- K9: m2 depthwise 3x3 (C4 channels, pad 1) + gelu ----------------
__global__ void k_dw3x3_gelu(const float* __restrict__ in, const float* __restrict__ w,
                             const float* __restrict__ bias, float* __restrict__ out)
{
    int idx = blockIdx.x*256 + threadIdx.x;        // over B*C4*NPIX = 2^26
    int x = idx & 255;
    int y = (idx >> 8) & 255;
    int c = (idx >> 16) & 255;
    int b = idx >> 24;
    const float* ip = in + ((size_t)(b*C4 + c))*NPIX;
    const float* wp = w + c*9;
    float s = bias[c];
#pragma unroll
    for (int dy = -1; dy <= 1; dy++){
        int rr = y + dy;
        if ((unsigned)rr < Hh){
#pragma unroll
            for (int dx = -1; dx <= 1; dx++){
                int cc = x + dx;
                if ((unsigned)cc < Ww)
                    s += wp[(dy+1)*3 + (dx+1)] * ip[rr*Ww + cc];
            }
        }
    }
    out[idx] = gelu_f(s);
}

// ---------------- K10: m3 1x1 conv 256->128 + residual add into d_out ----------------
__global__ void k_m3_add(const float* __restrict__ in, const float* __restrict__ w,
                         const float* __restrict__ bias, float* __restrict__ out)
{
    __shared__ __align__(16) float wsm[128*64];
    int z = blockIdx.y;  int b = z >> 1;  int coBase = (z & 1)*64;
    int tid = threadIdx.x;
    unsigned wb = (unsigned)__cvta_generic_to_shared(wsm);
    int pos = blockIdx.x*256 + tid;
    const float* xp = in + (size_t)b*C4*NPIX + pos;
    u64 acc[32];
#pragma unroll
    for (int i = 0; i < 32; i++) acc[i] = 0ull;
    for (int stage = 0; stage < 2; stage++){
        __syncthreads();
        for (int i = tid; i < 8192; i += 256){
            int co = i & 63, ci = i >> 6;
            wsm[ci*64 + co] = w[(size_t)(coBase + co)*C4 + stage*128 + ci];
        }
        __syncthreads();
        for (int ci = 0; ci < 128; ci++){
            u64 xv = pack2(xp[(size_t)(stage*128 + ci)*NPIX]);
            unsigned base = wb + ci*256;
#pragma unroll
            for (int k = 0; k < 16; k++){
                u64 w0, w1;
                lds2(w0, w1, base + k*16);
                ffma2(acc[2*k+0], w0, xv);
                ffma2(acc[2*k+1], w1, xv);
            }
        }
    }
    float* op = out + (size_t)b*C2*NPIX + pos;
#pragma unroll
    for (int i = 0; i < 32; i++){
        float lo, hi; unpack2(acc[i], lo, hi);
        int co = 2*i;
        size_t o0 = (size_t)(coBase + co    )*NPIX;
        size_t o1 = (size_t)(coBase + co + 1)*NPIX;
        op[o0] = op[o0] + lo + bias[coBase + co    ];   // attention + m
        op[o1] = op[o1] + hi + bias[coBase + co + 1];
    }
}

// ---------------- launch ----------------
extern "C" void kernel_launch(void* const* d_in, const int* in_sizes, int n_in,
                              void* d_out, int out_size)
{
    (void)in_sizes; (void)n_in; (void)out_size;
    const float* x1   = (const float*)d_in[0];
    const float* x2   = (const float*)d_in[1];
    const float* q1_w = (const float*)d_in[2];
    const float* q1_b = (const float*)d_in[3];
    const float* q2_w = (const float*)d_in[4];
    const float* q2_b = (const float*)d_in[5];
    const float* k1_w = (const float*)d_in[6];
    const float* k1_b = (const float*)d_in[7];
    const float* k2_w = (const float*)d_in[8];
    const float* k2_b = (const float*)d_in[9];
    const float* v1_w = (const float*)d_in[10];
    const float* v1_b = (const float*)d_in[11];
    const float* v2_w = (const float*)d_in[12];
    const float* v2_b = (const float*)d_in[13];
    const float* r_w  = (const float*)d_in[14];
    const float* r_b  = (const float*)d_in[15];
    const float* m1_w = (const float*)d_in[16];
    const float* m1_b = (const float*)d_in[17];
    const float* m2_w = (const float*)d_in[18];
    const float* m2_b = (const float*)d_in[19];
    const float* m3_w = (const float*)d_in[20];
    const float* m3_b = (const float*)d_in[21];
    float* out = (float*)d_out;

    float *qpre, *kpre, *vpre, *qs, *ks, *vs, *atts, *part, *ctx, *ma, *mb;
    cudaGetSymbolAddress((void**)&qpre, g_qpre);
    cudaGetSymbolAddress((void**)&kpre, g_kpre);
    cudaGetSymbolAddress((void**)&vpre, g_vpre);
    cudaGetSymbolAddress((void**)&qs,   g_qs);
    cudaGetSymbolAddress((void**)&ks,   g_ks);
    cudaGetSymbolAddress((void**)&vs,   g_vs);
    cudaGetSymbolAddress((void**)&atts, g_atts);
    cudaGetSymbolAddress((void**)&part, g_ctx_part);
    cudaGetSymbolAddress((void**)&ctx,  g_ctx);
    cudaGetSymbolAddress((void**)&ma,   g_ma);
    cudaGetSymbolAddress((void**)&mb,   g_mb);

    k_conv1x1_qkv<<<dim3(NPIX/256, Bq), 256>>>(x1, q1_w, q1_b, qpre, 0);
    k_conv1x1_qkv<<<dim3(NPIX/256, Bq), 256>>>(x1, k1_w, k1_b, kpre, 1);
    k_conv1x1_qkv<<<dim3(NPIX/256, Bq), 256>>>(x2, v1_w, v1_b, vpre, 2);

    k_dw3x3_squeeze<<<(Bq*Cc*Hh*W2)/256, 256>>>(qpre, q2_w, q2_b, qs, 0);
    k_dw3x3_squeeze<<<(Bq*Cc*Hh*W2)/256, 256>>>(kpre, k2_w, k2_b, ks, 1);
    k_dw3x3_squeeze<<<(Bq*Cc*Hh*W2)/256, 256>>>(vpre, v2_w, v2_b, vs, 1);

    k_softmax_d<<<(Bq*NHEAD*NS)/256, 256>>>(qs);
    k_softmax_n<<<Bq*Cc, 256>>>(ks);

    k_ctx_part<<<dim3(32, Bq*NHEAD), 512>>>(ks, vs, part);
    k_ctx_reduce<<<Bq*NHEAD, 256>>>(part, ctx);

    k_att<<<dim3(NS/128, Bq*NHEAD), 128>>>(qs, ctx, atts);

    k_conv5x5<<<dim3(Ww/32, Hh/16, Bq*(C2/16)), 256>>>(atts, r_w, r_b, out);

    k_m1<<<dim3(NPIX/256, Bq*4), 256>>>(out, m1_w, m1_b, ma);
    k_dw3x3_gelu<<<(Bq*C4*NPIX)/256, 256>>>(ma, m2_w, m2_b, mb);
    k_m3_add<<<dim3(NPIX/256, Bq*2), 256>>>(mb, m3_w, m3_b, out);
}

// round 3
// speedup vs baseline: 1.3487x; 1.3487x over previous
#include <cuda_runtime.h>
#include <math.h>

#define Bq    4
#define Cc    64
#define Hh    256
#define Ww    256
#define W2    128
#define NPIX  65536   // Hh*Ww
#define NS    32768   // Hh*W2
#define NHEAD 4
#define Dd    16
#define C2    128
#define C4    256

// ---------------- scratch (device globals; no runtime allocation) ----------------
__device__ float g_qs0 [(size_t)Bq*Cc*NS];    // conv1x1 q output, squeezed (nonanchor)
__device__ float g_ks0 [(size_t)Bq*Cc*NS];    // conv1x1 k output, squeezed (anchor)
__device__ float g_vpre[(size_t)Bq*Cc*NPIX];  // conv1x1 v output, full
__device__ float g_qs  [(size_t)Bq*Cc*NS];
__device__ float g_ks  [(size_t)Bq*Cc*NS];
__device__ float g_vs  [(size_t)Bq*Cc*NS];
__device__ float g_atts[(size_t)Bq*Cc*NS];
__device__ float g_kinv[Bq*Cc];
__device__ float g_ctx_part[16*32*16*16];
__device__ float g_ctx[16*256];
__device__ float g_ma[(size_t)Bq*C4*NPIX];
__device__ float g_mb[(size_t)Bq*C4*NPIX];

__device__ __forceinline__ float gelu_f(float x){
    return 0.5f * x * (1.0f + erff(x * 0.70710678118654752f));
}

// ---------------- K1a: 1x1 conv (64->64) evaluated ONLY at kept parity, stored squeezed ----------------
// anchorSel=0 (q): position col = 2j + (r&1);  anchorSel=1 (k): col = 2j + 1-(r&1)
__global__ void k_conv1x1_qk(const float* __restrict__ x, const float* __restrict__ w,
                             const float* __restrict__ bias, float* __restrict__ outSq, int anchorSel)
{
    __shared__ float wsm[64*64];            // [ci][co]
    int tid = threadIdx.x;
    for (int i = tid; i < 4096; i += 256){
        int co = i & 63, ci = i >> 6;
        wsm[ci*64 + co] = w[co*64 + ci];
    }
    __syncthreads();
    int b  = blockIdx.y;
    int ps = blockIdx.x*256 + tid;          // squeezed position within batch
    int j = ps & (W2-1);
    int r = ps >> 7;
    int col = 2*j + (anchorSel ? (1 - (r & 1)) : (r & 1));
    const float* xp = x + (size_t)b*Cc*NPIX + r*Ww + col;

    float acc[64];
#pragma unroll
    for (int i = 0; i < 64; i++) acc[i] = 0.f;

    for (int ci = 0; ci < 64; ci++){
        float xv = xp[(size_t)ci*NPIX];
        const float4* w4 = (const float4*)(wsm + ci*64);
#pragma unroll
        for (int c4 = 0; c4 < 16; c4++){
            float4 wv = w4[c4];
            acc[c4*4+0] += wv.x*xv; acc[c4*4+1] += wv.y*xv;
            acc[c4*4+2] += wv.z*xv; acc[c4*4+3] += wv.w*xv;
        }
    }
    float* op = outSq + (size_t)b*Cc*NS + ps;
#pragma unroll
    for (int co = 0; co < 64; co++)
        op[(size_t)co*NS] = acc[co] + bias[co];
}

// ---------------- K1b: 1x1 conv (64->64) full image (v) ----------------
__global__ void k_conv1x1_v(const float* __restrict__ x, const float* __restrict__ w,
                            const float* __restrict__ bias, float* __restrict__ out)
{
    __shared__ float wsm[64*64];
    int tid = threadIdx.x;
    for (int i = tid; i < 4096; i += 256){
        int co = i & 63, ci = i >> 6;
        wsm[ci*64 + co] = w[co*64 + ci];
    }
    __syncthreads();
    int b   = blockIdx.y;
    int pos = blockIdx.x*256 + tid;
    const float* xp = x + (size_t)b*Cc*NPIX + pos;

    float acc[64];
#pragma unroll
    for (int i = 0; i < 64; i++) acc[i] = 0.f;

    for (int ci = 0; ci < 64; ci++){
        float xv = xp[(size_t)ci*NPIX];
        const float4* w4 = (const float4*)(wsm + ci*64);
#pragma unroll
        for (int c4 = 0; c4 < 16; c4++){
            float4 wv = w4[c4];
            acc[c4*4+0] += wv.x*xv; acc[c4*4+1] += wv.y*xv;
            acc[c4*4+2] += wv.z*xv; acc[c4*4+3] += wv.w*xv;
        }
    }
    float* op = out + (size_t)b*Cc*NPIX + pos;
#pragma unroll
    for (int co = 0; co < 64; co++)
        op[(size_t)co*NPIX] = acc[co] + bias[co];
}

// ---------------- K2a: depthwise 3x3 for q/k on squeezed pre-buffer ----------------
// Same-parity taps are the 4 diagonals + center; opposite-parity neighbors hold conv1 bias.
__global__ void k_dw3x3_qk(const float* __restrict__ in, const float* __restrict__ w,
                           const float* __restrict__ bias, const float* __restrict__ pbias,
                           float* __restrict__ out, int anchorSel)
{
    int idx = blockIdx.x*256 + threadIdx.x;        // over B*C*NS
    int j = idx & (W2-1);
    int r = (idx >> 7) & (Hh-1);
    int c = (idx >> 15) & (Cc-1);
    int o = anchorSel ? (1 - (r & 1)) : (r & 1);
    int col = 2*j + o;
    const float* ip = in + (size_t)(idx >> 15) * NS;   // (b*Cc+c)*NS
    const float* wp = w + c*9;

    float s = bias[c] + wp[4]*ip[r*W2 + j];
    // bias contributions from opposite-parity taps (value = pbias[c] when in-bounds)
    float cb = pbias[c];
    float bw = 0.f;
    if (r > 0)       bw += wp[1];
    if (r < Hh-1)    bw += wp[7];
    if (col > 0)     bw += wp[3];
    if (col < Ww-1)  bw += wp[5];
    s += cb * bw;
    // diagonal taps
    int jm = j - 1 + o, jp = j + o;
    if (r > 0){
        const float* rp = ip + (r-1)*W2;
        if ((unsigned)jm < W2) s += wp[0]*rp[jm];
        if ((unsigned)jp < W2) s += wp[2]*rp[jp];
    }
    if (r < Hh-1){
        const float* rp = ip + (r+1)*W2;
        if ((unsigned)jm < W2) s += wp[6]*rp[jm];
        if ((unsigned)jp < W2) s += wp[8]*rp[jp];
    }
    out[idx] = s;
}

// ---------------- K2b: depthwise 3x3 for v (full input, anchor output, squeezed) ----------------
__global__ void k_dw3x3_v(const float* __restrict__ in, const float* __restrict__ w,
                          const float* __restrict__ bias, float* __restrict__ out)
{
    int idx = blockIdx.x*256 + threadIdx.x;        // over B*C*NS
    int j = idx & (W2-1);
    int r = (idx >> 7) & (Hh-1);
    int c = (idx >> 15) & (Cc-1);
    int col = 2*j + (1 - (r & 1));                 // anchor
    const float* ip = in + (size_t)(idx >> 15) * NPIX;
    const float* wp = w + c*9;
    float s = bias[c];
#pragma unroll
    for (int dy = -1; dy <= 1; dy++){
        int rr = r + dy;
        if ((unsigned)rr < Hh){
#pragma unroll
            for (int dx = -1; dx <= 1; dx++){
                int cc = col + dx;
                if ((unsigned)cc < Ww)
                    s += wp[(dy+1)*3 + (dx+1)] * ip[rr*Ww + cc];
            }
        }
    }
    out[idx] = s;
}

// ---------------- K4: k softmax (max + exp; normalization deferred to ctx_reduce) ----------------
__global__ void k_softmax_n_exp(float* __restrict__ kk, float* __restrict__ kinv)
{
    int row = blockIdx.x;                          // B*C = 256 rows
    float* p = kk + (size_t)row*NS;
    int tid = threadIdx.x;
    __shared__ float red[256];
    float mx = -1e30f;
    for (int i = tid; i < NS; i += 256) mx = fmaxf(mx, p[i]);
    red[tid] = mx; __syncthreads();
    for (int s = 128; s > 0; s >>= 1){ if (tid < s) red[tid] = fmaxf(red[tid], red[tid+s]); __syncthreads(); }
    mx = red[0]; __syncthreads();
    float sum = 0.f;
    for (int i = tid; i < NS; i += 256){
        float e = __expf(p[i]-mx);
        p[i] = e;
        sum += e;
    }
    red[tid] = sum; __syncthreads();
    for (int s = 128; s > 0; s >>= 1){ if (tid < s) red[tid] += red[tid+s]; __syncthreads(); }
    if (tid == 0) kinv[row] = 1.f/red[0];
}

// ---------------- K5: ctx partials: ctx[d][e] = sum_n expk[d,n]*vs[e,n] ----------------
__global__ void k_ctx_part(const float* __restrict__ ks, const float* __restrict__ vs,
                           float* __restrict__ part)
{
    int bh = blockIdx.y;                           // 16
    int chunk = blockIdx.x;                        // 32 chunks of 1024
    int e    = threadIdx.x >> 5;
    int lane = threadIdx.x & 31;
    int b = bh >> 2, hd = bh & 3;
    const float* kp = ks + ((size_t)(b*Cc + hd*Dd))*NS;
    const float* vp = vs + ((size_t)(b*Cc + hd*Dd + e))*NS;
    float acc[16];
#pragma unroll
    for (int d = 0; d < 16; d++) acc[d] = 0.f;
    int n0 = chunk*1024;
    for (int n = n0 + lane; n < n0 + 1024; n += 32){
        float vv = vp[n];
#pragma unroll
        for (int d = 0; d < 16; d++) acc[d] += kp[(size_t)d*NS + n]*vv;
    }
#pragma unroll
    for (int d = 0; d < 16; d++){
#pragma unroll
        for (int off = 16; off; off >>= 1) acc[d] += __shfl_xor_sync(0xffffffffu, acc[d], off);
    }
    if (lane == 0){
#pragma unroll
        for (int d = 0; d < 16; d++)
            part[(((size_t)bh*32 + chunk)*16 + e)*16 + d] = acc[d];
    }
}

__global__ void k_ctx_reduce(const float* __restrict__ part, const float* __restrict__ kinv,
                             float* __restrict__ ctx)
{
    int bh = blockIdx.x, t = threadIdx.x;          // t = e*16+d
    int e = t >> 4, d = t & 15;
    float s = 0.f;
    for (int ch = 0; ch < 32; ch++) s += part[(((size_t)bh*32 + ch)*16 + e)*16 + d];
    int b = bh >> 2, hd = bh & 3;
    s *= kinv[b*Cc + hd*Dd + d];
    ctx[bh*256 + d*16 + e] = s;                    // stored [d][e]
}

// ---------------- K6: att[e,n] = sum_d ctx[d,e]*softmax_d(q)[d,n]  (softmax fused) ----------------
__global__ void k_att(const float* __restrict__ q, const float* __restrict__ ctx,
                      float* __restrict__ atts)
{
    int bh = blockIdx.y;
    __shared__ float csm[256];
    for (int i = threadIdx.x; i < 256; i += 128) csm[i] = ctx[bh*256 + i];
    __syncthreads();
    int n = blockIdx.x*128 + threadIdx.x;
    int b = bh >> 2, hd = bh & 3;
    const float* qp = q + ((size_t)(b*Cc + hd*Dd))*NS + n;
    float qv[16];
    float mx = -1e30f;
#pragma unroll
    for (int d = 0; d < 16; d++){ qv[d] = qp[(size_t)d*NS]; mx = fmaxf(mx, qv[d]); }
    float ssum = 0.f;
#pragma unroll
    for (int d = 0; d < 16; d++){ qv[d] = __expf(qv[d]-mx); ssum += qv[d]; }
    float inv = 1.f/ssum;
    float o[16];
#pragma unroll
    for (int e = 0; e < 16; e++) o[e] = 0.f;
#pragma unroll
    for (int d = 0; d < 16; d++){
        float qd = qv[d]*inv;
#pragma unroll
        for (int e = 0; e < 16; e++) o[e] += csm[d*16 + e]*qd;
    }
    float* op = atts + ((size_t)(b*Cc + hd*Dd))*NS + n;
#pragma unroll
    for (int e = 0; e < 16; e++) op[(size_t)e*NS] = o[e];
}

// ---------------- K7: 5x5 conv 64->128 (pad 2) reading compact checkerboard input ----------------
// 32 output channels per block; tap parity t=(ky+kx)&1 routes to aU (col x0+py) / aV (col x0+1-py).
__global__ void k_conv5x5(const float* __restrict__ atts, const float* __restrict__ rw,
                          const float* __restrict__ rb, float* __restrict__ out)
{
    int z = blockIdx.z;  int b = z >> 2;  int coBase = (z & 3)*32;
    int wBase = blockIdx.x*32;
    int hBase = blockIdx.y*16;
    int tid = threadIdx.x;                          // 256
    int px = tid & 15, yl = tid >> 4;
    int y  = hBase + yl;
    int x0 = wBase + 2*px;                          // even
    int py = y & 1;

    __shared__ float insm[20*18];
    __shared__ float wsm[25*32];                    // [tap][co]
    int jBase = (wBase >> 1) - 1;

    float aU[32], aV[32];
#pragma unroll
    for (int i = 0; i < 32; i++){ aU[i] = 0.f; aV[i] = 0.f; }

    for (int ci = 0; ci < 64; ci++){
        __syncthreads();
        for (int i = tid; i < 360; i += 256){
            int rr = i/18, jj = i - rr*18;
            int gy = hBase - 2 + rr;
            int gj = jBase + jj;
            float v = 0.f;
            if ((unsigned)gy < Hh && (unsigned)gj < W2)
                v = atts[(((size_t)(b*Cc + ci))*Hh + gy)*W2 + gj];
            insm[rr*18 + jj] = v;
        }
        for (int i = tid; i < 800; i += 256){
            int tap = i >> 5, co = i & 31;
            wsm[tap*32 + co] = rw[((size_t)(coBase + co)*64 + ci)*25 + tap];
        }
        __syncthreads();
#pragma unroll
        for (int ky = 0; ky < 5; ky++){
#pragma unroll
            for (int kx = 0; kx < 5; kx++){
                const int t = (ky + kx) & 1;        // compile-time
                int s  = t ^ py;
                int ix = x0 + s + kx - 2;
                int rr = yl + ky;
                int jj = (ix >> 1) - jBase;
                float iv = insm[rr*18 + jj];
                const float4* w4 = (const float4*)(wsm + (ky*5 + kx)*32);
                if (t == 0){
#pragma unroll
                    for (int c4 = 0; c4 < 8; c4++){
                        float4 wv = w4[c4];
                        aU[c4*4+0] += wv.x*iv; aU[c4*4+1] += wv.y*iv;
                        aU[c4*4+2] += wv.z*iv; aU[c4*4+3] += wv.w*iv;
                    }
                } else {
#pragma unroll
                    for (int c4 = 0; c4 < 8; c4++){
                        float4 wv = w4[c4];
                        aV[c4*4+0] += wv.x*iv; aV[c4*4+1] += wv.y*iv;
                        aV[c4*4+2] += wv.z*iv; aV[c4*4+3] += wv.w*iv;
                    }
                }
            }
        }
    }
#pragma unroll
    for (int co = 0; co < 32; co++){
        float bv = rb[coBase + co];
        size_t base = (((size_t)(b*C2 + coBase + co))*Hh + y)*Ww;
        out[base + x0 + py]       = aU[co] + bv;
        out[base + x0 + 1 - py]   = aV[co] + bv;
    }
}

// ---------------- K8: m1 1x1 conv 128->256 + exact gelu ----------------
__global__ void k_m1(const float* __restrict__ in, const float* __restrict__ w,
                     const float* __restrict__ bias, float* __restrict__ out)
{
    __shared__ float wsm[128*64];                   // [ci][co]
    int z = blockIdx.y;  int b = z >> 2;  int coBase = (z & 3)*64;
    int tid = threadIdx.x;
    for (int i = tid; i < 8192; i += 256){
        int co = i & 63, ci = i >> 6;
        wsm[ci*64 + co] = w[(size_t)(coBase + co)*C2 + ci];
    }
    __syncthreads();
    int pos = blockIdx.x*256 + tid;
    const float* xp = in + (size_t)b*C2*NPIX + pos;
    float acc[64];
#pragma unroll
    for (int i = 0; i < 64; i++) acc[i] = 0.f;
    for (int ci = 0; ci < 128; ci++){
        float xv = xp[(size_t)ci*NPIX];
        const float4* w4 = (const float4*)(wsm + ci*64);
#pragma unroll
        for (int c4 = 0; c4 < 16; c4++){
            float4 wv = w4[c4];
            acc[c4*4+0] += wv.x*xv; acc[c4*4+1] += wv.y*xv;
            acc[c4*4+2] += wv.z*xv; acc[c4*4+3] += wv.w*xv;
        }
    }
    float* op = out + (size_t)b*C4*NPIX + pos;
#pragma unroll
    for (int co = 0; co < 64; co++)
        op[(size_t)(coBase + co)*NPIX] = gelu_f(acc[co] + bias[coBase + co]);
}

// ---------------- K9: m2 depthwise 3x3 (C4 channels, pad 1) + gelu ----------------
__global__ void k_dw3x3_gelu(const float* __restrict__ in, const float* __restrict__ w,
                             const float* __restrict__ bias, float* __restrict__ out)
{
    int idx = blockIdx.x*256 + threadIdx.x;        // over B*C4*NPIX = 2^26
    int x = idx & 255;
    int y = (idx >> 8) & 255;
    int c = (idx >> 16) & 255;
    const float* ip = in + (size_t)(idx >> 16) * NPIX;
    const float* wp = w + c*9;
    float s = bias[c];
#pragma unroll
    for (int dy = -1; dy <= 1; dy++){
        int rr = y + dy;
        if ((unsigned)rr < Hh){
#pragma unroll
            for (int dx = -1; dx <= 1; dx++){
                int cc = x + dx;
                if ((unsigned)cc < Ww)
                    s += wp[(dy+1)*3 + (dx+1)] * ip[rr*Ww + cc];
            }
        }
    }
    out[idx] = gelu_f(s);
}

// ---------------- K10: m3 1x1 conv 256->128 + residual add into d_out ----------------
__global__ void k_m3_add(const float* __restrict__ in, const float* __restrict__ w,
                         const float* __restrict__ bias, float* __restrict__ out)
{
    __shared__ float wsm[128*64];
    int z = blockIdx.y;  int b = z >> 1;  int coBase = (z & 1)*64;
    int tid = threadIdx.x;
    int pos = blockIdx.x*256 + tid;
    const float* xp = in + (size_t)b*C4*NPIX + pos;
    float acc[64];
#pragma unroll
    for (int i = 0; i < 64; i++) acc[i] = 0.f;
    for (int stage = 0; stage < 2; stage++){
        __syncthreads();
        for (int i = tid; i < 8192; i += 256){
            int co = i & 63, ci = i >> 6;
            wsm[ci*64 + co] = w[(size_t)(coBase + co)*C4 + stage*128 + ci];
        }
        __syncthreads();
        for (int ci = 0; ci < 128; ci++){
            float xv = xp[(size_t)(stage*128 + ci)*NPIX];
            const float4* w4 = (const float4*)(wsm + ci*64);
#pragma unroll
            for (int c4 = 0; c4 < 16; c4++){
                float4 wv = w4[c4];
                acc[c4*4+0] += wv.x*xv; acc[c4*4+1] += wv.y*xv;
                acc[c4*4+2] += wv.z*xv; acc[c4*4+3] += wv.w*xv;
            }
        }
    }
    float* op = out + (size_t)b*C2*NPIX + pos;
#pragma unroll
    for (int co = 0; co < 64; co++){
        size_t o = (size_t)(coBase + co)*NPIX;
        op[o] = op[o] + acc[co] + bias[coBase + co];   // attention + m
    }
}

// ---------------- launch ----------------
extern "C" void kernel_launch(void* const* d_in, const int* in_sizes, int n_in,
                              void* d_out, int out_size)
{
    (void)in_sizes; (void)n_in; (void)out_size;
    const float* x1   = (const float*)d_in[0];
    const float* x2   = (const float*)d_in[1];
    const float* q1_w = (const float*)d_in[2];
    const float* q1_b = (const float*)d_in[3];
    const float* q2_w = (const float*)d_in[4];
    const float* q2_b = (const float*)d_in[5];
    const float* k1_w = (const float*)d_in[6];
    const float* k1_b = (const float*)d_in[7];
    const float* k2_w = (const float*)d_in[8];
    const float* k2_b = (const float*)d_in[9];
    const float* v1_w = (const float*)d_in[10];
    const float* v1_b = (const float*)d_in[11];
    const float* v2_w = (const float*)d_in[12];
    const float* v2_b = (const float*)d_in[13];
    const float* r_w  = (const float*)d_in[14];
    const float* r_b  = (const float*)d_in[15];
    const float* m1_w = (const float*)d_in[16];
    const float* m1_b = (const float*)d_in[17];
    const float* m2_w = (const float*)d_in[18];
    const float* m2_b = (const float*)d_in[19];
    const float* m3_w = (const float*)d_in[20];
    const float* m3_b = (const float*)d_in[21];
    float* out = (float*)d_out;

    float *qs0, *ks0, *vpre, *qs, *ks, *vs, *atts, *kinv, *part, *ctx, *ma, *mb;
    cudaGetSymbolAddress((void**)&qs0,  g_qs0);
    cudaGetSymbolAddress((void**)&ks0,  g_ks0);
    cudaGetSymbolAddress((void**)&vpre, g_vpre);
    cudaGetSymbolAddress((void**)&qs,   g_qs);
    cudaGetSymbolAddress((void**)&ks,   g_ks);
    cudaGetSymbolAddress((void**)&vs,   g_vs);
    cudaGetSymbolAddress((void**)&atts, g_atts);
    cudaGetSymbolAddress((void**)&kinv, g_kinv);
    cudaGetSymbolAddress((void**)&part, g_ctx_part);
    cudaGetSymbolAddress((void**)&ctx,  g_ctx);
    cudaGetSymbolAddress((void**)&ma,   g_ma);
    cudaGetSymbolAddress((void**)&mb,   g_mb);

    k_conv1x1_qk<<<dim3(NS/256, Bq), 256>>>(x1, q1_w, q1_b, qs0, 0);
    k_conv1x1_qk<<<dim3(NS/256, Bq), 256>>>(x1, k1_w, k1_b, ks0, 1);
    k_conv1x1_v <<<dim3(NPIX/256, Bq), 256>>>(x2, v1_w, v1_b, vpre);

    k_dw3x3_qk<<<(Bq*Cc*NS)/256, 256>>>(qs0, q2_w, q2_b, q1_b, qs, 0);
    k_dw3x3_qk<<<(Bq*Cc*NS)/256, 256>>>(ks0, k2_w, k2_b, k1_b, ks, 1);
    k_dw3x3_v <<<(Bq*Cc*NS)/256, 256>>>(vpre, v2_w, v2_b, vs);

    k_softmax_n_exp<<<Bq*Cc, 256>>>(ks, kinv);

    k_ctx_part<<<dim3(32, Bq*NHEAD), 512>>>(ks, vs, part);
    k_ctx_reduce<<<Bq*NHEAD, 256>>>(part, kinv, ctx);

    k_att<<<dim3(NS/128, Bq*NHEAD), 128>>>(qs, ctx, atts);

    k_conv5x5<<<dim3(Ww/32, Hh/16, Bq*4), 256>>>(atts, r_w, r_b, out);

    k_m1<<<dim3(NPIX/256, Bq*4), 256>>>(out, m1_w, m1_b, ma);
    k_dw3x3_gelu<<<(Bq*C4*NPIX)/256, 256>>>(ma, m2_w, m2_b, mb);
    k_m3_add<<<dim3(NPIX/256, Bq*2), 256>>>(mb, m3_w, m3_b, out);
}

// round 6
// speedup vs baseline: 1.5597x; 1.1564x over previous
#include <cuda_runtime.h>
#include <cuda_bf16.h>
#include <math.h>
#include <stdint.h>

#define Bq    4
#define Cc    64
#define Hh    256
#define Ww    256
#define W2    128
#define NPIX  65536   // Hh*Ww
#define NS    32768   // Hh*W2
#define NHEAD 4
#define Dd    16
#define C2    128
#define C4    256

// ---------------- scratch (device globals; no runtime allocation) ----------------
__device__ float g_qs0 [(size_t)Bq*Cc*NS];
__device__ float g_ks0 [(size_t)Bq*Cc*NS];
__device__ float g_vpre[(size_t)Bq*Cc*NPIX];
__device__ float g_qs  [(size_t)Bq*Cc*NS];
__device__ float g_ks  [(size_t)Bq*Cc*NS];
__device__ float g_vs  [(size_t)Bq*Cc*NS];
__device__ float g_atts[(size_t)Bq*Cc*NS];
__device__ float g_kinv[Bq*Cc];
__device__ float g_ctx_part[16*32*16*16];
__device__ float g_ctx[16*256];
__device__ float g_ma[(size_t)Bq*C4*NPIX];
__device__ float g_mb[(size_t)Bq*C4*NPIX];

__device__ __forceinline__ float gelu_f(float x){
    return 0.5f * x * (1.0f + erff(x * 0.70710678118654752f));
}

// ================= mma.sync helpers (baseline ISA; compiles for compute_103) =================
__device__ __forceinline__ void ldsm4(uint32_t &r0, uint32_t &r1, uint32_t &r2, uint32_t &r3, uint32_t addr){
    asm volatile("ldmatrix.sync.aligned.m8n8.x4.shared.b16 {%0,%1,%2,%3}, [%4];"
                 : "=r"(r0), "=r"(r1), "=r"(r2), "=r"(r3) : "r"(addr));
}
__device__ __forceinline__ void mma16816(float* c, const uint32_t* a, uint32_t b0, uint32_t b1){
    asm volatile(
        "mma.sync.aligned.m16n8k16.row.col.f32.bf16.bf16.f32 "
        "{%0,%1,%2,%3}, {%4,%5,%6,%7}, {%8,%9}, {%0,%1,%2,%3};"
        : "+f"(c[0]), "+f"(c[1]), "+f"(c[2]), "+f"(c[3])
        : "r"(a[0]), "r"(a[1]), "r"(a[2]), "r"(a[3]), "r"(b0), "r"(b1));
}

// ================= tensor-core GEMM: out[co,pos] = sum_ci w[co,ci]*in[ci,pos] =================
// Split-bf16 (hi/lo): acc = AhBh + AhBl + AlBh.  CTA: 128co x 128pos, K chunk 64.
// GELU: out = gelu(acc+bias).  RES: out += acc+bias (residual into existing out).
#define KC    64
#define PAD   72                              // bf16 per smem row (144B stride, 16B aligned, conflict-free)
#define SMEM_OP (128*PAD)                     // bf16 elems per operand buffer
#define SM_GEMM_BYTES (4*SMEM_OP*2)           // Ah, Al, Bh, Bl

template<int CIN, int COUT, bool GELU, bool RES>
__global__ void __launch_bounds__(256, 1)
k_gemm_mma(const float* __restrict__ in, const float* __restrict__ w,
           const float* __restrict__ bias, float* __restrict__ out)
{
    extern __shared__ __align__(16) __nv_bfloat16 sm[];
    __nv_bfloat16* Ah = sm;
    __nv_bfloat16* Al = sm + SMEM_OP;
    __nv_bfloat16* Bh = sm + 2*SMEM_OP;
    __nv_bfloat16* Bl = sm + 3*SMEM_OP;
    uint32_t aBaseH = (uint32_t)__cvta_generic_to_shared(Ah);
    uint32_t aBaseL = (uint32_t)__cvta_generic_to_shared(Al);
    uint32_t bBaseH = (uint32_t)__cvta_generic_to_shared(Bh);
    uint32_t bBaseL = (uint32_t)__cvta_generic_to_shared(Bl);

    int tid = threadIdx.x;
    int b = blockIdx.x >> 9;
    int posBase = (blockIdx.x & 511)*128;
    int coBase = blockIdx.y*128;
    int lane = tid & 31, warp = tid >> 5;
    int wco = (warp & 3)*32;
    int wpos = (warp >> 2)*64;

    float acc[2][8][4];
#pragma unroll
    for (int mt = 0; mt < 2; mt++)
#pragma unroll
        for (int nt = 0; nt < 8; nt++)
#pragma unroll
            for (int r = 0; r < 4; r++) acc[mt][nt][r] = 0.f;

    const int KO = CIN/KC;
#pragma unroll 1
    for (int ko = 0; ko < KO; ko++){
        __syncthreads();
        // stage A = w[coBase+co][ko*64+k] -> Ah/Al [co][k]
        for (int i = tid; i < 128*KC; i += 256){
            int co = i >> 6, k = i & (KC-1);
            float v = w[(size_t)(coBase + co)*CIN + ko*KC + k];
            __nv_bfloat16 h = __float2bfloat16(v);
            __nv_bfloat16 l = __float2bfloat16(v - __bfloat162float(h));
            Ah[co*PAD + k] = h;
            Al[co*PAD + k] = l;
        }
        // stage B = in[ko*64+ci][posBase+p] -> Bh/Bl [p][ci]  (coalesced gmem read)
        for (int i = tid; i < 128*KC; i += 256){
            int p = i & 127, ci = i >> 7;
            float v = in[((size_t)(b*CIN + ko*KC + ci))*NPIX + posBase + p];
            __nv_bfloat16 h = __float2bfloat16(v);
            __nv_bfloat16 l = __float2bfloat16(v - __bfloat162float(h));
            Bh[p*PAD + ci] = h;
            Bl[p*PAD + ci] = l;
        }
        __syncthreads();

#pragma unroll
        for (int ks = 0; ks < KC/16; ks++){
            int k0 = ks*16;
            // per-lane ldmatrix addressing: g = lane>>3 selects 8x8 quadrant
            int g = lane >> 3;
            int rofs = (lane & 7) + ((g & 1) ? 8 : 0);
            int cofs = k0 + ((g >> 1) ? 8 : 0);
            uint32_t ah[2][4], al[2][4];
#pragma unroll
            for (int mt = 0; mt < 2; mt++){
                uint32_t off = ((wco + mt*16 + rofs)*PAD + cofs)*2;
                ldsm4(ah[mt][0], ah[mt][1], ah[mt][2], ah[mt][3], aBaseH + off);
                ldsm4(al[mt][0], al[mt][1], al[mt][2], al[mt][3], aBaseL + off);
            }
            uint32_t bh[4][4], bl[4][4];
#pragma unroll
            for (int ntp = 0; ntp < 4; ntp++){
                uint32_t off = ((wpos + ntp*16 + rofs)*PAD + cofs)*2;
                ldsm4(bh[ntp][0], bh[ntp][1], bh[ntp][2], bh[ntp][3], bBaseH + off);
                ldsm4(bl[ntp][0], bl[ntp][1], bl[ntp][2], bl[ntp][3], bBaseL + off);
            }
#pragma unroll
            for (int mt = 0; mt < 2; mt++){
#pragma unroll
                for (int ntp = 0; ntp < 4; ntp++){
#pragma unroll
                    for (int sub = 0; sub < 2; sub++){
                        int nt = ntp*2 + sub;
                        uint32_t h0 = bh[ntp][sub], h1 = bh[ntp][sub+2];
                        uint32_t l0 = bl[ntp][sub], l1 = bl[ntp][sub+2];
                        mma16816(acc[mt][nt], ah[mt], h0, h1);
                        mma16816(acc[mt][nt], ah[mt], l0, l1);
                        mma16816(acc[mt][nt], al[mt], h0, h1);
                    }
                }
            }
        }
    }

    // epilogue: lane mapping for m16n8 f32 accum
    {
        int r = lane >> 2, cc = (lane & 3)*2;
#pragma unroll
        for (int mt = 0; mt < 2; mt++){
            int co0 = coBase + wco + mt*16 + r;
            float bv0 = bias[co0], bv8 = bias[co0 + 8];
            float* op0 = out + ((size_t)(b*COUT + co0    ))*NPIX + posBase + wpos + cc;
            float* op8 = out + ((size_t)(b*COUT + co0 + 8))*NPIX + posBase + wpos + cc;
#pragma unroll
            for (int nt = 0; nt < 8; nt++){
                float2 v0, v8;
                v0.x = acc[mt][nt][0] + bv0;  v0.y = acc[mt][nt][1] + bv0;
                v8.x = acc[mt][nt][2] + bv8;  v8.y = acc[mt][nt][3] + bv8;
                if (GELU){
                    v0.x = gelu_f(v0.x); v0.y = gelu_f(v0.y);
                    v8.x = gelu_f(v8.x); v8.y = gelu_f(v8.y);
                }
                if (RES){
                    float2 o0 = *(const float2*)(op0 + nt*8);
                    float2 o8 = *(const float2*)(op8 + nt*8);
                    v0.x += o0.x; v0.y += o0.y;
                    v8.x += o8.x; v8.y += o8.y;
                }
                *(float2*)(op0 + nt*8) = v0;
                *(float2*)(op8 + nt*8) = v8;
            }
        }
    }
}

// ---------------- K1a: 1x1 conv (64->64) only at kept parity, stored squeezed ----------------
__global__ void k_conv1x1_qk(const float* __restrict__ x, const float* __restrict__ w,
                             const float* __restrict__ bias, float* __restrict__ outSq, int anchorSel)
{
    __shared__ float wsm[64*64];
    int tid = threadIdx.x;
    for (int i = tid; i < 4096; i += 256){
        int co = i & 63, ci = i >> 6;
        wsm[ci*64 + co] = w[co*64 + ci];
    }
    __syncthreads();
    int b  = blockIdx.y;
    int ps = blockIdx.x*256 + tid;
    int j = ps & (W2-1);
    int r = ps >> 7;
    int col = 2*j + (anchorSel ? (1 - (r & 1)) : (r & 1));
    const float* xp = x + (size_t)b*Cc*NPIX + r*Ww + col;

    float acc[64];
#pragma unroll
    for (int i = 0; i < 64; i++) acc[i] = 0.f;
    for (int ci = 0; ci < 64; ci++){
        float xv = xp[(size_t)ci*NPIX];
        const float4* w4 = (const float4*)(wsm + ci*64);
#pragma unroll
        for (int c4 = 0; c4 < 16; c4++){
            float4 wv = w4[c4];
            acc[c4*4+0] += wv.x*xv; acc[c4*4+1] += wv.y*xv;
            acc[c4*4+2] += wv.z*xv; acc[c4*4+3] += wv.w*xv;
        }
    }
    float* op = outSq + (size_t)b*Cc*NS + ps;
#pragma unroll
    for (int co = 0; co < 64; co++)
        op[(size_t)co*NS] = acc[co] + bias[co];
}

// ---------------- K1b: 1x1 conv (64->64) full image (v) ----------------
__global__ void k_conv1x1_v(const float* __restrict__ x, const float* __restrict__ w,
                            const float* __restrict__ bias, float* __restrict__ out)
{
    __shared__ float wsm[64*64];
    int tid = threadIdx.x;
    for (int i = tid; i < 4096; i += 256){
        int co = i & 63, ci = i >> 6;
        wsm[ci*64 + co] = w[co*64 + ci];
    }
    __syncthreads();
    int b   = blockIdx.y;
    int pos = blockIdx.x*256 + tid;
    const float* xp = x + (size_t)b*Cc*NPIX + pos;
    float acc[64];
#pragma unroll
    for (int i = 0; i < 64; i++) acc[i] = 0.f;
    for (int ci = 0; ci < 64; ci++){
        float xv = xp[(size_t)ci*NPIX];
        const float4* w4 = (const float4*)(wsm + ci*64);
#pragma unroll
        for (int c4 = 0; c4 < 16; c4++){
            float4 wv = w4[c4];
            acc[c4*4+0] += wv.x*xv; acc[c4*4+1] += wv.y*xv;
            acc[c4*4+2] += wv.z*xv; acc[c4*4+3] += wv.w*xv;
        }
    }
    float* op = out + (size_t)b*Cc*NPIX + pos;
#pragma unroll
    for (int co = 0; co < 64; co++)
        op[(size_t)co*NPIX] = acc[co] + bias[co];
}

// ---------------- K2a: depthwise 3x3 for q/k on squeezed pre-buffer ----------------
__global__ void k_dw3x3_qk(const float* __restrict__ in, const float* __restrict__ w,
                           const float* __restrict__ bias, const float* __restrict__ pbias,
                           float* __restrict__ out, int anchorSel)
{
    int idx = blockIdx.x*256 + threadIdx.x;
    int j = idx & (W2-1);
    int r = (idx >> 7) & (Hh-1);
    int c = (idx >> 15) & (Cc-1);
    int o = anchorSel ? (1 - (r & 1)) : (r & 1);
    int col = 2*j + o;
    const float* ip = in + (size_t)(idx >> 15) * NS;
    const float* wp = w + c*9;

    float s = bias[c] + wp[4]*ip[r*W2 + j];
    float cb = pbias[c];
    float bw = 0.f;
    if (r > 0)       bw += wp[1];
    if (r < Hh-1)    bw += wp[7];
    if (col > 0)     bw += wp[3];
    if (col < Ww-1)  bw += wp[5];
    s += cb * bw;
    int jm = j - 1 + o, jp = j + o;
    if (r > 0){
        const float* rp = ip + (r-1)*W2;
        if ((unsigned)jm < W2) s += wp[0]*rp[jm];
        if ((unsigned)jp < W2) s += wp[2]*rp[jp];
    }
    if (r < Hh-1){
        const float* rp = ip + (r+1)*W2;
        if ((unsigned)jm < W2) s += wp[6]*rp[jm];
        if ((unsigned)jp < W2) s += wp[8]*rp[jp];
    }
    out[idx] = s;
}

// ---------------- K2b: depthwise 3x3 for v (full input, anchor output, squeezed) ----------------
__global__ void k_dw3x3_v(const float* __restrict__ in, const float* __restrict__ w,
                          const float* __restrict__ bias, float* __restrict__ out)
{
    int idx = blockIdx.x*256 + threadIdx.x;
    int j = idx & (W2-1);
    int r = (idx >> 7) & (Hh-1);
    int c = (idx >> 15) & (Cc-1);
    int col = 2*j + (1 - (r & 1));
    const float* ip = in + (size_t)(idx >> 15) * NPIX;
    const float* wp = w + c*9;
    float s = bias[c];
#pragma unroll
    for (int dy = -1; dy <= 1; dy++){
        int rr = r + dy;
        if ((unsigned)rr < Hh){
#pragma unroll
            for (int dx = -1; dx <= 1; dx++){
                int cc = col + dx;
                if ((unsigned)cc < Ww)
                    s += wp[(dy+1)*3 + (dx+1)] * ip[rr*Ww + cc];
            }
        }
    }
    out[idx] = s;
}

// ---------------- K4: k softmax (max + exp; normalization deferred) ----------------
__global__ void k_softmax_n_exp(float* __restrict__ kk, float* __restrict__ kinv)
{
    int row = blockIdx.x;
    float* p = kk + (size_t)row*NS;
    int tid = threadIdx.x;
    __shared__ float red[256];
    float mx = -1e30f;
    for (int i = tid; i < NS; i += 256) mx = fmaxf(mx, p[i]);
    red[tid] = mx; __syncthreads();
    for (int s = 128; s > 0; s >>= 1){ if (tid < s) red[tid] = fmaxf(red[tid], red[tid+s]); __syncthreads(); }
    mx = red[0]; __syncthreads();
    float sum = 0.f;
    for (int i = tid; i < NS; i += 256){
        float e = __expf(p[i]-mx);
        p[i] = e;
        sum += e;
    }
    red[tid] = sum; __syncthreads();
    for (int s = 128; s > 0; s >>= 1){ if (tid < s) red[tid] += red[tid+s]; __syncthreads(); }
    if (tid == 0) kinv[row] = 1.f/red[0];
}

// ---------------- K5: ctx partials ----------------
__global__ void k_ctx_part(const float* __restrict__ ks, const float* __restrict__ vs,
                           float* __restrict__ part)
{
    int bh = blockIdx.y;
    int chunk = blockIdx.x;
    int e    = threadIdx.x >> 5;
    int lane = threadIdx.x & 31;
    int b = bh >> 2, hd = bh & 3;
    const float* kp = ks + ((size_t)(b*Cc + hd*Dd))*NS;
    const float* vp = vs + ((size_t)(b*Cc + hd*Dd + e))*NS;
    float acc[16];
#pragma unroll
    for (int d = 0; d < 16; d++) acc[d] = 0.f;
    int n0 = chunk*1024;
    for (int n = n0 + lane; n < n0 + 1024; n += 32){
        float vv = vp[n];
#pragma unroll
        for (int d = 0; d < 16; d++) acc[d] += kp[(size_t)d*NS + n]*vv;
    }
#pragma unroll
    for (int d = 0; d < 16; d++){
#pragma unroll
        for (int off = 16; off; off >>= 1) acc[d] += __shfl_xor_sync(0xffffffffu, acc[d], off);
    }
    if (lane == 0){
#pragma unroll
        for (int d = 0; d < 16; d++)
            part[(((size_t)bh*32 + chunk)*16 + e)*16 + d] = acc[d];
    }
}

__global__ void k_ctx_reduce(const float* __restrict__ part, const float* __restrict__ kinv,
                             float* __restrict__ ctx)
{
    int bh = blockIdx.x, t = threadIdx.x;
    int e = t >> 4, d = t & 15;
    float s = 0.f;
    for (int ch = 0; ch < 32; ch++) s += part[(((size_t)bh*32 + ch)*16 + e)*16 + d];
    int b = bh >> 2, hd = bh & 3;
    s *= kinv[b*Cc + hd*Dd + d];
    ctx[bh*256 + d*16 + e] = s;
}

// ---------------- K6: att (q softmax fused) ----------------
__global__ void k_att(const float* __restrict__ q, const float* __restrict__ ctx,
                      float* __restrict__ atts)
{
    int bh = blockIdx.y;
    __shared__ float csm[256];
    for (int i = threadIdx.x; i < 256; i += 128) csm[i] = ctx[bh*256 + i];
    __syncthreads();
    int n = blockIdx.x*128 + threadIdx.x;
    int b = bh >> 2, hd = bh & 3;
    const float* qp = q + ((size_t)(b*Cc + hd*Dd))*NS + n;
    float qv[16];
    float mx = -1e30f;
#pragma unroll
    for (int d = 0; d < 16; d++){ qv[d] = qp[(size_t)d*NS]; mx = fmaxf(mx, qv[d]); }
    float ssum = 0.f;
#pragma unroll
    for (int d = 0; d < 16; d++){ qv[d] = __expf(qv[d]-mx); ssum += qv[d]; }
    float inv = 1.f/ssum;
    float o[16];
#pragma unroll
    for (int e = 0; e < 16; e++) o[e] = 0.f;
#pragma unroll
    for (int d = 0; d < 16; d++){
        float qd = qv[d]*inv;
#pragma unroll
        for (int e = 0; e < 16; e++) o[e] += csm[d*16 + e]*qd;
    }
    float* op = atts + ((size_t)(b*Cc + hd*Dd))*NS + n;
#pragma unroll
    for (int e = 0; e < 16; e++) op[(size_t)e*NS] = o[e];
}

// ---------------- K7: 5x5 conv 64->128 (pad 2) reading compact checkerboard input ----------------
__global__ void k_conv5x5(const float* __restrict__ atts, const float* __restrict__ rw,
                          const float* __restrict__ rb, float* __restrict__ out)
{
    int z = blockIdx.z;  int b = z >> 2;  int coBase = (z & 3)*32;
    int wBase = blockIdx.x*32;
    int hBase = blockIdx.y*16;
    int tid = threadIdx.x;
    int px = tid & 15, yl = tid >> 4;
    int y  = hBase + yl;
    int x0 = wBase + 2*px;
    int py = y & 1;

    __shared__ float insm[20*18];
    __shared__ float wsm[25*32];
    int jBase = (wBase >> 1) - 1;

    float aU[32], aV[32];
#pragma unroll
    for (int i = 0; i < 32; i++){ aU[i] = 0.f; aV[i] = 0.f; }

    for (int ci = 0; ci < 64; ci++){
        __syncthreads();
        for (int i = tid; i < 360; i += 256){
            int rr = i/18, jj = i - rr*18;
            int gy = hBase - 2 + rr;
            int gj = jBase + jj;
            float v = 0.f;
            if ((unsigned)gy < Hh && (unsigned)gj < W2)
                v = atts[(((size_t)(b*Cc + ci))*Hh + gy)*W2 + gj];
            insm[rr*18 + jj] = v;
        }
        for (int i = tid; i < 800; i += 256){
            int tap = i >> 5, co = i & 31;
            wsm[tap*32 + co] = rw[((size_t)(coBase + co)*64 + ci)*25 + tap];
        }
        __syncthreads();
#pragma unroll
        for (int ky = 0; ky < 5; ky++){
#pragma unroll
            for (int kx = 0; kx < 5; kx++){
                const int t = (ky + kx) & 1;
                int s  = t ^ py;
                int ix = x0 + s + kx - 2;
                int rr = yl + ky;
                int jj = (ix >> 1) - jBase;
                float iv = insm[rr*18 + jj];
                const float4* w4 = (const float4*)(wsm + (ky*5 + kx)*32);
                if (t == 0){
#pragma unroll
                    for (int c4 = 0; c4 < 8; c4++){
                        float4 wv = w4[c4];
                        aU[c4*4+0] += wv.x*iv; aU[c4*4+1] += wv.y*iv;
                        aU[c4*4+2] += wv.z*iv; aU[c4*4+3] += wv.w*iv;
                    }
                } else {
#pragma unroll
                    for (int c4 = 0; c4 < 8; c4++){
                        float4 wv = w4[c4];
                        aV[c4*4+0] += wv.x*iv; aV[c4*4+1] += wv.y*iv;
                        aV[c4*4+2] += wv.z*iv; aV[c4*4+3] += wv.w*iv;
                    }
                }
            }
        }
    }
#pragma unroll
    for (int co = 0; co < 32; co++){
        float bv = rb[coBase + co];
        size_t base = (((size_t)(b*C2 + coBase + co))*Hh + y)*Ww;
        out[base + x0 + py]       = aU[co] + bv;
        out[base + x0 + 1 - py]   = aV[co] + bv;
    }
}

// ---------------- K9: m2 depthwise 3x3 (C4 channels, pad 1) + gelu ----------------
__global__ void k_dw3x3_gelu(const float* __restrict__ in, const float* __restrict__ w,
                             const float* __restrict__ bias, float* __restrict__ out)
{
    int idx = blockIdx.x*256 + threadIdx.x;
    int x = idx & 255;
    int y = (idx >> 8) & 255;
    int c = (idx >> 16) & 255;
    const float* ip = in + (size_t)(idx >> 16) * NPIX;
    const float* wp = w + c*9;
    float s = bias[c];
#pragma unroll
    for (int dy = -1; dy <= 1; dy++){
        int rr = y + dy;
        if ((unsigned)rr < Hh){
#pragma unroll
            for (int dx = -1; dx <= 1; dx++){
                int cc = x + dx;
                if ((unsigned)cc < Ww)
                    s += wp[(dy+1)*3 + (dx+1)] * ip[rr*Ww + cc];
            }
        }
    }
    out[idx] = gelu_f(s);
}

// ---------------- launch ----------------
extern "C" void kernel_launch(void* const* d_in, const int* in_sizes, int n_in,
                              void* d_out, int out_size)
{
    (void)in_sizes; (void)n_in; (void)out_size;
    const float* x1   = (const float*)d_in[0];
    const float* x2   = (const float*)d_in[1];
    const float* q1_w = (const float*)d_in[2];
    const float* q1_b = (const float*)d_in[3];
    const float* q2_w = (const float*)d_in[4];
    const float* q2_b = (const float*)d_in[5];
    const float* k1_w = (const float*)d_in[6];
    const float* k1_b = (const float*)d_in[7];
    const float* k2_w = (const float*)d_in[8];
    const float* k2_b = (const float*)d_in[9];
    const float* v1_w = (const float*)d_in[10];
    const float* v1_b = (const float*)d_in[11];
    const float* v2_w = (const float*)d_in[12];
    const float* v2_b = (const float*)d_in[13];
    const float* r_w  = (const float*)d_in[14];
    const float* r_b  = (const float*)d_in[15];
    const float* m1_w = (const float*)d_in[16];
    const float* m1_b = (const float*)d_in[17];
    const float* m2_w = (const float*)d_in[18];
    const float* m2_b = (const float*)d_in[19];
    const float* m3_w = (const float*)d_in[20];
    const float* m3_b = (const float*)d_in[21];
    float* out = (float*)d_out;

    float *qs0, *ks0, *vpre, *qs, *ks, *vs, *atts, *kinv, *part, *ctx, *ma, *mb;
    cudaGetSymbolAddress((void**)&qs0,  g_qs0);
    cudaGetSymbolAddress((void**)&ks0,  g_ks0);
    cudaGetSymbolAddress((void**)&vpre, g_vpre);
    cudaGetSymbolAddress((void**)&qs,   g_qs);
    cudaGetSymbolAddress((void**)&ks,   g_ks);
    cudaGetSymbolAddress((void**)&vs,   g_vs);
    cudaGetSymbolAddress((void**)&atts, g_atts);
    cudaGetSymbolAddress((void**)&kinv, g_kinv);
    cudaGetSymbolAddress((void**)&part, g_ctx_part);
    cudaGetSymbolAddress((void**)&ctx,  g_ctx);
    cudaGetSymbolAddress((void**)&ma,   g_ma);
    cudaGetSymbolAddress((void**)&mb,   g_mb);

    cudaFuncSetAttribute(k_gemm_mma<C2, C4, true, false>,
                         cudaFuncAttributeMaxDynamicSharedMemorySize, SM_GEMM_BYTES);
    cudaFuncSetAttribute(k_gemm_mma<C4, C2, false, true>,
                         cudaFuncAttributeMaxDynamicSharedMemorySize, SM_GEMM_BYTES);

    k_conv1x1_qk<<<dim3(NS/256, Bq), 256>>>(x1, q1_w, q1_b, qs0, 0);
    k_conv1x1_qk<<<dim3(NS/256, Bq), 256>>>(x1, k1_w, k1_b, ks0, 1);
    k_conv1x1_v <<<dim3(NPIX/256, Bq), 256>>>(x2, v1_w, v1_b, vpre);

    k_dw3x3_qk<<<(Bq*Cc*NS)/256, 256>>>(qs0, q2_w, q2_b, q1_b, qs, 0);
    k_dw3x3_qk<<<(Bq*Cc*NS)/256, 256>>>(ks0, k2_w, k2_b, k1_b, ks, 1);
    k_dw3x3_v <<<(Bq*Cc*NS)/256, 256>>>(vpre, v2_w, v2_b, vs);

    k_softmax_n_exp<<<Bq*Cc, 256>>>(ks, kinv);

    k_ctx_part<<<dim3(32, Bq*NHEAD), 512>>>(ks, vs, part);
    k_ctx_reduce<<<Bq*NHEAD, 256>>>(part, kinv, ctx);

    k_att<<<dim3(NS/128, Bq*NHEAD), 128>>>(qs, ctx, atts);

    k_conv5x5<<<dim3(Ww/32, Hh/16, Bq*4), 256>>>(atts, r_w, r_b, out);

    // m1: 128 -> 256 + gelu (HMMA split-bf16)
    k_gemm_mma<C2, C4, true, false><<<dim3(Bq*(NPIX/128), C4/128), 256, SM_GEMM_BYTES>>>(out, m1_w, m1_b, ma);
    k_dw3x3_gelu<<<(Bq*C4*NPIX)/256, 256>>>(ma, m2_w, m2_b, mb);
    // m3: 256 -> 128 + residual into out (HMMA split-bf16)
    k_gemm_mma<C4, C2, false, true><<<dim3(Bq*(NPIX/128), C2/128), 256, SM_GEMM_BYTES>>>(mb, m3_w, m3_b, out);
}

// round 7
// speedup vs baseline: 1.8896x; 1.2115x over previous
#include <cuda_runtime.h>
#include <cuda_bf16.h>
#include <math.h>
#include <stdint.h>

#define Bq    4
#define Cc    64
#define Hh    256
#define Ww    256
#define W2    128
#define NPIX  65536   // Hh*Ww
#define NS    32768   // Hh*W2
#define NHEAD 4
#define Dd    16
#define C2    128
#define C4    256

// ---------------- scratch (device globals; no runtime allocation) ----------------
__device__ float g_qs0 [(size_t)Bq*Cc*NS];
__device__ float g_ks0 [(size_t)Bq*Cc*NS];
__device__ float g_vpre[(size_t)Bq*Cc*NPIX];
__device__ float g_qs  [(size_t)Bq*Cc*NS];
__device__ float g_ks  [(size_t)Bq*Cc*NS];
__device__ float g_vs  [(size_t)Bq*Cc*NS];
__device__ float g_atts[(size_t)Bq*Cc*NS];
__device__ float g_kinv[Bq*Cc];
__device__ float g_ctx_part[16*32*16*16];
__device__ float g_ctx[16*256];
__device__ float g_ma[(size_t)Bq*C4*NPIX];
__device__ float g_mb[(size_t)Bq*C4*NPIX];

// tap tables: class 0 = (ky+kx) even (13 taps), class 1 = odd (12 taps)
__device__ __constant__ int8_t TAPS_E[13][2] = {
    {0,0},{0,2},{0,4},{1,1},{1,3},{2,0},{2,2},{2,4},{3,1},{3,3},{4,0},{4,2},{4,4}};
__device__ __constant__ int8_t TAPS_O[12][2] = {
    {0,1},{0,3},{1,0},{1,2},{1,4},{2,1},{2,3},{3,0},{3,2},{3,4},{4,1},{4,3}};

__device__ __forceinline__ float gelu_f(float x){
    return 0.5f * x * (1.0f + erff(x * 0.70710678118654752f));
}

// ================= mma.sync helpers (baseline ISA; compiles for compute_103) =================
__device__ __forceinline__ void ldsm4(uint32_t &r0, uint32_t &r1, uint32_t &r2, uint32_t &r3, uint32_t addr){
    asm volatile("ldmatrix.sync.aligned.m8n8.x4.shared.b16 {%0,%1,%2,%3}, [%4];"
                 : "=r"(r0), "=r"(r1), "=r"(r2), "=r"(r3) : "r"(addr));
}
__device__ __forceinline__ void mma16816(float* c, const uint32_t* a, uint32_t b0, uint32_t b1){
    asm volatile(
        "mma.sync.aligned.m16n8k16.row.col.f32.bf16.bf16.f32 "
        "{%0,%1,%2,%3}, {%4,%5,%6,%7}, {%8,%9}, {%0,%1,%2,%3};"
        : "+f"(c[0]), "+f"(c[1]), "+f"(c[2]), "+f"(c[3])
        : "r"(a[0]), "r"(a[1]), "r"(a[2]), "r"(a[3]), "r"(b0), "r"(b1));
}

#define KC    64
#define PAD   72                              // bf16 per smem row (144B stride, 16B aligned)
#define SMEM_OP (128*PAD)
#define SM_GEMM_BYTES (4*SMEM_OP*2)           // Ah, Al, Bh, Bl

// ================= generic 1x1 GEMM (m1/m3), validated in R6 =================
template<int CIN, int COUT, bool GELU, bool RES>
__global__ void __launch_bounds__(256, 1)
k_gemm_mma(const float* __restrict__ in, const float* __restrict__ w,
           const float* __restrict__ bias, float* __restrict__ out)
{
    extern __shared__ __align__(16) __nv_bfloat16 sm[];
    __nv_bfloat16* Ah = sm;
    __nv_bfloat16* Al = sm + SMEM_OP;
    __nv_bfloat16* Bh = sm + 2*SMEM_OP;
    __nv_bfloat16* Bl = sm + 3*SMEM_OP;
    uint32_t aBaseH = (uint32_t)__cvta_generic_to_shared(Ah);
    uint32_t aBaseL = (uint32_t)__cvta_generic_to_shared(Al);
    uint32_t bBaseH = (uint32_t)__cvta_generic_to_shared(Bh);
    uint32_t bBaseL = (uint32_t)__cvta_generic_to_shared(Bl);

    int tid = threadIdx.x;
    int b = blockIdx.x >> 9;
    int posBase = (blockIdx.x & 511)*128;
    int coBase = blockIdx.y*128;
    int lane = tid & 31, warp = tid >> 5;
    int wco = (warp & 3)*32;
    int wpos = (warp >> 2)*64;

    float acc[2][8][4];
#pragma unroll
    for (int mt = 0; mt < 2; mt++)
#pragma unroll
        for (int nt = 0; nt < 8; nt++)
#pragma unroll
            for (int r = 0; r < 4; r++) acc[mt][nt][r] = 0.f;

    const int KO = CIN/KC;
#pragma unroll 1
    for (int ko = 0; ko < KO; ko++){
        __syncthreads();
        for (int i = tid; i < 128*KC; i += 256){
            int co = i >> 6, k = i & (KC-1);
            float v = w[(size_t)(coBase + co)*CIN + ko*KC + k];
            __nv_bfloat16 h = __float2bfloat16(v);
            __nv_bfloat16 l = __float2bfloat16(v - __bfloat162float(h));
            Ah[co*PAD + k] = h;
            Al[co*PAD + k] = l;
        }
        for (int i = tid; i < 128*KC; i += 256){
            int p = i & 127, ci = i >> 7;
            float v = in[((size_t)(b*CIN + ko*KC + ci))*NPIX + posBase + p];
            __nv_bfloat16 h = __float2bfloat16(v);
            __nv_bfloat16 l = __float2bfloat16(v - __bfloat162float(h));
            Bh[p*PAD + ci] = h;
            Bl[p*PAD + ci] = l;
        }
        __syncthreads();

#pragma unroll
        for (int ks = 0; ks < KC/16; ks++){
            int k0 = ks*16;
            int g = lane >> 3;
            int rofs = (lane & 7) + ((g & 1) ? 8 : 0);
            int cofs = k0 + ((g >> 1) ? 8 : 0);
            uint32_t ah[2][4], al[2][4];
#pragma unroll
            for (int mt = 0; mt < 2; mt++){
                uint32_t off = ((wco + mt*16 + rofs)*PAD + cofs)*2;
                ldsm4(ah[mt][0], ah[mt][1], ah[mt][2], ah[mt][3], aBaseH + off);
                ldsm4(al[mt][0], al[mt][1], al[mt][2], al[mt][3], aBaseL + off);
            }
            uint32_t bh[4][4], bl[4][4];
#pragma unroll
            for (int ntp = 0; ntp < 4; ntp++){
                uint32_t off = ((wpos + ntp*16 + rofs)*PAD + cofs)*2;
                ldsm4(bh[ntp][0], bh[ntp][1], bh[ntp][2], bh[ntp][3], bBaseH + off);
                ldsm4(bl[ntp][0], bl[ntp][1], bl[ntp][2], bl[ntp][3], bBaseL + off);
            }
#pragma unroll
            for (int mt = 0; mt < 2; mt++){
#pragma unroll
                for (int ntp = 0; ntp < 4; ntp++){
#pragma unroll
                    for (int sub = 0; sub < 2; sub++){
                        int nt = ntp*2 + sub;
                        uint32_t h0 = bh[ntp][sub], h1 = bh[ntp][sub+2];
                        uint32_t l0 = bl[ntp][sub], l1 = bl[ntp][sub+2];
                        mma16816(acc[mt][nt], ah[mt], h0, h1);
                        mma16816(acc[mt][nt], ah[mt], l0, l1);
                        mma16816(acc[mt][nt], al[mt], h0, h1);
                    }
                }
            }
        }
    }

    {
        int r = lane >> 2, cc = (lane & 3)*2;
#pragma unroll
        for (int mt = 0; mt < 2; mt++){
            int co0 = coBase + wco + mt*16 + r;
            float bv0 = bias[co0], bv8 = bias[co0 + 8];
            float* op0 = out + ((size_t)(b*COUT + co0    ))*NPIX + posBase + wpos + cc;
            float* op8 = out + ((size_t)(b*COUT + co0 + 8))*NPIX + posBase + wpos + cc;
#pragma unroll
            for (int nt = 0; nt < 8; nt++){
                float2 v0, v8;
                v0.x = acc[mt][nt][0] + bv0;  v0.y = acc[mt][nt][1] + bv0;
                v8.x = acc[mt][nt][2] + bv8;  v8.y = acc[mt][nt][3] + bv8;
                if (GELU){
                    v0.x = gelu_f(v0.x); v0.y = gelu_f(v0.y);
                    v8.x = gelu_f(v8.x); v8.y = gelu_f(v8.y);
                }
                if (RES){
                    float2 o0 = *(const float2*)(op0 + nt*8);
                    float2 o8 = *(const float2*)(op8 + nt*8);
                    v0.x += o0.x; v0.y += o0.y;
                    v8.x += o8.x; v8.y += o8.y;
                }
                *(float2*)(op0 + nt*8) = v0;
                *(float2*)(op8 + nt*8) = v8;
            }
        }
    }
}

// ================= conv5x5 as implicit GEMM (tap-major K) =================
// Class pc: output pixels (y, x=2j+s), s=(y&1)^pc. Only taps with (ky+kx)%2==pc contribute.
// Per tap: K-chunk = 64 ci; B[p][ci] = atts[b][ci][y+ky-2][j + ((s+kx-2)>>1)] (coalesced slice).
__global__ void __launch_bounds__(256, 1)
k_conv5x5_mma(const float* __restrict__ atts, const float* __restrict__ rw,
              const float* __restrict__ rb, float* __restrict__ out)
{
    extern __shared__ __align__(16) __nv_bfloat16 sm[];
    __nv_bfloat16* Ah = sm;
    __nv_bfloat16* Al = sm + SMEM_OP;
    __nv_bfloat16* Bh = sm + 2*SMEM_OP;
    __nv_bfloat16* Bl = sm + 3*SMEM_OP;
    uint32_t aBaseH = (uint32_t)__cvta_generic_to_shared(Ah);
    uint32_t aBaseL = (uint32_t)__cvta_generic_to_shared(Al);
    uint32_t bBaseH = (uint32_t)__cvta_generic_to_shared(Bh);
    uint32_t bBaseL = (uint32_t)__cvta_generic_to_shared(Bl);

    int tid = threadIdx.x;
    int tx = blockIdx.x;                  // 256 tiles: 32 y-tiles x 8 j-tiles
    int z = blockIdx.y;                   // b*2 + pc
    int b = z >> 1, pc = z & 1;
    int jBase = (tx & 7)*16;
    int yBase = (tx >> 3)*8;
    int NT = pc ? 12 : 13;
    int lane = tid & 31, warp = tid >> 5;
    int wco = (warp & 3)*32;
    int wpos = (warp >> 2)*64;

    float acc[2][8][4];
#pragma unroll
    for (int mt = 0; mt < 2; mt++)
#pragma unroll
        for (int nt = 0; nt < 8; nt++)
#pragma unroll
            for (int r = 0; r < 4; r++) acc[mt][nt][r] = 0.f;

#pragma unroll 1
    for (int t = 0; t < NT; t++){
        int ky = pc ? TAPS_O[t][0] : TAPS_E[t][0];
        int kx = pc ? TAPS_O[t][1] : TAPS_E[t][1];
        int tap = ky*5 + kx;
        __syncthreads();
        // stage A = rw[co][ci][tap]
        for (int i = tid; i < 8192; i += 256){
            int co = i >> 6, ci = i & 63;
            float v = rw[(size_t)(co*64 + ci)*25 + tap];
            __nv_bfloat16 h = __float2bfloat16(v);
            __nv_bfloat16 l = __float2bfloat16(v - __bfloat162float(h));
            Ah[co*PAD + ci] = h;
            Al[co*PAD + ci] = l;
        }
        // stage B: shifted slice of atts
        for (int i = tid; i < 8192; i += 256){
            int p = i & 127, ci = i >> 7;
            int yl = p >> 4, jx = p & 15;
            int y = yBase + yl;
            int s = (y & 1) ^ pc;
            int yy = y + ky - 2;
            int jj = jBase + jx + (((s + kx - 2)) >> 1);   // arithmetic shift = floor div 2
            float v = 0.f;
            if ((unsigned)yy < Hh && (unsigned)jj < W2)
                v = atts[((size_t)(b*Cc + ci))*NS + yy*W2 + jj];
            __nv_bfloat16 h = __float2bfloat16(v);
            __nv_bfloat16 l = __float2bfloat16(v - __bfloat162float(h));
            Bh[p*PAD + ci] = h;
            Bl[p*PAD + ci] = l;
        }
        __syncthreads();

#pragma unroll
        for (int ks = 0; ks < 4; ks++){
            int k0 = ks*16;
            int g = lane >> 3;
            int rofs = (lane & 7) + ((g & 1) ? 8 : 0);
            int cofs = k0 + ((g >> 1) ? 8 : 0);
            uint32_t ah[2][4], al[2][4];
#pragma unroll
            for (int mt = 0; mt < 2; mt++){
                uint32_t off = ((wco + mt*16 + rofs)*PAD + cofs)*2;
                ldsm4(ah[mt][0], ah[mt][1], ah[mt][2], ah[mt][3], aBaseH + off);
                ldsm4(al[mt][0], al[mt][1], al[mt][2], al[mt][3], aBaseL + off);
            }
            uint32_t bh[4][4], bl[4][4];
#pragma unroll
            for (int ntp = 0; ntp < 4; ntp++){
                uint32_t off = ((wpos + ntp*16 + rofs)*PAD + cofs)*2;
                ldsm4(bh[ntp][0], bh[ntp][1], bh[ntp][2], bh[ntp][3], bBaseH + off);
                ldsm4(bl[ntp][0], bl[ntp][1], bl[ntp][2], bl[ntp][3], bBaseL + off);
            }
#pragma unroll
            for (int mt = 0; mt < 2; mt++){
#pragma unroll
                for (int ntp = 0; ntp < 4; ntp++){
#pragma unroll
                    for (int sub = 0; sub < 2; sub++){
                        int nt = ntp*2 + sub;
                        uint32_t h0 = bh[ntp][sub], h1 = bh[ntp][sub+2];
                        uint32_t l0 = bl[ntp][sub], l1 = bl[ntp][sub+2];
                        mma16816(acc[mt][nt], ah[mt], h0, h1);
                        mma16816(acc[mt][nt], ah[mt], l0, l1);
                        mma16816(acc[mt][nt], al[mt], h0, h1);
                    }
                }
            }
        }
    }

    // epilogue: p = wpos + nt*8 + (lane&3)*2 (+1); rows co0, co0+8
    {
        int r = lane >> 2, cc = (lane & 3)*2;
#pragma unroll
        for (int mt = 0; mt < 2; mt++){
            int co0 = wco + mt*16 + r;
            float bv0 = rb[co0], bv8 = rb[co0 + 8];
#pragma unroll
            for (int nt = 0; nt < 8; nt++){
                int p = wpos + nt*8 + cc;
                int yl = p >> 4, jx = p & 15;
                int y = yBase + yl;
                int s = (y & 1) ^ pc;
                int x0 = 2*(jBase + jx) + s;
                size_t r0 = ((size_t)(b*C2 + co0    ))*NPIX + y*Ww + x0;
                size_t r8 = ((size_t)(b*C2 + co0 + 8))*NPIX + y*Ww + x0;
                out[r0]     = acc[mt][nt][0] + bv0;
                out[r0 + 2] = acc[mt][nt][1] + bv0;
                out[r8]     = acc[mt][nt][2] + bv8;
                out[r8 + 2] = acc[mt][nt][3] + bv8;
            }
        }
    }
}

// ---------------- K1a: 1x1 conv (64->64) only at kept parity, stored squeezed ----------------
__global__ void k_conv1x1_qk(const float* __restrict__ x, const float* __restrict__ w,
                             const float* __restrict__ bias, float* __restrict__ outSq, int anchorSel)
{
    __shared__ float wsm[64*64];
    int tid = threadIdx.x;
    for (int i = tid; i < 4096; i += 256){
        int co = i & 63, ci = i >> 6;
        wsm[ci*64 + co] = w[co*64 + ci];
    }
    __syncthreads();
    int b  = blockIdx.y;
    int ps = blockIdx.x*256 + tid;
    int j = ps & (W2-1);
    int r = ps >> 7;
    int col = 2*j + (anchorSel ? (1 - (r & 1)) : (r & 1));
    const float* xp = x + (size_t)b*Cc*NPIX + r*Ww + col;

    float acc[64];
#pragma unroll
    for (int i = 0; i < 64; i++) acc[i] = 0.f;
    for (int ci = 0; ci < 64; ci++){
        float xv = xp[(size_t)ci*NPIX];
        const float4* w4 = (const float4*)(wsm + ci*64);
#pragma unroll
        for (int c4 = 0; c4 < 16; c4++){
            float4 wv = w4[c4];
            acc[c4*4+0] += wv.x*xv; acc[c4*4+1] += wv.y*xv;
            acc[c4*4+2] += wv.z*xv; acc[c4*4+3] += wv.w*xv;
        }
    }
    float* op = outSq + (size_t)b*Cc*NS + ps;
#pragma unroll
    for (int co = 0; co < 64; co++)
        op[(size_t)co*NS] = acc[co] + bias[co];
}

// ---------------- K1b: 1x1 conv (64->64) full image (v) ----------------
__global__ void k_conv1x1_v(const float* __restrict__ x, const float* __restrict__ w,
                            const float* __restrict__ bias, float* __restrict__ out)
{
    __shared__ float wsm[64*64];
    int tid = threadIdx.x;
    for (int i = tid; i < 4096; i += 256){
        int co = i & 63, ci = i >> 6;
        wsm[ci*64 + co] = w[co*64 + ci];
    }
    __syncthreads();
    int b   = blockIdx.y;
    int pos = blockIdx.x*256 + tid;
    const float* xp = x + (size_t)b*Cc*NPIX + pos;
    float acc[64];
#pragma unroll
    for (int i = 0; i < 64; i++) acc[i] = 0.f;
    for (int ci = 0; ci < 64; ci++){
        float xv = xp[(size_t)ci*NPIX];
        const float4* w4 = (const float4*)(wsm + ci*64);
#pragma unroll
        for (int c4 = 0; c4 < 16; c4++){
            float4 wv = w4[c4];
            acc[c4*4+0] += wv.x*xv; acc[c4*4+1] += wv.y*xv;
            acc[c4*4+2] += wv.z*xv; acc[c4*4+3] += wv.w*xv;
        }
    }
    float* op = out + (size_t)b*Cc*NPIX + pos;
#pragma unroll
    for (int co = 0; co < 64; co++)
        op[(size_t)co*NPIX] = acc[co] + bias[co];
}

// ---------------- K2a: depthwise 3x3 for q/k on squeezed pre-buffer ----------------
__global__ void k_dw3x3_qk(const float* __restrict__ in, const float* __restrict__ w,
                           const float* __restrict__ bias, const float* __restrict__ pbias,
                           float* __restrict__ out, int anchorSel)
{
    int idx = blockIdx.x*256 + threadIdx.x;
    int j = idx & (W2-1);
    int r = (idx >> 7) & (Hh-1);
    int c = (idx >> 15) & (Cc-1);
    int o = anchorSel ? (1 - (r & 1)) : (r & 1);
    int col = 2*j + o;
    const float* ip = in + (size_t)(idx >> 15) * NS;
    const float* wp = w + c*9;

    float s = bias[c] + wp[4]*ip[r*W2 + j];
    float cb = pbias[c];
    float bw = 0.f;
    if (r > 0)       bw += wp[1];
    if (r < Hh-1)    bw += wp[7];
    if (col > 0)     bw += wp[3];
    if (col < Ww-1)  bw += wp[5];
    s += cb * bw;
    int jm = j - 1 + o, jp = j + o;
    if (r > 0){
        const float* rp = ip + (r-1)*W2;
        if ((unsigned)jm < W2) s += wp[0]*rp[jm];
        if ((unsigned)jp < W2) s += wp[2]*rp[jp];
    }
    if (r < Hh-1){
        const float* rp = ip + (r+1)*W2;
        if ((unsigned)jm < W2) s += wp[6]*rp[jm];
        if ((unsigned)jp < W2) s += wp[8]*rp[jp];
    }
    out[idx] = s;
}

// ---------------- K2b: depthwise 3x3 for v (full input, anchor output, squeezed) ----------------
__global__ void k_dw3x3_v(const float* __restrict__ in, const float* __restrict__ w,
                          const float* __restrict__ bias, float* __restrict__ out)
{
    int idx = blockIdx.x*256 + threadIdx.x;
    int j = idx & (W2-1);
    int r = (idx >> 7) & (Hh-1);
    int c = (idx >> 15) & (Cc-1);
    int col = 2*j + (1 - (r & 1));
    const float* ip = in + (size_t)(idx >> 15) * NPIX;
    const float* wp = w + c*9;
    float s = bias[c];
#pragma unroll
    for (int dy = -1; dy <= 1; dy++){
        int rr = r + dy;
        if ((unsigned)rr < Hh){
#pragma unroll
            for (int dx = -1; dx <= 1; dx++){
                int cc = col + dx;
                if ((unsigned)cc < Ww)
                    s += wp[(dy+1)*3 + (dx+1)] * ip[rr*Ww + cc];
            }
        }
    }
    out[idx] = s;
}

// ---------------- K4: k softmax (max + exp; normalization deferred) ----------------
__global__ void k_softmax_n_exp(float* __restrict__ kk, float* __restrict__ kinv)
{
    int row = blockIdx.x;
    float* p = kk + (size_t)row*NS;
    int tid = threadIdx.x;
    __shared__ float red[256];
    float mx = -1e30f;
    for (int i = tid; i < NS; i += 256) mx = fmaxf(mx, p[i]);
    red[tid] = mx; __syncthreads();
    for (int s = 128; s > 0; s >>= 1){ if (tid < s) red[tid] = fmaxf(red[tid], red[tid+s]); __syncthreads(); }
    mx = red[0]; __syncthreads();
    float sum = 0.f;
    for (int i = tid; i < NS; i += 256){
        float e = __expf(p[i]-mx);
        p[i] = e;
        sum += e;
    }
    red[tid] = sum; __syncthreads();
    for (int s = 128; s > 0; s >>= 1){ if (tid < s) red[tid] += red[tid+s]; __syncthreads(); }
    if (tid == 0) kinv[row] = 1.f/red[0];
}

// ---------------- K5: ctx partials ----------------
__global__ void k_ctx_part(const float* __restrict__ ks, const float* __restrict__ vs,
                           float* __restrict__ part)
{
    int bh = blockIdx.y;
    int chunk = blockIdx.x;
    int e    = threadIdx.x >> 5;
    int lane = threadIdx.x & 31;
    int b = bh >> 2, hd = bh & 3;
    const float* kp = ks + ((size_t)(b*Cc + hd*Dd))*NS;
    const float* vp = vs + ((size_t)(b*Cc + hd*Dd + e))*NS;
    float acc[16];
#pragma unroll
    for (int d = 0; d < 16; d++) acc[d] = 0.f;
    int n0 = chunk*1024;
    for (int n = n0 + lane; n < n0 + 1024; n += 32){
        float vv = vp[n];
#pragma unroll
        for (int d = 0; d < 16; d++) acc[d] += kp[(size_t)d*NS + n]*vv;
    }
#pragma unroll
    for (int d = 0; d < 16; d++){
#pragma unroll
        for (int off = 16; off; off >>= 1) acc[d] += __shfl_xor_sync(0xffffffffu, acc[d], off);
    }
    if (lane == 0){
#pragma unroll
        for (int d = 0; d < 16; d++)
            part[(((size_t)bh*32 + chunk)*16 + e)*16 + d] = acc[d];
    }
}

__global__ void k_ctx_reduce(const float* __restrict__ part, const float* __restrict__ kinv,
                             float* __restrict__ ctx)
{
    int bh = blockIdx.x, t = threadIdx.x;
    int e = t >> 4, d = t & 15;
    float s = 0.f;
    for (int ch = 0; ch < 32; ch++) s += part[(((size_t)bh*32 + ch)*16 + e)*16 + d];
    int b = bh >> 2, hd = bh & 3;
    s *= kinv[b*Cc + hd*Dd + d];
    ctx[bh*256 + d*16 + e] = s;
}

// ---------------- K6: att (q softmax fused) ----------------
__global__ void k_att(const float* __restrict__ q, const float* __restrict__ ctx,
                      float* __restrict__ atts)
{
    int bh = blockIdx.y;
    __shared__ float csm[256];
    for (int i = threadIdx.x; i < 256; i += 128) csm[i] = ctx[bh*256 + i];
    __syncthreads();
    int n = blockIdx.x*128 + threadIdx.x;
    int b = bh >> 2, hd = bh & 3;
    const float* qp = q + ((size_t)(b*Cc + hd*Dd))*NS + n;
    float qv[16];
    float mx = -1e30f;
#pragma unroll
    for (int d = 0; d < 16; d++){ qv[d] = qp[(size_t)d*NS]; mx = fmaxf(mx, qv[d]); }
    float ssum = 0.f;
#pragma unroll
    for (int d = 0; d < 16; d++){ qv[d] = __expf(qv[d]-mx); ssum += qv[d]; }
    float inv = 1.f/ssum;
    float o[16];
#pragma unroll
    for (int e = 0; e < 16; e++) o[e] = 0.f;
#pragma unroll
    for (int d = 0; d < 16; d++){
        float qd = qv[d]*inv;
#pragma unroll
        for (int e = 0; e < 16; e++) o[e] += csm[d*16 + e]*qd;
    }
    float* op = atts + ((size_t)(b*Cc + hd*Dd))*NS + n;
#pragma unroll
    for (int e = 0; e < 16; e++) op[(size_t)e*NS] = o[e];
}

// ---------------- K9: m2 depthwise 3x3 (C4 channels, pad 1) + gelu ----------------
__global__ void k_dw3x3_gelu(const float* __restrict__ in, const float* __restrict__ w,
                             const float* __restrict__ bias, float* __restrict__ out)
{
    int idx = blockIdx.x*256 + threadIdx.x;
    int x = idx & 255;
    int y = (idx >> 8) & 255;
    int c = (idx >> 16) & 255;
    const float* ip = in + (size_t)(idx >> 16) * NPIX;
    const float* wp = w + c*9;
    float s = bias[c];
#pragma unroll
    for (int dy = -1; dy <= 1; dy++){
        int rr = y + dy;
        if ((unsigned)rr < Hh){
#pragma unroll
            for (int dx = -1; dx <= 1; dx++){
                int cc = x + dx;
                if ((unsigned)cc < Ww)
                    s += wp[(dy+1)*3 + (dx+1)] * ip[rr*Ww + cc];
            }
        }
    }
    out[idx] = gelu_f(s);
}

// ---------------- launch ----------------
extern "C" void kernel_launch(void* const* d_in, const int* in_sizes, int n_in,
                              void* d_out, int out_size)
{
    (void)in_sizes; (void)n_in; (void)out_size;
    const float* x1   = (const float*)d_in[0];
    const float* x2   = (const float*)d_in[1];
    const float* q1_w = (const float*)d_in[2];
    const float* q1_b = (const float*)d_in[3];
    const float* q2_w = (const float*)d_in[4];
    const float* q2_b = (const float*)d_in[5];
    const float* k1_w = (const float*)d_in[6];
    const float* k1_b = (const float*)d_in[7];
    const float* k2_w = (const float*)d_in[8];
    const float* k2_b = (const float*)d_in[9];
    const float* v1_w = (const float*)d_in[10];
    const float* v1_b = (const float*)d_in[11];
    const float* v2_w = (const float*)d_in[12];
    const float* v2_b = (const float*)d_in[13];
    const float* r_w  = (const float*)d_in[14];
    const float* r_b  = (const float*)d_in[15];
    const float* m1_w = (const float*)d_in[16];
    const float* m1_b = (const float*)d_in[17];
    const float* m2_w = (const float*)d_in[18];
    const float* m2_b = (const float*)d_in[19];
    const float* m3_w = (const float*)d_in[20];
    const float* m3_b = (const float*)d_in[21];
    float* out = (float*)d_out;

    float *qs0, *ks0, *vpre, *qs, *ks, *vs, *atts, *kinv, *part, *ctx, *ma, *mb;
    cudaGetSymbolAddress((void**)&qs0,  g_qs0);
    cudaGetSymbolAddress((void**)&ks0,  g_ks0);
    cudaGetSymbolAddress((void**)&vpre, g_vpre);
    cudaGetSymbolAddress((void**)&qs,   g_qs);
    cudaGetSymbolAddress((void**)&ks,   g_ks);
    cudaGetSymbolAddress((void**)&vs,   g_vs);
    cudaGetSymbolAddress((void**)&atts, g_atts);
    cudaGetSymbolAddress((void**)&kinv, g_kinv);
    cudaGetSymbolAddress((void**)&part, g_ctx_part);
    cudaGetSymbolAddress((void**)&ctx,  g_ctx);
    cudaGetSymbolAddress((void**)&ma,   g_ma);
    cudaGetSymbolAddress((void**)&mb,   g_mb);

    cudaFuncSetAttribute(k_gemm_mma<C2, C4, true, false>,
                         cudaFuncAttributeMaxDynamicSharedMemorySize, SM_GEMM_BYTES);
    cudaFuncSetAttribute(k_gemm_mma<C4, C2, false, true>,
                         cudaFuncAttributeMaxDynamicSharedMemorySize, SM_GEMM_BYTES);
    cudaFuncSetAttribute(k_conv5x5_mma,
                         cudaFuncAttributeMaxDynamicSharedMemorySize, SM_GEMM_BYTES);

    k_conv1x1_qk<<<dim3(NS/256, Bq), 256>>>(x1, q1_w, q1_b, qs0, 0);
    k_conv1x1_qk<<<dim3(NS/256, Bq), 256>>>(x1, k1_w, k1_b, ks0, 1);
    k_conv1x1_v <<<dim3(NPIX/256, Bq), 256>>>(x2, v1_w, v1_b, vpre);

    k_dw3x3_qk<<<(Bq*Cc*NS)/256, 256>>>(qs0, q2_w, q2_b, q1_b, qs, 0);
    k_dw3x3_qk<<<(Bq*Cc*NS)/256, 256>>>(ks0, k2_w, k2_b, k1_b, ks, 1);
    k_dw3x3_v <<<(Bq*Cc*NS)/256, 256>>>(vpre, v2_w, v2_b, vs);

    k_softmax_n_exp<<<Bq*Cc, 256>>>(ks, kinv);

    k_ctx_part<<<dim3(32, Bq*NHEAD), 512>>>(ks, vs, part);
    k_ctx_reduce<<<Bq*NHEAD, 256>>>(part, kinv, ctx);

    k_att<<<dim3(NS/128, Bq*NHEAD), 128>>>(qs, ctx, atts);

    // conv5x5 via implicit GEMM (HMMA split-bf16), two parity classes
    k_conv5x5_mma<<<dim3(256, Bq*2), 256, SM_GEMM_BYTES>>>(atts, r_w, r_b, out);

    // m1: 128 -> 256 + gelu (HMMA split-bf16)
    k_gemm_mma<C2, C4, true, false><<<dim3(Bq*(NPIX/128), C4/128), 256, SM_GEMM_BYTES>>>(out, m1_w, m1_b, ma);
    k_dw3x3_gelu<<<(Bq*C4*NPIX)/256, 256>>>(ma, m2_w, m2_b, mb);
    // m3: 256 -> 128 + residual into out (HMMA split-bf16)
    k_gemm_mma<C4, C2, false, true><<<dim3(Bq*(NPIX/128), C2/128), 256, SM_GEMM_BYTES>>>(mb, m3_w, m3_b, out);
}

// round 8
// speedup vs baseline: 1.9915x; 1.0539x over previous
#include <cuda_runtime.h>
#include <cuda_bf16.h>
#include <math.h>
#include <stdint.h>

#define Bq    4
#define Cc    64
#define Hh    256
#define Ww    256
#define W2    128
#define NPIX  65536   // Hh*Ww
#define NS    32768   // Hh*W2
#define NHEAD 4
#define Dd    16
#define C2    128
#define C4    256

// ---------------- scratch (device globals; no runtime allocation) ----------------
__device__ float g_qs0 [(size_t)Bq*Cc*NS];
__device__ float g_ks0 [(size_t)Bq*Cc*NS];
__device__ float g_vpre[(size_t)Bq*Cc*NPIX];
__device__ float g_qs  [(size_t)Bq*Cc*NS];
__device__ float g_ks  [(size_t)Bq*Cc*NS];
__device__ float g_vs  [(size_t)Bq*Cc*NS];
__device__ float g_kinv[Bq*Cc];
__device__ float g_ctx_part[16*32*16*16];
__device__ float g_ctx[16*256];
__device__ float g_ma[(size_t)Bq*C4*NPIX];
__device__ float g_mb[(size_t)Bq*C4*NPIX];
// bf16 hi/lo staging sources
__device__ __nv_bfloat16 g_attsTh[(size_t)Bq*NS*64];   // [b][n][ci]
__device__ __nv_bfloat16 g_attsTl[(size_t)Bq*NS*64];
__device__ __nv_bfloat16 g_rw5h[25*128*64];            // [tap][co][ci]
__device__ __nv_bfloat16 g_rw5l[25*128*64];
__device__ __nv_bfloat16 g_m1wh[C4*C2];
__device__ __nv_bfloat16 g_m1wl[C4*C2];
__device__ __nv_bfloat16 g_m3wh[C2*C4];
__device__ __nv_bfloat16 g_m3wl[C2*C4];

// tap tables: class 0 = (ky+kx) even (13 taps), class 1 = odd (12 taps)
__device__ __constant__ int8_t TAPS_E[13][2] = {
    {0,0},{0,2},{0,4},{1,1},{1,3},{2,0},{2,2},{2,4},{3,1},{3,3},{4,0},{4,2},{4,4}};
__device__ __constant__ int8_t TAPS_O[12][2] = {
    {0,1},{0,3},{1,0},{1,2},{1,4},{2,1},{2,3},{3,0},{3,2},{3,4},{4,1},{4,3}};

__device__ __forceinline__ float gelu_f(float x){
    return 0.5f * x * (1.0f + erff(x * 0.70710678118654752f));
}

// ================= mma.sync + cp.async helpers (baseline ISA) =================
__device__ __forceinline__ void ldsm4(uint32_t &r0, uint32_t &r1, uint32_t &r2, uint32_t &r3, uint32_t addr){
    asm volatile("ldmatrix.sync.aligned.m8n8.x4.shared.b16 {%0,%1,%2,%3}, [%4];"
                 : "=r"(r0), "=r"(r1), "=r"(r2), "=r"(r3) : "r"(addr));
}
__device__ __forceinline__ void mma16816(float* c, const uint32_t* a, uint32_t b0, uint32_t b1){
    asm volatile(
        "mma.sync.aligned.m16n8k16.row.col.f32.bf16.bf16.f32 "
        "{%0,%1,%2,%3}, {%4,%5,%6,%7}, {%8,%9}, {%0,%1,%2,%3};"
        : "+f"(c[0]), "+f"(c[1]), "+f"(c[2]), "+f"(c[3])
        : "r"(a[0]), "r"(a[1]), "r"(a[2]), "r"(a[3]), "r"(b0), "r"(b1));
}
__device__ __forceinline__ void cpasync16(uint32_t smem_addr, const void* gptr, int src_bytes){
    asm volatile("cp.async.cg.shared.global [%0], [%1], 16, %2;"
                 :: "r"(smem_addr), "l"(gptr), "r"(src_bytes) : "memory");
}
#define CPASYNC_WAIT_ALL() asm volatile("cp.async.commit_group;\ncp.async.wait_group 0;" ::: "memory")

#define KC    64
#define PAD   72                              // bf16 per smem row (144B stride, 16B aligned)
#define PADB  144
#define SMEM_OP (128*PAD)
#define SM_GEMM_BYTES (4*SMEM_OP*2)           // Ah, Al, Bh, Bl

// ================= prep kernels: one-time float -> bf16 hi/lo =================
__global__ void k_prep_w(const float* __restrict__ w, __nv_bfloat16* __restrict__ h,
                         __nv_bfloat16* __restrict__ l, int n)
{
    int i = blockIdx.x*256 + threadIdx.x;
    if (i < n){
        float v = w[i];
        __nv_bfloat16 hh = __float2bfloat16(v);
        h[i] = hh;
        l[i] = __float2bfloat16(v - __bfloat162float(hh));
    }
}
__global__ void k_prep_rw5(const float* __restrict__ rw, __nv_bfloat16* __restrict__ h,
                           __nv_bfloat16* __restrict__ l)
{
    int i = blockIdx.x*256 + threadIdx.x;      // 25*128*64 = 204800
    int tap = i >> 13;                          // /8192
    int rem = i & 8191;                         // co*64+ci
    float v = rw[(size_t)rem*25 + tap];
    __nv_bfloat16 hh = __float2bfloat16(v);
    h[i] = hh;
    l[i] = __float2bfloat16(v - __bfloat162float(hh));
}

// ================= generic 1x1 GEMM (m1/m3), bf16-prepped A, cp.async A-stage =================
template<int CIN, int COUT, bool GELU, bool RES>
__global__ void __launch_bounds__(256, 1)
k_gemm_mma(const float* __restrict__ in,
           const __nv_bfloat16* __restrict__ wh, const __nv_bfloat16* __restrict__ wl,
           const float* __restrict__ bias, float* __restrict__ out)
{
    extern __shared__ __align__(16) __nv_bfloat16 sm[];
    __nv_bfloat16* Bh = sm + 2*SMEM_OP;
    __nv_bfloat16* Bl = sm + 3*SMEM_OP;
    uint32_t aBaseH = (uint32_t)__cvta_generic_to_shared(sm);
    uint32_t aBaseL = aBaseH + SMEM_OP*2;
    uint32_t bBaseH = aBaseH + 2*SMEM_OP*2;
    uint32_t bBaseL = aBaseH + 3*SMEM_OP*2;

    int tid = threadIdx.x;
    int b = blockIdx.x >> 9;
    int posBase = (blockIdx.x & 511)*128;
    int coBase = blockIdx.y*128;
    int lane = tid & 31, warp = tid >> 5;
    int wco = (warp & 3)*32;
    int wpos = (warp >> 2)*64;

    float acc[2][8][4];
#pragma unroll
    for (int mt = 0; mt < 2; mt++)
#pragma unroll
        for (int nt = 0; nt < 8; nt++)
#pragma unroll
            for (int r = 0; r < 4; r++) acc[mt][nt][r] = 0.f;

    const int KO = CIN/KC;
#pragma unroll 1
    for (int ko = 0; ko < KO; ko++){
        __syncthreads();
        // A-stage: cp.async 16B chunks from prepped weights (contiguous rows of 64)
        for (int i = tid; i < 1024; i += 256){
            int co = i >> 3, ch = i & 7;
            uint32_t d = co*PADB + ch*16;
            const __nv_bfloat16* s = wh + (size_t)(coBase + co)*CIN + ko*KC + ch*8;
            const __nv_bfloat16* s2 = wl + (size_t)(coBase + co)*CIN + ko*KC + ch*8;
            cpasync16(aBaseH + d, s, 16);
            cpasync16(aBaseL + d, s2, 16);
        }
        // B-stage: float load + split (in is produced as float)
        for (int i = tid; i < 128*KC; i += 256){
            int p = i & 127, ci = i >> 7;
            float v = in[((size_t)(b*CIN + ko*KC + ci))*NPIX + posBase + p];
            __nv_bfloat16 h = __float2bfloat16(v);
            __nv_bfloat16 l = __float2bfloat16(v - __bfloat162float(h));
            Bh[p*PAD + ci] = h;
            Bl[p*PAD + ci] = l;
        }
        CPASYNC_WAIT_ALL();
        __syncthreads();

#pragma unroll
        for (int ks = 0; ks < KC/16; ks++){
            int k0 = ks*16;
            int g = lane >> 3;
            int rofs = (lane & 7) + ((g & 1) ? 8 : 0);
            int cofs = k0 + ((g >> 1) ? 8 : 0);
            uint32_t ah[2][4], al[2][4];
#pragma unroll
            for (int mt = 0; mt < 2; mt++){
                uint32_t off = ((wco + mt*16 + rofs)*PAD + cofs)*2;
                ldsm4(ah[mt][0], ah[mt][1], ah[mt][2], ah[mt][3], aBaseH + off);
                ldsm4(al[mt][0], al[mt][1], al[mt][2], al[mt][3], aBaseL + off);
            }
            uint32_t bh[4][4], bl[4][4];
#pragma unroll
            for (int ntp = 0; ntp < 4; ntp++){
                uint32_t off = ((wpos + ntp*16 + rofs)*PAD + cofs)*2;
                ldsm4(bh[ntp][0], bh[ntp][1], bh[ntp][2], bh[ntp][3], bBaseH + off);
                ldsm4(bl[ntp][0], bl[ntp][1], bl[ntp][2], bl[ntp][3], bBaseL + off);
            }
#pragma unroll
            for (int mt = 0; mt < 2; mt++){
#pragma unroll
                for (int ntp = 0; ntp < 4; ntp++){
#pragma unroll
                    for (int sub = 0; sub < 2; sub++){
                        int nt = ntp*2 + sub;
                        uint32_t h0 = bh[ntp][sub], h1 = bh[ntp][sub+2];
                        uint32_t l0 = bl[ntp][sub], l1 = bl[ntp][sub+2];
                        mma16816(acc[mt][nt], ah[mt], h0, h1);
                        mma16816(acc[mt][nt], ah[mt], l0, l1);
                        mma16816(acc[mt][nt], al[mt], h0, h1);
                    }
                }
            }
        }
    }

    {
        int r = lane >> 2, cc = (lane & 3)*2;
#pragma unroll
        for (int mt = 0; mt < 2; mt++){
            int co0 = coBase + wco + mt*16 + r;
            float bv0 = bias[co0], bv8 = bias[co0 + 8];
            float* op0 = out + ((size_t)(b*COUT + co0    ))*NPIX + posBase + wpos + cc;
            float* op8 = out + ((size_t)(b*COUT + co0 + 8))*NPIX + posBase + wpos + cc;
#pragma unroll
            for (int nt = 0; nt < 8; nt++){
                float2 v0, v8;
                v0.x = acc[mt][nt][0] + bv0;  v0.y = acc[mt][nt][1] + bv0;
                v8.x = acc[mt][nt][2] + bv8;  v8.y = acc[mt][nt][3] + bv8;
                if (GELU){
                    v0.x = gelu_f(v0.x); v0.y = gelu_f(v0.y);
                    v8.x = gelu_f(v8.x); v8.y = gelu_f(v8.y);
                }
                if (RES){
                    float2 o0 = *(const float2*)(op0 + nt*8);
                    float2 o8 = *(const float2*)(op8 + nt*8);
                    v0.x += o0.x; v0.y += o0.y;
                    v8.x += o8.x; v8.y += o8.y;
                }
                *(float2*)(op0 + nt*8) = v0;
                *(float2*)(op8 + nt*8) = v8;
            }
        }
    }
}

// ================= conv5x5 as implicit GEMM, all staging via cp.async =================
__global__ void __launch_bounds__(256, 1)
k_conv5x5_mma(const __nv_bfloat16* __restrict__ attsTh, const __nv_bfloat16* __restrict__ attsTl,
              const __nv_bfloat16* __restrict__ rw5h, const __nv_bfloat16* __restrict__ rw5l,
              const float* __restrict__ rb, float* __restrict__ out)
{
    extern __shared__ __align__(16) __nv_bfloat16 sm[];
    uint32_t aBaseH = (uint32_t)__cvta_generic_to_shared(sm);
    uint32_t aBaseL = aBaseH + SMEM_OP*2;
    uint32_t bBaseH = aBaseH + 2*SMEM_OP*2;
    uint32_t bBaseL = aBaseH + 3*SMEM_OP*2;

    int tid = threadIdx.x;
    int tx = blockIdx.x;                  // 256 tiles: 32 y-tiles x 8 j-tiles
    int z = blockIdx.y;                   // b*2 + pc
    int b = z >> 1, pc = z & 1;
    int jBase = (tx & 7)*16;
    int yBase = (tx >> 3)*8;
    int NT = pc ? 12 : 13;
    int lane = tid & 31, warp = tid >> 5;
    int wco = (warp & 3)*32;
    int wpos = (warp >> 2)*64;

    float acc[2][8][4];
#pragma unroll
    for (int mt = 0; mt < 2; mt++)
#pragma unroll
        for (int nt = 0; nt < 8; nt++)
#pragma unroll
            for (int r = 0; r < 4; r++) acc[mt][nt][r] = 0.f;

#pragma unroll 1
    for (int t = 0; t < NT; t++){
        int ky = pc ? TAPS_O[t][0] : TAPS_E[t][0];
        int kx = pc ? TAPS_O[t][1] : TAPS_E[t][1];
        int tap = ky*5 + kx;
        __syncthreads();
        // A-stage: contiguous 16KB copy from tap-major prepped weights
        {
            const __nv_bfloat16* ah = rw5h + tap*8192;
            const __nv_bfloat16* al = rw5l + tap*8192;
            for (int i = tid; i < 1024; i += 256){
                int co = i >> 3, ch = i & 7;
                uint32_t d = co*PADB + ch*16;
                cpasync16(aBaseH + d, ah + co*64 + ch*8, 16);
                cpasync16(aBaseL + d, al + co*64 + ch*8, 16);
            }
        }
        // B-stage: shifted contiguous rows of attsT, zero-fill at borders
        for (int i = tid; i < 1024; i += 256){
            int p = i >> 3, ch = i & 7;
            int yl = p >> 4, jx = p & 15;
            int y = yBase + yl;
            int s = (y & 1) ^ pc;
            int yy = y + ky - 2;
            int jj = jBase + jx + ((s + kx - 2) >> 1);   // arithmetic shift = floor div 2
            bool inb = ((unsigned)yy < Hh) && ((unsigned)jj < W2);
            size_t go = 0;
            if (inb) go = ((size_t)b*NS + yy*W2 + jj)*64 + ch*8;
            int nb = inb ? 16 : 0;
            uint32_t d = p*PADB + ch*16;
            cpasync16(bBaseH + d, attsTh + go, nb);
            cpasync16(bBaseL + d, attsTl + go, nb);
        }
        CPASYNC_WAIT_ALL();
        __syncthreads();

#pragma unroll
        for (int ks = 0; ks < 4; ks++){
            int k0 = ks*16;
            int g = lane >> 3;
            int rofs = (lane & 7) + ((g & 1) ? 8 : 0);
            int cofs = k0 + ((g >> 1) ? 8 : 0);
            uint32_t ah[2][4], al[2][4];
#pragma unroll
            for (int mt = 0; mt < 2; mt++){
                uint32_t off = ((wco + mt*16 + rofs)*PAD + cofs)*2;
                ldsm4(ah[mt][0], ah[mt][1], ah[mt][2], ah[mt][3], aBaseH + off);
                ldsm4(al[mt][0], al[mt][1], al[mt][2], al[mt][3], aBaseL + off);
            }
            uint32_t bh[4][4], bl[4][4];
#pragma unroll
            for (int ntp = 0; ntp < 4; ntp++){
                uint32_t off = ((wpos + ntp*16 + rofs)*PAD + cofs)*2;
                ldsm4(bh[ntp][0], bh[ntp][1], bh[ntp][2], bh[ntp][3], bBaseH + off);
                ldsm4(bl[ntp][0], bl[ntp][1], bl[ntp][2], bl[ntp][3], bBaseL + off);
            }
#pragma unroll
            for (int mt = 0; mt < 2; mt++){
#pragma unroll
                for (int ntp = 0; ntp < 4; ntp++){
#pragma unroll
                    for (int sub = 0; sub < 2; sub++){
                        int nt = ntp*2 + sub;
                        uint32_t h0 = bh[ntp][sub], h1 = bh[ntp][sub+2];
                        uint32_t l0 = bl[ntp][sub], l1 = bl[ntp][sub+2];
                        mma16816(acc[mt][nt], ah[mt], h0, h1);
                        mma16816(acc[mt][nt], ah[mt], l0, l1);
                        mma16816(acc[mt][nt], al[mt], h0, h1);
                    }
                }
            }
        }
    }

    // epilogue
    {
        int r = lane >> 2, cc = (lane & 3)*2;
#pragma unroll
        for (int mt = 0; mt < 2; mt++){
            int co0 = wco + mt*16 + r;
            float bv0 = rb[co0], bv8 = rb[co0 + 8];
#pragma unroll
            for (int nt = 0; nt < 8; nt++){
                int p = wpos + nt*8 + cc;
                int yl = p >> 4, jx = p & 15;
                int y = yBase + yl;
                int s = (y & 1) ^ pc;
                int x0 = 2*(jBase + jx) + s;
                size_t r0 = ((size_t)(b*C2 + co0    ))*NPIX + y*Ww + x0;
                size_t r8 = ((size_t)(b*C2 + co0 + 8))*NPIX + y*Ww + x0;
                out[r0]     = acc[mt][nt][0] + bv0;
                out[r0 + 2] = acc[mt][nt][1] + bv0;
                out[r8]     = acc[mt][nt][2] + bv8;
                out[r8 + 2] = acc[mt][nt][3] + bv8;
            }
        }
    }
}

// ---------------- K1a: 1x1 conv (64->64) only at kept parity, stored squeezed ----------------
__global__ void k_conv1x1_qk(const float* __restrict__ x, const float* __restrict__ w,
                             const float* __restrict__ bias, float* __restrict__ outSq, int anchorSel)
{
    __shared__ float wsm[64*64];
    int tid = threadIdx.x;
    for (int i = tid; i < 4096; i += 256){
        int co = i & 63, ci = i >> 6;
        wsm[ci*64 + co] = w[co*64 + ci];
    }
    __syncthreads();
    int b  = blockIdx.y;
    int ps = blockIdx.x*256 + tid;
    int j = ps & (W2-1);
    int r = ps >> 7;
    int col = 2*j + (anchorSel ? (1 - (r & 1)) : (r & 1));
    const float* xp = x + (size_t)b*Cc*NPIX + r*Ww + col;

    float acc[64];
#pragma unroll
    for (int i = 0; i < 64; i++) acc[i] = 0.f;
    for (int ci = 0; ci < 64; ci++){
        float xv = xp[(size_t)ci*NPIX];
        const float4* w4 = (const float4*)(wsm + ci*64);
#pragma unroll
        for (int c4 = 0; c4 < 16; c4++){
            float4 wv = w4[c4];
            acc[c4*4+0] += wv.x*xv; acc[c4*4+1] += wv.y*xv;
            acc[c4*4+2] += wv.z*xv; acc[c4*4+3] += wv.w*xv;
        }
    }
    float* op = outSq + (size_t)b*Cc*NS + ps;
#pragma unroll
    for (int co = 0; co < 64; co++)
        op[(size_t)co*NS] = acc[co] + bias[co];
}

// ---------------- K1b: 1x1 conv (64->64) full image (v) ----------------
__global__ void k_conv1x1_v(const float* __restrict__ x, const float* __restrict__ w,
                            const float* __restrict__ bias, float* __restrict__ out)
{
    __shared__ float wsm[64*64];
    int tid = threadIdx.x;
    for (int i = tid; i < 4096; i += 256){
        int co = i & 63, ci = i >> 6;
        wsm[ci*64 + co] = w[co*64 + ci];
    }
    __syncthreads();
    int b   = blockIdx.y;
    int pos = blockIdx.x*256 + tid;
    const float* xp = x + (size_t)b*Cc*NPIX + pos;
    float acc[64];
#pragma unroll
    for (int i = 0; i < 64; i++) acc[i] = 0.f;
    for (int ci = 0; ci < 64; ci++){
        float xv = xp[(size_t)ci*NPIX];
        const float4* w4 = (const float4*)(wsm + ci*64);
#pragma unroll
        for (int c4 = 0; c4 < 16; c4++){
            float4 wv = w4[c4];
            acc[c4*4+0] += wv.x*xv; acc[c4*4+1] += wv.y*xv;
            acc[c4*4+2] += wv.z*xv; acc[c4*4+3] += wv.w*xv;
        }
    }
    float* op = out + (size_t)b*Cc*NPIX + pos;
#pragma unroll
    for (int co = 0; co < 64; co++)
        op[(size_t)co*NPIX] = acc[co] + bias[co];
}

// ---------------- K2a: depthwise 3x3 for q/k on squeezed pre-buffer ----------------
__global__ void k_dw3x3_qk(const float* __restrict__ in, const float* __restrict__ w,
                           const float* __restrict__ bias, const float* __restrict__ pbias,
                           float* __restrict__ out, int anchorSel)
{
    int idx = blockIdx.x*256 + threadIdx.x;
    int j = idx & (W2-1);
    int r = (idx >> 7) & (Hh-1);
    int c = (idx >> 15) & (Cc-1);
    int o = anchorSel ? (1 - (r & 1)) : (r & 1);
    int col = 2*j + o;
    const float* ip = in + (size_t)(idx >> 15) * NS;
    const float* wp = w + c*9;

    float s = bias[c] + wp[4]*ip[r*W2 + j];
    float cb = pbias[c];
    float bw = 0.f;
    if (r > 0)       bw += wp[1];
    if (r < Hh-1)    bw += wp[7];
    if (col > 0)     bw += wp[3];
    if (col < Ww-1)  bw += wp[5];
    s += cb * bw;
    int jm = j - 1 + o, jp = j + o;
    if (r > 0){
        const float* rp = ip + (r-1)*W2;
        if ((unsigned)jm < W2) s += wp[0]*rp[jm];
        if ((unsigned)jp < W2) s += wp[2]*rp[jp];
    }
    if (r < Hh-1){
        const float* rp = ip + (r+1)*W2;
        if ((unsigned)jm < W2) s += wp[6]*rp[jm];
        if ((unsigned)jp < W2) s += wp[8]*rp[jp];
    }
    out[idx] = s;
}

// ---------------- K2b: depthwise 3x3 for v (full input, anchor output, squeezed) ----------------
__global__ void k_dw3x3_v(const float* __restrict__ in, const float* __restrict__ w,
                          const float* __restrict__ bias, float* __restrict__ out)
{
    int idx = blockIdx.x*256 + threadIdx.x;
    int j = idx & (W2-1);
    int r = (idx >> 7) & (Hh-1);
    int c = (idx >> 15) & (Cc-1);
    int col = 2*j + (1 - (r & 1));
    const float* ip = in + (size_t)(idx >> 15) * NPIX;
    const float* wp = w + c*9;
    float s = bias[c];
#pragma unroll
    for (int dy = -1; dy <= 1; dy++){
        int rr = r + dy;
        if ((unsigned)rr < Hh){
#pragma unroll
            for (int dx = -1; dx <= 1; dx++){
                int cc = col + dx;
                if ((unsigned)cc < Ww)
                    s += wp[(dy+1)*3 + (dx+1)] * ip[rr*Ww + cc];
            }
        }
    }
    out[idx] = s;
}

// ---------------- K4: k softmax (max + exp; normalization deferred) ----------------
__global__ void k_softmax_n_exp(float* __restrict__ kk, float* __restrict__ kinv)
{
    int row = blockIdx.x;
    float* p = kk + (size_t)row*NS;
    int tid = threadIdx.x;
    __shared__ float red[256];
    float mx = -1e30f;
    for (int i = tid; i < NS; i += 256) mx = fmaxf(mx, p[i]);
    red[tid] = mx; __syncthreads();
    for (int s = 128; s > 0; s >>= 1){ if (tid < s) red[tid] = fmaxf(red[tid], red[tid+s]); __syncthreads(); }
    mx = red[0]; __syncthreads();
    float sum = 0.f;
    for (int i = tid; i < NS; i += 256){
        float e = __expf(p[i]-mx);
        p[i] = e;
        sum += e;
    }
    red[tid] = sum; __syncthreads();
    for (int s = 128; s > 0; s >>= 1){ if (tid < s) red[tid] += red[tid+s]; __syncthreads(); }
    if (tid == 0) kinv[row] = 1.f/red[0];
}

// ---------------- K5: ctx partials ----------------
__global__ void k_ctx_part(const float* __restrict__ ks, const float* __restrict__ vs,
                           float* __restrict__ part)
{
    int bh = blockIdx.y;
    int chunk = blockIdx.x;
    int e    = threadIdx.x >> 5;
    int lane = threadIdx.x & 31;
    int b = bh >> 2, hd = bh & 3;
    const float* kp = ks + ((size_t)(b*Cc + hd*Dd))*NS;
    const float* vp = vs + ((size_t)(b*Cc + hd*Dd + e))*NS;
    float acc[16];
#pragma unroll
    for (int d = 0; d < 16; d++) acc[d] = 0.f;
    int n0 = chunk*1024;
    for (int n = n0 + lane; n < n0 + 1024; n += 32){
        float vv = vp[n];
#pragma unroll
        for (int d = 0; d < 16; d++) acc[d] += kp[(size_t)d*NS + n]*vv;
    }
#pragma unroll
    for (int d = 0; d < 16; d++){
#pragma unroll
        for (int off = 16; off; off >>= 1) acc[d] += __shfl_xor_sync(0xffffffffu, acc[d], off);
    }
    if (lane == 0){
#pragma unroll
        for (int d = 0; d < 16; d++)
            part[(((size_t)bh*32 + chunk)*16 + e)*16 + d] = acc[d];
    }
}

__global__ void k_ctx_reduce(const float* __restrict__ part, const float* __restrict__ kinv,
                             float* __restrict__ ctx)
{
    int bh = blockIdx.x, t = threadIdx.x;
    int e = t >> 4, d = t & 15;
    float s = 0.f;
    for (int ch = 0; ch < 32; ch++) s += part[(((size_t)bh*32 + ch)*16 + e)*16 + d];
    int b = bh >> 2, hd = bh & 3;
    s *= kinv[b*Cc + hd*Dd + d];
    ctx[bh*256 + d*16 + e] = s;
}

// ---------------- K6: att (q softmax fused), writes transposed bf16 hi/lo ----------------
__global__ void k_att(const float* __restrict__ q, const float* __restrict__ ctx,
                      __nv_bfloat16* __restrict__ attsTh, __nv_bfloat16* __restrict__ attsTl)
{
    int bh = blockIdx.y;
    __shared__ float csm[256];
    for (int i = threadIdx.x; i < 256; i += 128) csm[i] = ctx[bh*256 + i];
    __syncthreads();
    int n = blockIdx.x*128 + threadIdx.x;
    int b = bh >> 2, hd = bh & 3;
    const float* qp = q + ((size_t)(b*Cc + hd*Dd))*NS + n;
    float qv[16];
    float mx = -1e30f;
#pragma unroll
    for (int d = 0; d < 16; d++){ qv[d] = qp[(size_t)d*NS]; mx = fmaxf(mx, qv[d]); }
    float ssum = 0.f;
#pragma unroll
    for (int d = 0; d < 16; d++){ qv[d] = __expf(qv[d]-mx); ssum += qv[d]; }
    float inv = 1.f/ssum;
    float o[16];
#pragma unroll
    for (int e = 0; e < 16; e++) o[e] = 0.f;
#pragma unroll
    for (int d = 0; d < 16; d++){
        float qd = qv[d]*inv;
#pragma unroll
        for (int e = 0; e < 16; e++) o[e] += csm[d*16 + e]*qd;
    }
    size_t base = ((size_t)b*NS + n)*64 + hd*16;
#pragma unroll
    for (int e = 0; e < 16; e++){
        __nv_bfloat16 h = __float2bfloat16(o[e]);
        attsTh[base + e] = h;
        attsTl[base + e] = __float2bfloat16(o[e] - __bfloat162float(h));
    }
}

// ---------------- K9: m2 depthwise 3x3 (C4 channels, pad 1) + gelu ----------------
__global__ void k_dw3x3_gelu(const float* __restrict__ in, const float* __restrict__ w,
                             const float* __restrict__ bias, float* __restrict__ out)
{
    int idx = blockIdx.x*256 + threadIdx.x;
    int x = idx & 255;
    int y = (idx >> 8) & 255;
    int c = (idx >> 16) & 255;
    const float* ip = in + (size_t)(idx >> 16) * NPIX;
    const float* wp = w + c*9;
    float s = bias[c];
#pragma unroll
    for (int dy = -1; dy <= 1; dy++){
        int rr = y + dy;
        if ((unsigned)rr < Hh){
#pragma unroll
            for (int dx = -1; dx <= 1; dx++){
                int cc = x + dx;
                if ((unsigned)cc < Ww)
                    s += wp[(dy+1)*3 + (dx+1)] * ip[rr*Ww + cc];
            }
        }
    }
    out[idx] = gelu_f(s);
}

// ---------------- launch ----------------
extern "C" void kernel_launch(void* const* d_in, const int* in_sizes, int n_in,
                              void* d_out, int out_size)
{
    (void)in_sizes; (void)n_in; (void)out_size;
    const float* x1   = (const float*)d_in[0];
    const float* x2   = (const float*)d_in[1];
    const float* q1_w = (const float*)d_in[2];
    const float* q1_b = (const float*)d_in[3];
    const float* q2_w = (const float*)d_in[4];
    const float* q2_b = (const float*)d_in[5];
    const float* k1_w = (const float*)d_in[6];
    const float* k1_b = (const float*)d_in[7];
    const float* k2_w = (const float*)d_in[8];
    const float* k2_b = (const float*)d_in[9];
    const float* v1_w = (const float*)d_in[10];
    const float* v1_b = (const float*)d_in[11];
    const float* v2_w = (const float*)d_in[12];
    const float* v2_b = (const float*)d_in[13];
    const float* r_w  = (const float*)d_in[14];
    const float* r_b  = (const float*)d_in[15];
    const float* m1_w = (const float*)d_in[16];
    const float* m1_b = (const float*)d_in[17];
    const float* m2_w = (const float*)d_in[18];
    const float* m2_b = (const float*)d_in[19];
    const float* m3_w = (const float*)d_in[20];
    const float* m3_b = (const float*)d_in[21];
    float* out = (float*)d_out;

    float *qs0, *ks0, *vpre, *qs, *ks, *vs, *kinv, *part, *ctx, *ma, *mb;
    __nv_bfloat16 *attsTh, *attsTl, *rw5h, *rw5l, *m1wh, *m1wl, *m3wh, *m3wl;
    cudaGetSymbolAddress((void**)&qs0,  g_qs0);
    cudaGetSymbolAddress((void**)&ks0,  g_ks0);
    cudaGetSymbolAddress((void**)&vpre, g_vpre);
    cudaGetSymbolAddress((void**)&qs,   g_qs);
    cudaGetSymbolAddress((void**)&ks,   g_ks);
    cudaGetSymbolAddress((void**)&vs,   g_vs);
    cudaGetSymbolAddress((void**)&kinv, g_kinv);
    cudaGetSymbolAddress((void**)&part, g_ctx_part);
    cudaGetSymbolAddress((void**)&ctx,  g_ctx);
    cudaGetSymbolAddress((void**)&ma,   g_ma);
    cudaGetSymbolAddress((void**)&mb,   g_mb);
    cudaGetSymbolAddress((void**)&attsTh, g_attsTh);
    cudaGetSymbolAddress((void**)&attsTl, g_attsTl);
    cudaGetSymbolAddress((void**)&rw5h, g_rw5h);
    cudaGetSymbolAddress((void**)&rw5l, g_rw5l);
    cudaGetSymbolAddress((void**)&m1wh, g_m1wh);
    cudaGetSymbolAddress((void**)&m1wl, g_m1wl);
    cudaGetSymbolAddress((void**)&m3wh, g_m3wh);
    cudaGetSymbolAddress((void**)&m3wl, g_m3wl);

    cudaFuncSetAttribute(k_gemm_mma<C2, C4, true, false>,
                         cudaFuncAttributeMaxDynamicSharedMemorySize, SM_GEMM_BYTES);
    cudaFuncSetAttribute(k_gemm_mma<C4, C2, false, true>,
                         cudaFuncAttributeMaxDynamicSharedMemorySize, SM_GEMM_BYTES);
    cudaFuncSetAttribute(k_conv5x5_mma,
                         cudaFuncAttributeMaxDynamicSharedMemorySize, SM_GEMM_BYTES);

    // weight prep (tiny)
    k_prep_rw5<<<800, 256>>>(r_w, rw5h, rw5l);
    k_prep_w<<<(C4*C2 + 255)/256, 256>>>(m1_w, m1wh, m1wl, C4*C2);
    k_prep_w<<<(C2*C4 + 255)/256, 256>>>(m3_w, m3wh, m3wl, C2*C4);

    k_conv1x1_qk<<<dim3(NS/256, Bq), 256>>>(x1, q1_w, q1_b, qs0, 0);
    k_conv1x1_qk<<<dim3(NS/256, Bq), 256>>>(x1, k1_w, k1_b, ks0, 1);
    k_conv1x1_v <<<dim3(NPIX/256, Bq), 256>>>(x2, v1_w, v1_b, vpre);

    k_dw3x3_qk<<<(Bq*Cc*NS)/256, 256>>>(qs0, q2_w, q2_b, q1_b, qs, 0);
    k_dw3x3_qk<<<(Bq*Cc*NS)/256, 256>>>(ks0, k2_w, k2_b, k1_b, ks, 1);
    k_dw3x3_v <<<(Bq*Cc*NS)/256, 256>>>(vpre, v2_w, v2_b, vs);

    k_softmax_n_exp<<<Bq*Cc, 256>>>(ks, kinv);

    k_ctx_part<<<dim3(32, Bq*NHEAD), 512>>>(ks, vs, part);
    k_ctx_reduce<<<Bq*NHEAD, 256>>>(part, kinv, ctx);

    k_att<<<dim3(NS/128, Bq*NHEAD), 128>>>(qs, ctx, attsTh, attsTl);

    // conv5x5 via implicit GEMM (HMMA split-bf16, cp.async staging), two parity classes
    k_conv5x5_mma<<<dim3(256, Bq*2), 256, SM_GEMM_BYTES>>>(attsTh, attsTl, rw5h, rw5l, r_b, out);

    // m1: 128 -> 256 + gelu (HMMA split-bf16)
    k_gemm_mma<C2, C4, true, false><<<dim3(Bq*(NPIX/128), C4/128), 256, SM_GEMM_BYTES>>>(out, m1wh, m1wl, m1_b, ma);
    k_dw3x3_gelu<<<(Bq*C4*NPIX)/256, 256>>>(ma, m2_w, m2_b, mb);
    // m3: 256 -> 128 + residual into out (HMMA split-bf16)
    k_gemm_mma<C4, C2, false, true><<<dim3(Bq*(NPIX/128), C2/128), 256, SM_GEMM_BYTES>>>(mb, m3wh, m3wl, m3_b, out);
}

// round 12
// speedup vs baseline: 3.0402x; 1.5266x over previous
#include <cuda_runtime.h>
#include <cuda_bf16.h>
#include <math.h>
#include <stdint.h>

#define Bq    4
#define Cc    64
#define Hh    256
#define Ww    256
#define W2    128
#define NPIX  65536   // Hh*Ww
#define NS    32768   // Hh*W2
#define NHEAD 4
#define Dd    16
#define C2    128
#define C4    256

// ---------------- scratch (device globals; no runtime allocation) ----------------
__device__ float g_qs0 [(size_t)Bq*Cc*NS];
__device__ float g_ks0 [(size_t)Bq*Cc*NS];
__device__ float g_vpre[(size_t)Bq*Cc*NPIX];
__device__ float g_qs  [(size_t)Bq*Cc*NS];
__device__ float g_ks  [(size_t)Bq*Cc*NS];
__device__ float g_vs  [(size_t)Bq*Cc*NS];
__device__ float g_kinv[Bq*Cc];
__device__ float g_ctx_part[16*32*16*16];
__device__ float g_ctx[16*256];
__device__ float g_ma[(size_t)Bq*C4*NPIX];
__device__ float g_mb[(size_t)Bq*C4*NPIX];
// bf16 hi/lo staging sources
__device__ __nv_bfloat16 g_attsTh[(size_t)Bq*NS*64];   // [b][n][ci]
__device__ __nv_bfloat16 g_attsTl[(size_t)Bq*NS*64];
__device__ __nv_bfloat16 g_rw5h[25*128*64];            // [tap][co][ci]
__device__ __nv_bfloat16 g_rw5l[25*128*64];
__device__ __nv_bfloat16 g_m1wh[C4*C2];
__device__ __nv_bfloat16 g_m1wl[C4*C2];
__device__ __nv_bfloat16 g_m3wh[C2*C4];
__device__ __nv_bfloat16 g_m3wl[C2*C4];
__device__ __nv_bfloat16 g_q1wh[Cc*Cc];
__device__ __nv_bfloat16 g_q1wl[Cc*Cc];
__device__ __nv_bfloat16 g_k1wh[Cc*Cc];
__device__ __nv_bfloat16 g_k1wl[Cc*Cc];
__device__ __nv_bfloat16 g_v1wh[Cc*Cc];
__device__ __nv_bfloat16 g_v1wl[Cc*Cc];

// tap tables: class 0 = (ky+kx) even (13 taps), class 1 = odd (12 taps)
__device__ __constant__ int8_t TAPS_E[13][2] = {
    {0,0},{0,2},{0,4},{1,1},{1,3},{2,0},{2,2},{2,4},{3,1},{3,3},{4,0},{4,2},{4,4}};
__device__ __constant__ int8_t TAPS_O[12][2] = {
    {0,1},{0,3},{1,0},{1,2},{1,4},{2,1},{2,3},{3,0},{3,2},{3,4},{4,1},{4,3}};

__device__ __forceinline__ float gelu_f(float x){
    return 0.5f * x * (1.0f + erff(x * 0.70710678118654752f));
}

// ================= mma.sync + cp.async helpers (baseline ISA) =================
__device__ __forceinline__ void ldsm4(uint32_t &r0, uint32_t &r1, uint32_t &r2, uint32_t &r3, uint32_t addr){
    asm volatile("ldmatrix.sync.aligned.m8n8.x4.shared.b16 {%0,%1,%2,%3}, [%4];"
                 : "=r"(r0), "=r"(r1), "=r"(r2), "=r"(r3) : "r"(addr));
}
__device__ __forceinline__ void mma16816(float* c, const uint32_t* a, uint32_t b0, uint32_t b1){
    asm volatile(
        "mma.sync.aligned.m16n8k16.row.col.f32.bf16.bf16.f32 "
        "{%0,%1,%2,%3}, {%4,%5,%6,%7}, {%8,%9}, {%0,%1,%2,%3};"
        : "+f"(c[0]), "+f"(c[1]), "+f"(c[2]), "+f"(c[3])
        : "r"(a[0]), "r"(a[1]), "r"(a[2]), "r"(a[3]), "r"(b0), "r"(b1));
}
__device__ __forceinline__ void cpasync16(uint32_t smem_addr, const void* gptr, int src_bytes){
    asm volatile("cp.async.cg.shared.global [%0], [%1], 16, %2;"
                 :: "r"(smem_addr), "l"(gptr), "r"(src_bytes) : "memory");
}
#define CPASYNC_WAIT_ALL() asm volatile("cp.async.commit_group;\ncp.async.wait_group 0;" ::: "memory")

#define KC    64
#define PAD   72                              // bf16 per smem row (144B stride, 16B aligned)
#define PADB  144
#define SMEM_OP (128*PAD)
#define SM_GEMM_BYTES (4*SMEM_OP*2)           // Ah, Al, Bh, Bl

// qkv GEMM smem layout: A 64 rows, B 256 rows (h/l each)
#define QKV_A_BYTES (64*PADB)                 // 9216
#define QKV_B_BYTES (256*PADB)                // 36864
#define SM_QKV_BYTES (2*QKV_A_BYTES + 2*QKV_B_BYTES)  // 92160

// ================= prep kernels: one-time float -> bf16 hi/lo =================
__global__ void k_prep_w(const float* __restrict__ w, __nv_bfloat16* __restrict__ h,
                         __nv_bfloat16* __restrict__ l, int n)
{
    int i = blockIdx.x*256 + threadIdx.x;
    if (i < n){
        float v = w[i];
        __nv_bfloat16 hh = __float2bfloat16(v);
        h[i] = hh;
        l[i] = __float2bfloat16(v - __bfloat162float(hh));
    }
}
__global__ void k_prep_rw5(const float* __restrict__ rw, __nv_bfloat16* __restrict__ h,
                           __nv_bfloat16* __restrict__ l)
{
    int i = blockIdx.x*256 + threadIdx.x;      // 25*128*64 = 204800
    int tap = i >> 13;
    int rem = i & 8191;
    float v = rw[(size_t)rem*25 + tap];
    __nv_bfloat16 hh = __float2bfloat16(v);
    h[i] = hh;
    l[i] = __float2bfloat16(v - __bfloat162float(hh));
}

// ================= qkv 1x1 conv as HMMA GEMM: tile 64co x 256pos, K=64 =================
// MODE 0: q gather (col=2j+(r&1), out stride NS); 1: k gather (col=2j+1-(r&1), NS); 2: v direct (NPIX)
template<int MODE>
__global__ void __launch_bounds__(256)
k_conv1x1_mma(const float* __restrict__ x,
              const __nv_bfloat16* __restrict__ wh, const __nv_bfloat16* __restrict__ wl,
              const float* __restrict__ bias, float* __restrict__ outp)
{
    const int OSTR = (MODE == 2) ? NPIX : NS;
    extern __shared__ __align__(16) __nv_bfloat16 sm[];
    uint32_t aBaseH = (uint32_t)__cvta_generic_to_shared(sm);
    uint32_t aBaseL = aBaseH + QKV_A_BYTES;
    uint32_t bBaseH = aBaseH + 2*QKV_A_BYTES;
    uint32_t bBaseL = bBaseH + QKV_B_BYTES;
    __nv_bfloat16* Bh = sm + 2*QKV_A_BYTES/2;
    __nv_bfloat16* Bl = sm + (2*QKV_A_BYTES + QKV_B_BYTES)/2;

    int tid = threadIdx.x;
    int b = blockIdx.y;
    int posBase = blockIdx.x*256;
    int lane = tid & 31, warp = tid >> 5;
    int wco = (warp & 1)*32;
    int wpos = (warp >> 1)*64;

    // A-stage: prepped weights [co][ci], 64 rows x 8 chunks of 16B (128B per row)
    for (int i = tid; i < 512; i += 256){
        int co = i >> 3, ch = i & 7;
        uint32_t d = co*PADB + ch*16;
        cpasync16(aBaseH + d, wh + co*64 + ch*8, 16);
        cpasync16(aBaseL + d, wl + co*64 + ch*8, 16);
    }
    // B-stage: gather x -> [p][ci] h/l
    for (int i = tid; i < 16384; i += 256){
        int ci = i >> 8, p = i & 255;
        int ps = posBase + p;
        size_t gidx;
        if (MODE == 2){
            gidx = ((size_t)(b*Cc + ci))*NPIX + ps;
        } else {
            int j = ps & (W2-1);
            int r = ps >> 7;
            int o = (MODE == 1) ? (1 - (r & 1)) : (r & 1);
            gidx = ((size_t)(b*Cc + ci))*NPIX + r*Ww + 2*j + o;
        }
        float v = x[gidx];
        __nv_bfloat16 h = __float2bfloat16(v);
        __nv_bfloat16 l = __float2bfloat16(v - __bfloat162float(h));
        Bh[p*PAD + ci] = h;
        Bl[p*PAD + ci] = l;
    }
    CPASYNC_WAIT_ALL();
    __syncthreads();

    float acc[2][8][4];
#pragma unroll
    for (int mt = 0; mt < 2; mt++)
#pragma unroll
        for (int nt = 0; nt < 8; nt++)
#pragma unroll
            for (int r = 0; r < 4; r++) acc[mt][nt][r] = 0.f;

#pragma unroll
    for (int ks = 0; ks < 4; ks++){
        int k0 = ks*16;
        int g = lane >> 3;
        int rofs = (lane & 7) + ((g & 1) ? 8 : 0);
        int cofs = k0 + ((g >> 1) ? 8 : 0);
        uint32_t ah[2][4], al[2][4];
#pragma unroll
        for (int mt = 0; mt < 2; mt++){
            uint32_t off = ((wco + mt*16 + rofs)*PAD + cofs)*2;
            ldsm4(ah[mt][0], ah[mt][1], ah[mt][2], ah[mt][3], aBaseH + off);
            ldsm4(al[mt][0], al[mt][1], al[mt][2], al[mt][3], aBaseL + off);
        }
        uint32_t bh[4][4], bl[4][4];
#pragma unroll
        for (int ntp = 0; ntp < 4; ntp++){
            uint32_t off = ((wpos + ntp*16 + rofs)*PAD + cofs)*2;
            ldsm4(bh[ntp][0], bh[ntp][1], bh[ntp][2], bh[ntp][3], bBaseH + off);
            ldsm4(bl[ntp][0], bl[ntp][1], bl[ntp][2], bl[ntp][3], bBaseL + off);
        }
#pragma unroll
        for (int mt = 0; mt < 2; mt++){
#pragma unroll
            for (int ntp = 0; ntp < 4; ntp++){
#pragma unroll
                for (int sub = 0; sub < 2; sub++){
                    int nt = ntp*2 + sub;
                    uint32_t h0 = bh[ntp][sub], h1 = bh[ntp][sub+2];
                    uint32_t l0 = bl[ntp][sub], l1 = bl[ntp][sub+2];
                    mma16816(acc[mt][nt], ah[mt], h0, h1);
                    mma16816(acc[mt][nt], ah[mt], l0, l1);
                    mma16816(acc[mt][nt], al[mt], h0, h1);
                }
            }
        }
    }

    // epilogue
    {
        int r = lane >> 2, cc = (lane & 3)*2;
#pragma unroll
        for (int mt = 0; mt < 2; mt++){
            int co0 = wco + mt*16 + r;
            float bv0 = bias[co0], bv8 = bias[co0 + 8];
            float* op0 = outp + ((size_t)(b*Cc + co0    ))*OSTR + posBase + wpos + cc;
            float* op8 = outp + ((size_t)(b*Cc + co0 + 8))*OSTR + posBase + wpos + cc;
#pragma unroll
            for (int nt = 0; nt < 8; nt++){
                float2 v0, v8;
                v0.x = acc[mt][nt][0] + bv0;  v0.y = acc[mt][nt][1] + bv0;
                v8.x = acc[mt][nt][2] + bv8;  v8.y = acc[mt][nt][3] + bv8;
                *(float2*)(op0 + nt*8) = v0;
                *(float2*)(op8 + nt*8) = v8;
            }
        }
    }
}

// ================= generic 1x1 GEMM (m1/m3), bf16-prepped A, cp.async A-stage =================
template<int CIN, int COUT, bool GELU, bool RES>
__global__ void __launch_bounds__(256, 1)
k_gemm_mma(const float* __restrict__ in,
           const __nv_bfloat16* __restrict__ wh, const __nv_bfloat16* __restrict__ wl,
           const float* __restrict__ bias, float* __restrict__ out)
{
    extern __shared__ __align__(16) __nv_bfloat16 sm[];
    __nv_bfloat16* Bh = sm + 2*SMEM_OP;
    __nv_bfloat16* Bl = sm + 3*SMEM_OP;
    uint32_t aBaseH = (uint32_t)__cvta_generic_to_shared(sm);
    uint32_t aBaseL = aBaseH + SMEM_OP*2;
    uint32_t bBaseH = aBaseH + 2*SMEM_OP*2;
    uint32_t bBaseL = aBaseH + 3*SMEM_OP*2;

    int tid = threadIdx.x;
    int b = blockIdx.x >> 9;
    int posBase = (blockIdx.x & 511)*128;
    int coBase = blockIdx.y*128;
    int lane = tid & 31, warp = tid >> 5;
    int wco = (warp & 3)*32;
    int wpos = (warp >> 2)*64;

    float acc[2][8][4];
#pragma unroll
    for (int mt = 0; mt < 2; mt++)
#pragma unroll
        for (int nt = 0; nt < 8; nt++)
#pragma unroll
            for (int r = 0; r < 4; r++) acc[mt][nt][r] = 0.f;

    const int KO = CIN/KC;
#pragma unroll 1
    for (int ko = 0; ko < KO; ko++){
        __syncthreads();
        for (int i = tid; i < 1024; i += 256){
            int co = i >> 3, ch = i & 7;
            uint32_t d = co*PADB + ch*16;
            cpasync16(aBaseH + d, wh + (size_t)(coBase + co)*CIN + ko*KC + ch*8, 16);
            cpasync16(aBaseL + d, wl + (size_t)(coBase + co)*CIN + ko*KC + ch*8, 16);
        }
        for (int i = tid; i < 128*KC; i += 256){
            int p = i & 127, ci = i >> 7;
            float v = in[((size_t)(b*CIN + ko*KC + ci))*NPIX + posBase + p];
            __nv_bfloat16 h = __float2bfloat16(v);
            __nv_bfloat16 l = __float2bfloat16(v - __bfloat162float(h));
            Bh[p*PAD + ci] = h;
            Bl[p*PAD + ci] = l;
        }
        CPASYNC_WAIT_ALL();
        __syncthreads();

#pragma unroll
        for (int ks = 0; ks < KC/16; ks++){
            int k0 = ks*16;
            int g = lane >> 3;
            int rofs = (lane & 7) + ((g & 1) ? 8 : 0);
            int cofs = k0 + ((g >> 1) ? 8 : 0);
            uint32_t ah[2][4], al[2][4];
#pragma unroll
            for (int mt = 0; mt < 2; mt++){
                uint32_t off = ((wco + mt*16 + rofs)*PAD + cofs)*2;
                ldsm4(ah[mt][0], ah[mt][1], ah[mt][2], ah[mt][3], aBaseH + off);
                ldsm4(al[mt][0], al[mt][1], al[mt][2], al[mt][3], aBaseL + off);
            }
            uint32_t bh[4][4], bl[4][4];
#pragma unroll
            for (int ntp = 0; ntp < 4; ntp++){
                uint32_t off = ((wpos + ntp*16 + rofs)*PAD + cofs)*2;
                ldsm4(bh[ntp][0], bh[ntp][1], bh[ntp][2], bh[ntp][3], bBaseH + off);
                ldsm4(bl[ntp][0], bl[ntp][1], bl[ntp][2], bl[ntp][3], bBaseL + off);
            }
#pragma unroll
            for (int mt = 0; mt < 2; mt++){
#pragma unroll
                for (int ntp = 0; ntp < 4; ntp++){
#pragma unroll
                    for (int sub = 0; sub < 2; sub++){
                        int nt = ntp*2 + sub;
                        uint32_t h0 = bh[ntp][sub], h1 = bh[ntp][sub+2];
                        uint32_t l0 = bl[ntp][sub], l1 = bl[ntp][sub+2];
                        mma16816(acc[mt][nt], ah[mt], h0, h1);
                        mma16816(acc[mt][nt], ah[mt], l0, l1);
                        mma16816(acc[mt][nt], al[mt], h0, h1);
                    }
                }
            }
        }
    }

    {
        int r = lane >> 2, cc = (lane & 3)*2;
#pragma unroll
        for (int mt = 0; mt < 2; mt++){
            int co0 = coBase + wco + mt*16 + r;
            float bv0 = bias[co0], bv8 = bias[co0 + 8];
            float* op0 = out + ((size_t)(b*COUT + co0    ))*NPIX + posBase + wpos + cc;
            float* op8 = out + ((size_t)(b*COUT + co0 + 8))*NPIX + posBase + wpos + cc;
#pragma unroll
            for (int nt = 0; nt < 8; nt++){
                float2 v0, v8;
                v0.x = acc[mt][nt][0] + bv0;  v0.y = acc[mt][nt][1] + bv0;
                v8.x = acc[mt][nt][2] + bv8;  v8.y = acc[mt][nt][3] + bv8;
                if (GELU){
                    v0.x = gelu_f(v0.x); v0.y = gelu_f(v0.y);
                    v8.x = gelu_f(v8.x); v8.y = gelu_f(v8.y);
                }
                if (RES){
                    float2 o0 = *(const float2*)(op0 + nt*8);
                    float2 o8 = *(const float2*)(op8 + nt*8);
                    v0.x += o0.x; v0.y += o0.y;
                    v8.x += o8.x; v8.y += o8.y;
                }
                *(float2*)(op0 + nt*8) = v0;
                *(float2*)(op8 + nt*8) = v8;
            }
        }
    }
}

// ================= conv5x5 as implicit GEMM, all staging via cp.async =================
__global__ void __launch_bounds__(256, 1)
k_conv5x5_mma(const __nv_bfloat16* __restrict__ attsTh, const __nv_bfloat16* __restrict__ attsTl,
              const __nv_bfloat16* __restrict__ rw5h, const __nv_bfloat16* __restrict__ rw5l,
              const float* __restrict__ rb, float* __restrict__ out)
{
    extern __shared__ __align__(16) __nv_bfloat16 sm[];
    uint32_t aBaseH = (uint32_t)__cvta_generic_to_shared(sm);
    uint32_t aBaseL = aBaseH + SMEM_OP*2;
    uint32_t bBaseH = aBaseH + 2*SMEM_OP*2;
    uint32_t bBaseL = aBaseH + 3*SMEM_OP*2;

    int tid = threadIdx.x;
    int tx = blockIdx.x;
    int z = blockIdx.y;
    int b = z >> 1, pc = z & 1;
    int jBase = (tx & 7)*16;
    int yBase = (tx >> 3)*8;
    int NT = pc ? 12 : 13;
    int lane = tid & 31, warp = tid >> 5;
    int wco = (warp & 3)*32;
    int wpos = (warp >> 2)*64;

    float acc[2][8][4];
#pragma unroll
    for (int mt = 0; mt < 2; mt++)
#pragma unroll
        for (int nt = 0; nt < 8; nt++)
#pragma unroll
            for (int r = 0; r < 4; r++) acc[mt][nt][r] = 0.f;

#pragma unroll 1
    for (int t = 0; t < NT; t++){
        int ky = pc ? TAPS_O[t][0] : TAPS_E[t][0];
        int kx = pc ? TAPS_O[t][1] : TAPS_E[t][1];
        int tap = ky*5 + kx;
        __syncthreads();
        {
            const __nv_bfloat16* ah = rw5h + tap*8192;
            const __nv_bfloat16* al = rw5l + tap*8192;
            for (int i = tid; i < 1024; i += 256){
                int co = i >> 3, ch = i & 7;
                uint32_t d = co*PADB + ch*16;
                cpasync16(aBaseH + d, ah + co*64 + ch*8, 16);
                cpasync16(aBaseL + d, al + co*64 + ch*8, 16);
            }
        }
        for (int i = tid; i < 1024; i += 256){
            int p = i >> 3, ch = i & 7;
            int yl = p >> 4, jx = p & 15;
            int y = yBase + yl;
            int s = (y & 1) ^ pc;
            int yy = y + ky - 2;
            int jj = jBase + jx + ((s + kx - 2) >> 1);
            bool inb = ((unsigned)yy < Hh) && ((unsigned)jj < W2);
            size_t go = 0;
            if (inb) go = ((size_t)b*NS + yy*W2 + jj)*64 + ch*8;
            int nb = inb ? 16 : 0;
            uint32_t d = p*PADB + ch*16;
            cpasync16(bBaseH + d, attsTh + go, nb);
            cpasync16(bBaseL + d, attsTl + go, nb);
        }
        CPASYNC_WAIT_ALL();
        __syncthreads();

#pragma unroll
        for (int ks = 0; ks < 4; ks++){
            int k0 = ks*16;
            int g = lane >> 3;
            int rofs = (lane & 7) + ((g & 1) ? 8 : 0);
            int cofs = k0 + ((g >> 1) ? 8 : 0);
            uint32_t ah[2][4], al[2][4];
#pragma unroll
            for (int mt = 0; mt < 2; mt++){
                uint32_t off = ((wco + mt*16 + rofs)*PAD + cofs)*2;
                ldsm4(ah[mt][0], ah[mt][1], ah[mt][2], ah[mt][3], aBaseH + off);
                ldsm4(al[mt][0], al[mt][1], al[mt][2], al[mt][3], aBaseL + off);
            }
            uint32_t bh[4][4], bl[4][4];
#pragma unroll
            for (int ntp = 0; ntp < 4; ntp++){
                uint32_t off = ((wpos + ntp*16 + rofs)*PAD + cofs)*2;
                ldsm4(bh[ntp][0], bh[ntp][1], bh[ntp][2], bh[ntp][3], bBaseH + off);
                ldsm4(bl[ntp][0], bl[ntp][1], bl[ntp][2], bl[ntp][3], bBaseL + off);
            }
#pragma unroll
            for (int mt = 0; mt < 2; mt++){
#pragma unroll
                for (int ntp = 0; ntp < 4; ntp++){
#pragma unroll
                    for (int sub = 0; sub < 2; sub++){
                        int nt = ntp*2 + sub;
                        uint32_t h0 = bh[ntp][sub], h1 = bh[ntp][sub+2];
                        uint32_t l0 = bl[ntp][sub], l1 = bl[ntp][sub+2];
                        mma16816(acc[mt][nt], ah[mt], h0, h1);
                        mma16816(acc[mt][nt], ah[mt], l0, l1);
                        mma16816(acc[mt][nt], al[mt], h0, h1);
                    }
                }
            }
        }
    }

    {
        int r = lane >> 2, cc = (lane & 3)*2;
#pragma unroll
        for (int mt = 0; mt < 2; mt++){
            int co0 = wco + mt*16 + r;
            float bv0 = rb[co0], bv8 = rb[co0 + 8];
#pragma unroll
            for (int nt = 0; nt < 8; nt++){
                int p = wpos + nt*8 + cc;
                int yl = p >> 4, jx = p & 15;
                int y = yBase + yl;
                int s = (y & 1) ^ pc;
                int x0 = 2*(jBase + jx) + s;
                size_t r0 = ((size_t)(b*C2 + co0    ))*NPIX + y*Ww + x0;
                size_t r8 = ((size_t)(b*C2 + co0 + 8))*NPIX + y*Ww + x0;
                out[r0]     = acc[mt][nt][0] + bv0;
                out[r0 + 2] = acc[mt][nt][1] + bv0;
                out[r8]     = acc[mt][nt][2] + bv8;
                out[r8 + 2] = acc[mt][nt][3] + bv8;
            }
        }
    }
}

// ---------------- K2a: depthwise 3x3 for q/k on squeezed pre-buffer ----------------
__global__ void k_dw3x3_qk(const float* __restrict__ in, const float* __restrict__ w,
                           const float* __restrict__ bias, const float* __restrict__ pbias,
                           float* __restrict__ out, int anchorSel)
{
    int idx = blockIdx.x*256 + threadIdx.x;
    int j = idx & (W2-1);
    int r = (idx >> 7) & (Hh-1);
    int c = (idx >> 15) & (Cc-1);
    int o = anchorSel ? (1 - (r & 1)) : (r & 1);
    int col = 2*j + o;
    const float* ip = in + (size_t)(idx >> 15) * NS;
    const float* wp = w + c*9;

    float s = bias[c] + wp[4]*ip[r*W2 + j];
    float cb = pbias[c];
    float bw = 0.f;
    if (r > 0)       bw += wp[1];
    if (r < Hh-1)    bw += wp[7];
    if (col > 0)     bw += wp[3];
    if (col < Ww-1)  bw += wp[5];
    s += cb * bw;
    int jm = j - 1 + o, jp = j + o;
    if (r > 0){
        const float* rp = ip + (r-1)*W2;
        if ((unsigned)jm < W2) s += wp[0]*rp[jm];
        if ((unsigned)jp < W2) s += wp[2]*rp[jp];
    }
    if (r < Hh-1){
        const float* rp = ip + (r+1)*W2;
        if ((unsigned)jm < W2) s += wp[6]*rp[jm];
        if ((unsigned)jp < W2) s += wp[8]*rp[jp];
    }
    out[idx] = s;
}

// ---------------- K2b: depthwise 3x3 for v (full input, anchor output, squeezed) ----------------
__global__ void k_dw3x3_v(const float* __restrict__ in, const float* __restrict__ w,
                          const float* __restrict__ bias, float* __restrict__ out)
{
    int idx = blockIdx.x*256 + threadIdx.x;
    int j = idx & (W2-1);
    int r = (idx >> 7) & (Hh-1);
    int c = (idx >> 15) & (Cc-1);
    int col = 2*j + (1 - (r & 1));
    const float* ip = in + (size_t)(idx >> 15) * NPIX;
    const float* wp = w + c*9;
    float s = bias[c];
#pragma unroll
    for (int dy = -1; dy <= 1; dy++){
        int rr = r + dy;
        if ((unsigned)rr < Hh){
#pragma unroll
            for (int dx = -1; dx <= 1; dx++){
                int cc = col + dx;
                if ((unsigned)cc < Ww)
                    s += wp[(dy+1)*3 + (dx+1)] * ip[rr*Ww + cc];
            }
        }
    }
    out[idx] = s;
}

// ---------------- K4: k softmax (max + exp; normalization deferred) ----------------
__global__ void k_softmax_n_exp(float* __restrict__ kk, float* __restrict__ kinv)
{
    int row = blockIdx.x;
    float* p = kk + (size_t)row*NS;
    int tid = threadIdx.x;
    __shared__ float red[256];
    float mx = -1e30f;
    for (int i = tid; i < NS; i += 256) mx = fmaxf(mx, p[i]);
    red[tid] = mx; __syncthreads();
    for (int s = 128; s > 0; s >>= 1){ if (tid < s) red[tid] = fmaxf(red[tid], red[tid+s]); __syncthreads(); }
    mx = red[0]; __syncthreads();
    float sum = 0.f;
    for (int i = tid; i < NS; i += 256){
        float e = __expf(p[i]-mx);
        p[i] = e;
        sum += e;
    }
    red[tid] = sum; __syncthreads();
    for (int s = 128; s > 0; s >>= 1){ if (tid < s) red[tid] += red[tid+s]; __syncthreads(); }
    if (tid == 0) kinv[row] = 1.f/red[0];
}

// ---------------- K5: ctx partials ----------------
__global__ void k_ctx_part(const float* __restrict__ ks, const float* __restrict__ vs,
                           float* __restrict__ part)
{
    int bh = blockIdx.y;
    int chunk = blockIdx.x;
    int e    = threadIdx.x >> 5;
    int lane = threadIdx.x & 31;
    int b = bh >> 2, hd = bh & 3;
    const float* kp = ks + ((size_t)(b*Cc + hd*Dd))*NS;
    const float* vp = vs + ((size_t)(b*Cc + hd*Dd + e))*NS;
    float acc[16];
#pragma unroll
    for (int d = 0; d < 16; d++) acc[d] = 0.f;
    int n0 = chunk*1024;
    for (int n = n0 + lane; n < n0 + 1024; n += 32){
        float vv = vp[n];
#pragma unroll
        for (int d = 0; d < 16; d++) acc[d] += kp[(size_t)d*NS + n]*vv;
    }
#pragma unroll
    for (int d = 0; d < 16; d++){
#pragma unroll
        for (int off = 16; off; off >>= 1) acc[d] += __shfl_xor_sync(0xffffffffu, acc[d], off);
    }
    if (lane == 0){
#pragma unroll
        for (int d = 0; d < 16; d++)
            part[(((size_t)bh*32 + chunk)*16 + e)*16 + d] = acc[d];
    }
}

__global__ void k_ctx_reduce(const float* __restrict__ part, const float* __restrict__ kinv,
                             float* __restrict__ ctx)
{
    int bh = blockIdx.x, t = threadIdx.x;
    int e = t >> 4, d = t & 15;
    float s = 0.f;
    for (int ch = 0; ch < 32; ch++) s += part[(((size_t)bh*32 + ch)*16 + e)*16 + d];
    int b = bh >> 2, hd = bh & 3;
    s *= kinv[b*Cc + hd*Dd + d];
    ctx[bh*256 + d*16 + e] = s;
}

// ---------------- K6: att (q softmax fused), writes transposed bf16 hi/lo ----------------
__global__ void k_att(const float* __restrict__ q, const float* __restrict__ ctx,
                      __nv_bfloat16* __restrict__ attsTh, __nv_bfloat16* __restrict__ attsTl)
{
    int bh = blockIdx.y;
    __shared__ float csm[256];
    for (int i = threadIdx.x; i < 256; i += 128) csm[i] = ctx[bh*256 + i];
    __syncthreads();
    int n = blockIdx.x*128 + threadIdx.x;
    int b = bh >> 2, hd = bh & 3;
    const float* qp = q + ((size_t)(b*Cc + hd*Dd))*NS + n;
    float qv[16];
    float mx = -1e30f;
#pragma unroll
    for (int d = 0; d < 16; d++){ qv[d] = qp[(size_t)d*NS]; mx = fmaxf(mx, qv[d]); }
    float ssum = 0.f;
#pragma unroll
    for (int d = 0; d < 16; d++){ qv[d] = __expf(qv[d]-mx); ssum += qv[d]; }
    float inv = 1.f/ssum;
    float o[16];
#pragma unroll
    for (int e = 0; e < 16; e++) o[e] = 0.f;
#pragma unroll
    for (int d = 0; d < 16; d++){
        float qd = qv[d]*inv;
#pragma unroll
        for (int e = 0; e < 16; e++) o[e] += csm[d*16 + e]*qd;
    }
    size_t base = ((size_t)b*NS + n)*64 + hd*16;
#pragma unroll
    for (int e = 0; e < 16; e++){
        __nv_bfloat16 h = __float2bfloat16(o[e]);
        attsTh[base + e] = h;
        attsTl[base + e] = __float2bfloat16(o[e] - __bfloat162float(h));
    }
}

// ---------------- K9: m2 depthwise 3x3 (C4 channels, pad 1) + gelu ----------------
__global__ void k_dw3x3_gelu(const float* __restrict__ in, const float* __restrict__ w,
                             const float* __restrict__ bias, float* __restrict__ out)
{
    int idx = blockIdx.x*256 + threadIdx.x;
    int x = idx & 255;
    int y = (idx >> 8) & 255;
    int c = (idx >> 16) & 255;
    const float* ip = in + (size_t)(idx >> 16) * NPIX;
    const float* wp = w + c*9;
    float s = bias[c];
#pragma unroll
    for (int dy = -1; dy <= 1; dy++){
        int rr = y + dy;
        if ((unsigned)rr < Hh){
#pragma unroll
            for (int dx = -1; dx <= 1; dx++){
                int cc = x + dx;
                if ((unsigned)cc < Ww)
                    s += wp[(dy+1)*3 + (dx+1)] * ip[rr*Ww + cc];
            }
        }
    }
    out[idx] = gelu_f(s);
}

// ---------------- launch ----------------
extern "C" void kernel_launch(void* const* d_in, const int* in_sizes, int n_in,
                              void* d_out, int out_size)
{
    (void)in_sizes; (void)n_in; (void)out_size;
    const float* x1   = (const float*)d_in[0];
    const float* x2   = (const float*)d_in[1];
    const float* q1_w = (const float*)d_in[2];
    const float* q1_b = (const float*)d_in[3];
    const float* q2_w = (const float*)d_in[4];
    const float* q2_b = (const float*)d_in[5];
    const float* k1_w = (const float*)d_in[6];
    const float* k1_b = (const float*)d_in[7];
    const float* k2_w = (const float*)d_in[8];
    const float* k2_b = (const float*)d_in[9];
    const float* v1_w = (const float*)d_in[10];
    const float* v1_b = (const float*)d_in[11];
    const float* v2_w = (const float*)d_in[12];
    const float* v2_b = (const float*)d_in[13];
    const float* r_w  = (const float*)d_in[14];
    const float* r_b  = (const float*)d_in[15];
    const float* m1_w = (const float*)d_in[16];
    const float* m1_b = (const float*)d_in[17];
    const float* m2_w = (const float*)d_in[18];
    const float* m2_b = (const float*)d_in[19];
    const float* m3_w = (const float*)d_in[20];
    const float* m3_b = (const float*)d_in[21];
    float* out = (float*)d_out;

    float *qs0, *ks0, *vpre, *qs, *ks, *vs, *kinv, *part, *ctx, *ma, *mb;
    __nv_bfloat16 *attsTh, *attsTl, *rw5h, *rw5l, *m1wh, *m1wl, *m3wh, *m3wl;
    __nv_bfloat16 *q1wh, *q1wl, *k1wh, *k1wl, *v1wh, *v1wl;
    cudaGetSymbolAddress((void**)&qs0,  g_qs0);
    cudaGetSymbolAddress((void**)&ks0,  g_ks0);
    cudaGetSymbolAddress((void**)&vpre, g_vpre);
    cudaGetSymbolAddress((void**)&qs,   g_qs);
    cudaGetSymbolAddress((void**)&ks,   g_ks);
    cudaGetSymbolAddress((void**)&vs,   g_vs);
    cudaGetSymbolAddress((void**)&kinv, g_kinv);
    cudaGetSymbolAddress((void**)&part, g_ctx_part);
    cudaGetSymbolAddress((void**)&ctx,  g_ctx);
    cudaGetSymbolAddress((void**)&ma,   g_ma);
    cudaGetSymbolAddress((void**)&mb,   g_mb);
    cudaGetSymbolAddress((void**)&attsTh, g_attsTh);
    cudaGetSymbolAddress((void**)&attsTl, g_attsTl);
    cudaGetSymbolAddress((void**)&rw5h, g_rw5h);
    cudaGetSymbolAddress((void**)&rw5l, g_rw5l);
    cudaGetSymbolAddress((void**)&m1wh, g_m1wh);
    cudaGetSymbolAddress((void**)&m1wl, g_m1wl);
    cudaGetSymbolAddress((void**)&m3wh, g_m3wh);
    cudaGetSymbolAddress((void**)&m3wl, g_m3wl);
    cudaGetSymbolAddress((void**)&q1wh, g_q1wh);
    cudaGetSymbolAddress((void**)&q1wl, g_q1wl);
    cudaGetSymbolAddress((void**)&k1wh, g_k1wh);
    cudaGetSymbolAddress((void**)&k1wl, g_k1wl);
    cudaGetSymbolAddress((void**)&v1wh, g_v1wh);
    cudaGetSymbolAddress((void**)&v1wl, g_v1wl);

    cudaFuncSetAttribute(k_gemm_mma<C2, C4, true, false>,
                         cudaFuncAttributeMaxDynamicSharedMemorySize, SM_GEMM_BYTES);
    cudaFuncSetAttribute(k_gemm_mma<C4, C2, false, true>,
                         cudaFuncAttributeMaxDynamicSharedMemorySize, SM_GEMM_BYTES);
    cudaFuncSetAttribute(k_conv5x5_mma,
                         cudaFuncAttributeMaxDynamicSharedMemorySize, SM_GEMM_BYTES);
    cudaFuncSetAttribute(k_conv1x1_mma<0>,
                         cudaFuncAttributeMaxDynamicSharedMemorySize, SM_QKV_BYTES);
    cudaFuncSetAttribute(k_conv1x1_mma<1>,
                         cudaFuncAttributeMaxDynamicSharedMemorySize, SM_QKV_BYTES);
    cudaFuncSetAttribute(k_conv1x1_mma<2>,
                         cudaFuncAttributeMaxDynamicSharedMemorySize, SM_QKV_BYTES);

    // weight prep (tiny)
    k_prep_rw5<<<800, 256>>>(r_w, rw5h, rw5l);
    k_prep_w<<<(C4*C2 + 255)/256, 256>>>(m1_w, m1wh, m1wl, C4*C2);
    k_prep_w<<<(C2*C4 + 255)/256, 256>>>(m3_w, m3wh, m3wl, C2*C4);
    k_prep_w<<<16, 256>>>(q1_w, q1wh, q1wl, Cc*Cc);
    k_prep_w<<<16, 256>>>(k1_w, k1wh, k1wl, Cc*Cc);
    k_prep_w<<<16, 256>>>(v1_w, v1wh, v1wl, Cc*Cc);

    // qkv 1x1 convs (HMMA)
    k_conv1x1_mma<0><<<dim3(NS/256,  Bq), 256, SM_QKV_BYTES>>>(x1, q1wh, q1wl, q1_b, qs0);
    k_conv1x1_mma<1><<<dim3(NS/256,  Bq), 256, SM_QKV_BYTES>>>(x1, k1wh, k1wl, k1_b, ks0);
    k_conv1x1_mma<2><<<dim3(NPIX/256, Bq), 256, SM_QKV_BYTES>>>(x2, v1wh, v1wl, v1_b, vpre);

    k_dw3x3_qk<<<(Bq*Cc*NS)/256, 256>>>(qs0, q2_w, q2_b, q1_b, qs, 0);
    k_dw3x3_qk<<<(Bq*Cc*NS)/256, 256>>>(ks0, k2_w, k2_b, k1_b, ks, 1);
    k_dw3x3_v <<<(Bq*Cc*NS)/256, 256>>>(vpre, v2_w, v2_b, vs);

    k_softmax_n_exp<<<Bq*Cc, 256>>>(ks, kinv);

    k_ctx_part<<<dim3(32, Bq*NHEAD), 512>>>(ks, vs, part);
    k_ctx_reduce<<<Bq*NHEAD, 256>>>(part, kinv, ctx);

    k_att<<<dim3(NS/128, Bq*NHEAD), 128>>>(qs, ctx, attsTh, attsTl);

    // conv5x5 via implicit GEMM (HMMA split-bf16, cp.async staging), two parity classes
    k_conv5x5_mma<<<dim3(256, Bq*2), 256, SM_GEMM_BYTES>>>(attsTh, attsTl, rw5h, rw5l, r_b, out);

    // m1: 128 -> 256 + gelu (HMMA split-bf16)
    k_gemm_mma<C2, C4, true, false><<<dim3(Bq*(NPIX/128), C4/128), 256, SM_GEMM_BYTES>>>(out, m1wh, m1wl, m1_b, ma);
    k_dw3x3_gelu<<<(Bq*C4*NPIX)/256, 256>>>(ma, m2_w, m2_b, mb);
    // m3: 256 -> 128 + residual into out (HMMA split-bf16)
    k_gemm_mma<C4, C2, false, true><<<dim3(Bq*(NPIX/128), C2/128), 256, SM_GEMM_BYTES>>>(mb, m3wh, m3wl, m3_b, out);
}

// round 14
// speedup vs baseline: 3.1791x; 1.0457x over previous
#include <cuda_runtime.h>
#include <cuda_bf16.h>
#include <math.h>
#include <stdint.h>

#define Bq    4
#define Cc    64
#define Hh    256
#define Ww    256
#define W2    128
#define NPIX  65536   // Hh*Ww
#define NS    32768   // Hh*W2
#define NHEAD 4
#define Dd    16
#define C2    128
#define C4    256

// ---------------- scratch (device globals; no runtime allocation) ----------------
__device__ float g_qs0 [(size_t)Bq*Cc*NS];
__device__ float g_ks0 [(size_t)Bq*Cc*NS];
__device__ float g_vpre[(size_t)Bq*Cc*NPIX];
__device__ float g_qs  [(size_t)Bq*Cc*NS];
__device__ float g_ks  [(size_t)Bq*Cc*NS];
__device__ float g_vs  [(size_t)Bq*Cc*NS];
__device__ float g_kinv[Bq*Cc];
__device__ float g_ctx_part[16*32*16*16];
__device__ float g_ctx[16*256];
__device__ float g_ma[(size_t)Bq*C4*NPIX];
__device__ float g_mb[(size_t)Bq*C4*NPIX];
// bf16 hi/lo staging sources
__device__ __nv_bfloat16 g_attsTh[(size_t)Bq*NS*64];   // [b][n][ci]
__device__ __nv_bfloat16 g_attsTl[(size_t)Bq*NS*64];
__device__ __nv_bfloat16 g_rw5h[25*128*64];            // [tap][co][ci]
__device__ __nv_bfloat16 g_rw5l[25*128*64];
__device__ __nv_bfloat16 g_m1wh[C4*C2];
__device__ __nv_bfloat16 g_m1wl[C4*C2];
__device__ __nv_bfloat16 g_m3wh[C2*C4];
__device__ __nv_bfloat16 g_m3wl[C2*C4];
__device__ __nv_bfloat16 g_q1wh[Cc*Cc];
__device__ __nv_bfloat16 g_q1wl[Cc*Cc];
__device__ __nv_bfloat16 g_k1wh[Cc*Cc];
__device__ __nv_bfloat16 g_k1wl[Cc*Cc];
__device__ __nv_bfloat16 g_v1wh[Cc*Cc];
__device__ __nv_bfloat16 g_v1wl[Cc*Cc];

// tap tables: class 0 = (ky+kx) even (13 taps), class 1 = odd (12 taps)
__device__ __constant__ int8_t TAPS_E[13][2] = {
    {0,0},{0,2},{0,4},{1,1},{1,3},{2,0},{2,2},{2,4},{3,1},{3,3},{4,0},{4,2},{4,4}};
__device__ __constant__ int8_t TAPS_O[12][2] = {
    {0,1},{0,3},{1,0},{1,2},{1,4},{2,1},{2,3},{3,0},{3,2},{3,4},{4,1},{4,3}};

__device__ __forceinline__ float gelu_f(float x){
    return 0.5f * x * (1.0f + erff(x * 0.70710678118654752f));
}

// ================= mma.sync + cp.async helpers (baseline ISA) =================
__device__ __forceinline__ void ldsm4(uint32_t &r0, uint32_t &r1, uint32_t &r2, uint32_t &r3, uint32_t addr){
    asm volatile("ldmatrix.sync.aligned.m8n8.x4.shared.b16 {%0,%1,%2,%3}, [%4];"
                 : "=r"(r0), "=r"(r1), "=r"(r2), "=r"(r3) : "r"(addr));
}
__device__ __forceinline__ void mma16816(float* c, const uint32_t* a, uint32_t b0, uint32_t b1){
    asm volatile(
        "mma.sync.aligned.m16n8k16.row.col.f32.bf16.bf16.f32 "
        "{%0,%1,%2,%3}, {%4,%5,%6,%7}, {%8,%9}, {%0,%1,%2,%3};"
        : "+f"(c[0]), "+f"(c[1]), "+f"(c[2]), "+f"(c[3])
        : "r"(a[0]), "r"(a[1]), "r"(a[2]), "r"(a[3]), "r"(b0), "r"(b1));
}
__device__ __forceinline__ void cpasync16(uint32_t smem_addr, const void* gptr, int src_bytes){
    asm volatile("cp.async.cg.shared.global [%0], [%1], 16, %2;"
                 :: "r"(smem_addr), "l"(gptr), "r"(src_bytes) : "memory");
}
#define CPASYNC_WAIT_ALL() asm volatile("cp.async.commit_group;\ncp.async.wait_group 0;" ::: "memory")
#define CPASYNC_COMMIT()   asm volatile("cp.async.commit_group;" ::: "memory")
#define CPASYNC_WAIT1()    asm volatile("cp.async.wait_group 1;" ::: "memory")
#define CPASYNC_WAIT0()    asm volatile("cp.async.wait_group 0;" ::: "memory")

#define KC    64
#define PAD   72                              // bf16 per smem row (144B stride, 16B aligned)
#define PADB  144
#define SMEM_OP (128*PAD)
#define SM_GEMM_BYTES (4*SMEM_OP*2)           // Ah, Al, Bh, Bl

// qkv GEMM smem layout: A 64 rows, B 256 rows (h/l each)
#define QKV_A_BYTES (64*PADB)                 // 9216
#define QKV_B_BYTES (256*PADB)                // 36864
#define SM_QKV_BYTES (2*QKV_A_BYTES + 2*QKV_B_BYTES)  // 92160

// conv5x5 v2 smem: A double-buffered (h/l), B halo (216 rows, h/l)
#define C5_A_BYTES (128*PADB)                 // 18432
#define C5_B_ROWS  216
#define C5_B_BYTES (C5_B_ROWS*PADB)           // 31104
#define SM_C5_BYTES (4*C5_A_BYTES + 2*C5_B_BYTES)   // 135936

// ================= prep kernels: one-time float -> bf16 hi/lo =================
__global__ void k_prep_w(const float* __restrict__ w, __nv_bfloat16* __restrict__ h,
                         __nv_bfloat16* __restrict__ l, int n)
{
    int i = blockIdx.x*256 + threadIdx.x;
    if (i < n){
        float v = w[i];
        __nv_bfloat16 hh = __float2bfloat16(v);
        h[i] = hh;
        l[i] = __float2bfloat16(v - __bfloat162float(hh));
    }
}
__global__ void k_prep_rw5(const float* __restrict__ rw, __nv_bfloat16* __restrict__ h,
                           __nv_bfloat16* __restrict__ l)
{
    int i = blockIdx.x*256 + threadIdx.x;      // 25*128*64 = 204800
    int tap = i >> 13;
    int rem = i & 8191;
    float v = rw[(size_t)rem*25 + tap];
    __nv_bfloat16 hh = __float2bfloat16(v);
    h[i] = hh;
    l[i] = __float2bfloat16(v - __bfloat162float(hh));
}

// ================= qkv 1x1 conv as HMMA GEMM: tile 64co x 256pos, K=64 =================
template<int MODE>
__global__ void __launch_bounds__(256)
k_conv1x1_mma(const float* __restrict__ x,
              const __nv_bfloat16* __restrict__ wh, const __nv_bfloat16* __restrict__ wl,
              const float* __restrict__ bias, float* __restrict__ outp)
{
    const int OSTR = (MODE == 2) ? NPIX : NS;
    extern __shared__ __align__(16) __nv_bfloat16 sm[];
    uint32_t aBaseH = (uint32_t)__cvta_generic_to_shared(sm);
    uint32_t aBaseL = aBaseH + QKV_A_BYTES;
    uint32_t bBaseH = aBaseH + 2*QKV_A_BYTES;
    uint32_t bBaseL = bBaseH + QKV_B_BYTES;
    __nv_bfloat16* Bh = sm + 2*QKV_A_BYTES/2;
    __nv_bfloat16* Bl = sm + (2*QKV_A_BYTES + QKV_B_BYTES)/2;

    int tid = threadIdx.x;
    int b = blockIdx.y;
    int posBase = blockIdx.x*256;
    int lane = tid & 31, warp = tid >> 5;
    int wco = (warp & 1)*32;
    int wpos = (warp >> 1)*64;

    for (int i = tid; i < 512; i += 256){
        int co = i >> 3, ch = i & 7;
        uint32_t d = co*PADB + ch*16;
        cpasync16(aBaseH + d, wh + co*64 + ch*8, 16);
        cpasync16(aBaseL + d, wl + co*64 + ch*8, 16);
    }
    for (int i = tid; i < 16384; i += 256){
        int ci = i >> 8, p = i & 255;
        int ps = posBase + p;
        size_t gidx;
        if (MODE == 2){
            gidx = ((size_t)(b*Cc + ci))*NPIX + ps;
        } else {
            int j = ps & (W2-1);
            int r = ps >> 7;
            int o = (MODE == 1) ? (1 - (r & 1)) : (r & 1);
            gidx = ((size_t)(b*Cc + ci))*NPIX + r*Ww + 2*j + o;
        }
        float v = x[gidx];
        __nv_bfloat16 h = __float2bfloat16(v);
        __nv_bfloat16 l = __float2bfloat16(v - __bfloat162float(h));
        Bh[p*PAD + ci] = h;
        Bl[p*PAD + ci] = l;
    }
    CPASYNC_WAIT_ALL();
    __syncthreads();

    float acc[2][8][4];
#pragma unroll
    for (int mt = 0; mt < 2; mt++)
#pragma unroll
        for (int nt = 0; nt < 8; nt++)
#pragma unroll
            for (int r = 0; r < 4; r++) acc[mt][nt][r] = 0.f;

#pragma unroll
    for (int ks = 0; ks < 4; ks++){
        int k0 = ks*16;
        int g = lane >> 3;
        int rofs = (lane & 7) + ((g & 1) ? 8 : 0);
        int cofs = k0 + ((g >> 1) ? 8 : 0);
        uint32_t ah[2][4], al[2][4];
#pragma unroll
        for (int mt = 0; mt < 2; mt++){
            uint32_t off = ((wco + mt*16 + rofs)*PAD + cofs)*2;
            ldsm4(ah[mt][0], ah[mt][1], ah[mt][2], ah[mt][3], aBaseH + off);
            ldsm4(al[mt][0], al[mt][1], al[mt][2], al[mt][3], aBaseL + off);
        }
        uint32_t bh[4][4], bl[4][4];
#pragma unroll
        for (int ntp = 0; ntp < 4; ntp++){
            uint32_t off = ((wpos + ntp*16 + rofs)*PAD + cofs)*2;
            ldsm4(bh[ntp][0], bh[ntp][1], bh[ntp][2], bh[ntp][3], bBaseH + off);
            ldsm4(bl[ntp][0], bl[ntp][1], bl[ntp][2], bl[ntp][3], bBaseL + off);
        }
#pragma unroll
        for (int mt = 0; mt < 2; mt++){
#pragma unroll
            for (int ntp = 0; ntp < 4; ntp++){
#pragma unroll
                for (int sub = 0; sub < 2; sub++){
                    int nt = ntp*2 + sub;
                    uint32_t h0 = bh[ntp][sub], h1 = bh[ntp][sub+2];
                    uint32_t l0 = bl[ntp][sub], l1 = bl[ntp][sub+2];
                    mma16816(acc[mt][nt], ah[mt], h0, h1);
                    mma16816(acc[mt][nt], ah[mt], l0, l1);
                    mma16816(acc[mt][nt], al[mt], h0, h1);
                }
            }
        }
    }

    {
        int r = lane >> 2, cc = (lane & 3)*2;
#pragma unroll
        for (int mt = 0; mt < 2; mt++){
            int co0 = wco + mt*16 + r;
            float bv0 = bias[co0], bv8 = bias[co0 + 8];
            float* op0 = outp + ((size_t)(b*Cc + co0    ))*OSTR + posBase + wpos + cc;
            float* op8 = outp + ((size_t)(b*Cc + co0 + 8))*OSTR + posBase + wpos + cc;
#pragma unroll
            for (int nt = 0; nt < 8; nt++){
                float2 v0, v8;
                v0.x = acc[mt][nt][0] + bv0;  v0.y = acc[mt][nt][1] + bv0;
                v8.x = acc[mt][nt][2] + bv8;  v8.y = acc[mt][nt][3] + bv8;
                *(float2*)(op0 + nt*8) = v0;
                *(float2*)(op8 + nt*8) = v8;
            }
        }
    }
}

// ================= generic 1x1 GEMM (m1/m3) =================
template<int CIN, int COUT, bool GELU, bool RES>
__global__ void __launch_bounds__(256, 1)
k_gemm_mma(const float* __restrict__ in,
           const __nv_bfloat16* __restrict__ wh, const __nv_bfloat16* __restrict__ wl,
           const float* __restrict__ bias, float* __restrict__ out)
{
    extern __shared__ __align__(16) __nv_bfloat16 sm[];
    __nv_bfloat16* Bh = sm + 2*SMEM_OP;
    __nv_bfloat16* Bl = sm + 3*SMEM_OP;
    uint32_t aBaseH = (uint32_t)__cvta_generic_to_shared(sm);
    uint32_t aBaseL = aBaseH + SMEM_OP*2;
    uint32_t bBaseH = aBaseH + 2*SMEM_OP*2;
    uint32_t bBaseL = aBaseH + 3*SMEM_OP*2;

    int tid = threadIdx.x;
    int b = blockIdx.x >> 9;
    int posBase = (blockIdx.x & 511)*128;
    int coBase = blockIdx.y*128;
    int lane = tid & 31, warp = tid >> 5;
    int wco = (warp & 3)*32;
    int wpos = (warp >> 2)*64;

    float acc[2][8][4];
#pragma unroll
    for (int mt = 0; mt < 2; mt++)
#pragma unroll
        for (int nt = 0; nt < 8; nt++)
#pragma unroll
            for (int r = 0; r < 4; r++) acc[mt][nt][r] = 0.f;

    const int KO = CIN/KC;
#pragma unroll 1
    for (int ko = 0; ko < KO; ko++){
        __syncthreads();
        for (int i = tid; i < 1024; i += 256){
            int co = i >> 3, ch = i & 7;
            uint32_t d = co*PADB + ch*16;
            cpasync16(aBaseH + d, wh + (size_t)(coBase + co)*CIN + ko*KC + ch*8, 16);
            cpasync16(aBaseL + d, wl + (size_t)(coBase + co)*CIN + ko*KC + ch*8, 16);
        }
        for (int i = tid; i < 128*KC; i += 256){
            int p = i & 127, ci = i >> 7;
            float v = in[((size_t)(b*CIN + ko*KC + ci))*NPIX + posBase + p];
            __nv_bfloat16 h = __float2bfloat16(v);
            __nv_bfloat16 l = __float2bfloat16(v - __bfloat162float(h));
            Bh[p*PAD + ci] = h;
            Bl[p*PAD + ci] = l;
        }
        CPASYNC_WAIT_ALL();
        __syncthreads();

#pragma unroll
        for (int ks = 0; ks < KC/16; ks++){
            int k0 = ks*16;
            int g = lane >> 3;
            int rofs = (lane & 7) + ((g & 1) ? 8 : 0);
            int cofs = k0 + ((g >> 1) ? 8 : 0);
            uint32_t ah[2][4], al[2][4];
#pragma unroll
            for (int mt = 0; mt < 2; mt++){
                uint32_t off = ((wco + mt*16 + rofs)*PAD + cofs)*2;
                ldsm4(ah[mt][0], ah[mt][1], ah[mt][2], ah[mt][3], aBaseH + off);
                ldsm4(al[mt][0], al[mt][1], al[mt][2], al[mt][3], aBaseL + off);
            }
            uint32_t bh[4][4], bl[4][4];
#pragma unroll
            for (int ntp = 0; ntp < 4; ntp++){
                uint32_t off = ((wpos + ntp*16 + rofs)*PAD + cofs)*2;
                ldsm4(bh[ntp][0], bh[ntp][1], bh[ntp][2], bh[ntp][3], bBaseH + off);
                ldsm4(bl[ntp][0], bl[ntp][1], bl[ntp][2], bl[ntp][3], bBaseL + off);
            }
#pragma unroll
            for (int mt = 0; mt < 2; mt++){
#pragma unroll
                for (int ntp = 0; ntp < 4; ntp++){
#pragma unroll
                    for (int sub = 0; sub < 2; sub++){
                        int nt = ntp*2 + sub;
                        uint32_t h0 = bh[ntp][sub], h1 = bh[ntp][sub+2];
                        uint32_t l0 = bl[ntp][sub], l1 = bl[ntp][sub+2];
                        mma16816(acc[mt][nt], ah[mt], h0, h1);
                        mma16816(acc[mt][nt], ah[mt], l0, l1);
                        mma16816(acc[mt][nt], al[mt], h0, h1);
                    }
                }
            }
        }
    }

    {
        int r = lane >> 2, cc = (lane & 3)*2;
#pragma unroll
        for (int mt = 0; mt < 2; mt++){
            int co0 = coBase + wco + mt*16 + r;
            float bv0 = bias[co0], bv8 = bias[co0 + 8];
            float* op0 = out + ((size_t)(b*COUT + co0    ))*NPIX + posBase + wpos + cc;
            float* op8 = out + ((size_t)(b*COUT + co0 + 8))*NPIX + posBase + wpos + cc;
#pragma unroll
            for (int nt = 0; nt < 8; nt++){
                float2 v0, v8;
                v0.x = acc[mt][nt][0] + bv0;  v0.y = acc[mt][nt][1] + bv0;
                v8.x = acc[mt][nt][2] + bv8;  v8.y = acc[mt][nt][3] + bv8;
                if (GELU){
                    v0.x = gelu_f(v0.x); v0.y = gelu_f(v0.y);
                    v8.x = gelu_f(v8.x); v8.y = gelu_f(v8.y);
                }
                if (RES){
                    float2 o0 = *(const float2*)(op0 + nt*8);
                    float2 o8 = *(const float2*)(op8 + nt*8);
                    v0.x += o0.x; v0.y += o0.y;
                    v8.x += o8.x; v8.y += o8.y;
                }
                *(float2*)(op0 + nt*8) = v0;
                *(float2*)(op8 + nt*8) = v8;
            }
        }
    }
}

// ================= conv5x5 v2: halo B staged once, A double-buffered pipeline =================
__global__ void __launch_bounds__(256, 1)
k_conv5x5_mma(const __nv_bfloat16* __restrict__ attsTh, const __nv_bfloat16* __restrict__ attsTl,
              const __nv_bfloat16* __restrict__ rw5h, const __nv_bfloat16* __restrict__ rw5l,
              const float* __restrict__ rb, float* __restrict__ out)
{
    extern __shared__ __align__(16) __nv_bfloat16 sm[];
    uint32_t smb = (uint32_t)__cvta_generic_to_shared(sm);
    uint32_t aB0 = smb;                         // A buf0 h, then l
    uint32_t aB1 = smb + 2*C5_A_BYTES;          // A buf1 h, then l
    uint32_t bBaseH = smb + 4*C5_A_BYTES;
    uint32_t bBaseL = bBaseH + C5_B_BYTES;

    int tid = threadIdx.x;
    int tx = blockIdx.x;                        // 256 tiles: (tx>>3) y-tile, (tx&7) j-tile
    int z = blockIdx.y;                         // b*2 + pc
    int b = z >> 1, pc = z & 1;
    int jBase = (tx & 7)*16;
    int yBase = (tx >> 3)*8;
    int NT = pc ? 12 : 13;
    int lane = tid & 31, warp = tid >> 5;
    int wco = (warp & 3)*32;
    int wpos = (warp >> 2)*64;

    // ---- stage halo B (once): rows hr = hy*18+hj, hy in 0..11 (yy=yBase-2+hy), hj in 0..17 (jj=jBase-1+hj)
    for (int i = tid; i < C5_B_ROWS*8; i += 256){
        int row = i >> 3, ch = i & 7;
        int hy = row/18, hj = row - hy*18;
        int yy = yBase - 2 + hy;
        int jj = jBase - 1 + hj;
        bool inb = ((unsigned)yy < Hh) && ((unsigned)jj < W2);
        size_t go = inb ? (((size_t)b*NS + yy*W2 + jj)*64 + ch*8) : 0;
        int nb = inb ? 16 : 0;
        uint32_t d = row*PADB + ch*16;
        cpasync16(bBaseH + d, attsTh + go, nb);
        cpasync16(bBaseL + d, attsTl + go, nb);
    }
    // ---- stage A for tap 0 into buf0
    {
        int tap0 = pc ? (TAPS_O[0][0]*5 + TAPS_O[0][1]) : (TAPS_E[0][0]*5 + TAPS_E[0][1]);
        const __nv_bfloat16* ah = rw5h + tap0*8192;
        const __nv_bfloat16* al = rw5l + tap0*8192;
        for (int i = tid; i < 1024; i += 256){
            int co = i >> 3, ch = i & 7;
            uint32_t d = co*PADB + ch*16;
            cpasync16(aB0 + d,              ah + co*64 + ch*8, 16);
            cpasync16(aB0 + C5_A_BYTES + d, al + co*64 + ch*8, 16);
        }
    }
    CPASYNC_COMMIT();

    // per-lane constants
    int g = lane >> 3;
    int rofs = (lane & 7) + ((g & 1) ? 8 : 0);
    int cofsk = (g >> 1) ? 8 : 0;
    int pyl[4], pjx[4], spar[4];
#pragma unroll
    for (int ntp = 0; ntp < 4; ntp++){
        int p = wpos + ntp*16 + rofs;
        pyl[ntp] = p >> 4;
        pjx[ntp] = p & 15;
        spar[ntp] = (pyl[ntp] & 1) ^ pc;        // yBase is even
    }

    float acc[2][8][4];
#pragma unroll
    for (int mt = 0; mt < 2; mt++)
#pragma unroll
        for (int nt = 0; nt < 8; nt++)
#pragma unroll
            for (int r = 0; r < 4; r++) acc[mt][nt][r] = 0.f;

#pragma unroll 1
    for (int t = 0; t < NT; t++){
        int ky = pc ? TAPS_O[t][0] : TAPS_E[t][0];
        int kx = pc ? TAPS_O[t][1] : TAPS_E[t][1];
        if (t + 1 < NT){
            __syncthreads();                    // all MMA(t-1) reads done before overwriting alt buffer
            int tapn = pc ? (TAPS_O[t+1][0]*5 + TAPS_O[t+1][1]) : (TAPS_E[t+1][0]*5 + TAPS_E[t+1][1]);
            uint32_t aDst = ((t+1) & 1) ? aB1 : aB0;
            const __nv_bfloat16* ah = rw5h + tapn*8192;
            const __nv_bfloat16* al = rw5l + tapn*8192;
            for (int i = tid; i < 1024; i += 256){
                int co = i >> 3, ch = i & 7;
                uint32_t d = co*PADB + ch*16;
                cpasync16(aDst + d,              ah + co*64 + ch*8, 16);
                cpasync16(aDst + C5_A_BYTES + d, al + co*64 + ch*8, 16);
            }
            CPASYNC_COMMIT();
            CPASYNC_WAIT1();                    // tap t's group (and halo) complete
        } else {
            CPASYNC_WAIT0();
        }
        __syncthreads();

        uint32_t aH = (t & 1) ? aB1 : aB0;
        uint32_t aL = aH + C5_A_BYTES;
        // per-ntp halo row byte offsets for this tap
        uint32_t bro[4];
#pragma unroll
        for (int ntp = 0; ntp < 4; ntp++){
            int shift = (spar[ntp] + kx - 2) >> 1;
            int hr = (pyl[ntp] + ky)*18 + pjx[ntp] + 1 + shift;
            bro[ntp] = (uint32_t)hr*PADB;
        }

#pragma unroll
        for (int ks = 0; ks < 4; ks++){
            int cofs = ks*16 + cofsk;
            uint32_t ah[2][4], al[2][4];
#pragma unroll
            for (int mt = 0; mt < 2; mt++){
                uint32_t off = ((wco + mt*16 + rofs)*PAD + cofs)*2;
                ldsm4(ah[mt][0], ah[mt][1], ah[mt][2], ah[mt][3], aH + off);
                ldsm4(al[mt][0], al[mt][1], al[mt][2], al[mt][3], aL + off);
            }
            uint32_t bh[4][4], bl[4][4];
#pragma unroll
            for (int ntp = 0; ntp < 4; ntp++){
                uint32_t off = bro[ntp] + (uint32_t)cofs*2;
                ldsm4(bh[ntp][0], bh[ntp][1], bh[ntp][2], bh[ntp][3], bBaseH + off);
                ldsm4(bl[ntp][0], bl[ntp][1], bl[ntp][2], bl[ntp][3], bBaseL + off);
            }
#pragma unroll
            for (int mt = 0; mt < 2; mt++){
#pragma unroll
                for (int ntp = 0; ntp < 4; ntp++){
#pragma unroll
                    for (int sub = 0; sub < 2; sub++){
                        int nt = ntp*2 + sub;
                        uint32_t h0 = bh[ntp][sub], h1 = bh[ntp][sub+2];
                        uint32_t l0 = bl[ntp][sub], l1 = bl[ntp][sub+2];
                        mma16816(acc[mt][nt], ah[mt], h0, h1);
                        mma16816(acc[mt][nt], ah[mt], l0, l1);
                        mma16816(acc[mt][nt], al[mt], h0, h1);
                    }
                }
            }
        }
    }

    // epilogue (unchanged mapping)
    {
        int r = lane >> 2, cc = (lane & 3)*2;
#pragma unroll
        for (int mt = 0; mt < 2; mt++){
            int co0 = wco + mt*16 + r;
            float bv0 = rb[co0], bv8 = rb[co0 + 8];
#pragma unroll
            for (int nt = 0; nt < 8; nt++){
                int p = wpos + nt*8 + cc;
                int yl = p >> 4, jx = p & 15;
                int y = yBase + yl;
                int s = (y & 1) ^ pc;
                int x0 = 2*(jBase + jx) + s;
                size_t r0 = ((size_t)(b*C2 + co0    ))*NPIX + y*Ww + x0;
                size_t r8 = ((size_t)(b*C2 + co0 + 8))*NPIX + y*Ww + x0;
                out[r0]     = acc[mt][nt][0] + bv0;
                out[r0 + 2] = acc[mt][nt][1] + bv0;
                out[r8]     = acc[mt][nt][2] + bv8;
                out[r8 + 2] = acc[mt][nt][3] + bv8;
            }
        }
    }
}

// ---------------- K2a: depthwise 3x3 for q/k on squeezed pre-buffer ----------------
__global__ void k_dw3x3_qk(const float* __restrict__ in, const float* __restrict__ w,
                           const float* __restrict__ bias, const float* __restrict__ pbias,
                           float* __restrict__ out, int anchorSel)
{
    int idx = blockIdx.x*256 + threadIdx.x;
    int j = idx & (W2-1);
    int r = (idx >> 7) & (Hh-1);
    int c = (idx >> 15) & (Cc-1);
    int o = anchorSel ? (1 - (r & 1)) : (r & 1);
    int col = 2*j + o;
    const float* ip = in + (size_t)(idx >> 15) * NS;
    const float* wp = w + c*9;

    float s = bias[c] + wp[4]*ip[r*W2 + j];
    float cb = pbias[c];
    float bw = 0.f;
    if (r > 0)       bw += wp[1];
    if (r < Hh-1)    bw += wp[7];
    if (col > 0)     bw += wp[3];
    if (col < Ww-1)  bw += wp[5];
    s += cb * bw;
    int jm = j - 1 + o, jp = j + o;
    if (r > 0){
        const float* rp = ip + (r-1)*W2;
        if ((unsigned)jm < W2) s += wp[0]*rp[jm];
        if ((unsigned)jp < W2) s += wp[2]*rp[jp];
    }
    if (r < Hh-1){
        const float* rp = ip + (r+1)*W2;
        if ((unsigned)jm < W2) s += wp[6]*rp[jm];
        if ((unsigned)jp < W2) s += wp[8]*rp[jp];
    }
    out[idx] = s;
}

// ---------------- K2b: depthwise 3x3 for v ----------------
__global__ void k_dw3x3_v(const float* __restrict__ in, const float* __restrict__ w,
                          const float* __restrict__ bias, float* __restrict__ out)
{
    int idx = blockIdx.x*256 + threadIdx.x;
    int j = idx & (W2-1);
    int r = (idx >> 7) & (Hh-1);
    int c = (idx >> 15) & (Cc-1);
    int col = 2*j + (1 - (r & 1));
    const float* ip = in + (size_t)(idx >> 15) * NPIX;
    const float* wp = w + c*9;
    float s = bias[c];
#pragma unroll
    for (int dy = -1; dy <= 1; dy++){
        int rr = r + dy;
        if ((unsigned)rr < Hh){
#pragma unroll
            for (int dx = -1; dx <= 1; dx++){
                int cc = col + dx;
                if ((unsigned)cc < Ww)
                    s += wp[(dy+1)*3 + (dx+1)] * ip[rr*Ww + cc];
            }
        }
    }
    out[idx] = s;
}

// ---------------- K4: k softmax (max + exp; normalization deferred) ----------------
__global__ void k_softmax_n_exp(float* __restrict__ kk, float* __restrict__ kinv)
{
    int row = blockIdx.x;
    float* p = kk + (size_t)row*NS;
    int tid = threadIdx.x;
    __shared__ float red[256];
    float mx = -1e30f;
    for (int i = tid; i < NS; i += 256) mx = fmaxf(mx, p[i]);
    red[tid] = mx; __syncthreads();
    for (int s = 128; s > 0; s >>= 1){ if (tid < s) red[tid] = fmaxf(red[tid], red[tid+s]); __syncthreads(); }
    mx = red[0]; __syncthreads();
    float sum = 0.f;
    for (int i = tid; i < NS; i += 256){
        float e = __expf(p[i]-mx);
        p[i] = e;
        sum += e;
    }
    red[tid] = sum; __syncthreads();
    for (int s = 128; s > 0; s >>= 1){ if (tid < s) red[tid] += red[tid+s]; __syncthreads(); }
    if (tid == 0) kinv[row] = 1.f/red[0];
}

// ---------------- K5: ctx partials ----------------
__global__ void k_ctx_part(const float* __restrict__ ks, const float* __restrict__ vs,
                           float* __restrict__ part)
{
    int bh = blockIdx.y;
    int chunk = blockIdx.x;
    int e    = threadIdx.x >> 5;
    int lane = threadIdx.x & 31;
    int b = bh >> 2, hd = bh & 3;
    const float* kp = ks + ((size_t)(b*Cc + hd*Dd))*NS;
    const float* vp = vs + ((size_t)(b*Cc + hd*Dd + e))*NS;
    float acc[16];
#pragma unroll
    for (int d = 0; d < 16; d++) acc[d] = 0.f;
    int n0 = chunk*1024;
    for (int n = n0 + lane; n < n0 + 1024; n += 32){
        float vv = vp[n];
#pragma unroll
        for (int d = 0; d < 16; d++) acc[d] += kp[(size_t)d*NS + n]*vv;
    }
#pragma unroll
    for (int d = 0; d < 16; d++){
#pragma unroll
        for (int off = 16; off; off >>= 1) acc[d] += __shfl_xor_sync(0xffffffffu, acc[d], off);
    }
    if (lane == 0){
#pragma unroll
        for (int d = 0; d < 16; d++)
            part[(((size_t)bh*32 + chunk)*16 + e)*16 + d] = acc[d];
    }
}

__global__ void k_ctx_reduce(const float* __restrict__ part, const float* __restrict__ kinv,
                             float* __restrict__ ctx)
{
    int bh = blockIdx.x, t = threadIdx.x;
    int e = t >> 4, d = t & 15;
    float s = 0.f;
    for (int ch = 0; ch < 32; ch++) s += part[(((size_t)bh*32 + ch)*16 + e)*16 + d];
    int b = bh >> 2, hd = bh & 3;
    s *= kinv[b*Cc + hd*Dd + d];
    ctx[bh*256 + d*16 + e] = s;
}

// ---------------- K6: att (q softmax fused), writes transposed bf16 hi/lo ----------------
__global__ void k_att(const float* __restrict__ q, const float* __restrict__ ctx,
                      __nv_bfloat16* __restrict__ attsTh, __nv_bfloat16* __restrict__ attsTl)
{
    int bh = blockIdx.y;
    __shared__ float csm[256];
    for (int i = threadIdx.x; i < 256; i += 128) csm[i] = ctx[bh*256 + i];
    __syncthreads();
    int n = blockIdx.x*128 + threadIdx.x;
    int b = bh >> 2, hd = bh & 3;
    const float* qp = q + ((size_t)(b*Cc + hd*Dd))*NS + n;
    float qv[16];
    float mx = -1e30f;
#pragma unroll
    for (int d = 0; d < 16; d++){ qv[d] = qp[(size_t)d*NS]; mx = fmaxf(mx, qv[d]); }
    float ssum = 0.f;
#pragma unroll
    for (int d = 0; d < 16; d++){ qv[d] = __expf(qv[d]-mx); ssum += qv[d]; }
    float inv = 1.f/ssum;
    float o[16];
#pragma unroll
    for (int e = 0; e < 16; e++) o[e] = 0.f;
#pragma unroll
    for (int d = 0; d < 16; d++){
        float qd = qv[d]*inv;
#pragma unroll
        for (int e = 0; e < 16; e++) o[e] += csm[d*16 + e]*qd;
    }
    size_t base = ((size_t)b*NS + n)*64 + hd*16;
#pragma unroll
    for (int e = 0; e < 16; e++){
        __nv_bfloat16 h = __float2bfloat16(o[e]);
        attsTh[base + e] = h;
        attsTl[base + e] = __float2bfloat16(o[e] - __bfloat162float(h));
    }
}

// ---------------- K9: m2 depthwise 3x3 (C4 channels, pad 1) + gelu ----------------
__global__ void k_dw3x3_gelu(const float* __restrict__ in, const float* __restrict__ w,
                             const float* __restrict__ bias, float* __restrict__ out)
{
    int idx = blockIdx.x*256 + threadIdx.x;
    int x = idx & 255;
    int y = (idx >> 8) & 255;
    int c = (idx >> 16) & 255;
    const float* ip = in + (size_t)(idx >> 16) * NPIX;
    const float* wp = w + c*9;
    float s = bias[c];
#pragma unroll
    for (int dy = -1; dy <= 1; dy++){
        int rr = y + dy;
        if ((unsigned)rr < Hh){
#pragma unroll
            for (int dx = -1; dx <= 1; dx++){
                int cc = x + dx;
                if ((unsigned)cc < Ww)
                    s += wp[(dy+1)*3 + (dx+1)] * ip[rr*Ww + cc];
            }
        }
    }
    out[idx] = gelu_f(s);
}

// ---------------- launch ----------------
extern "C" void kernel_launch(void* const* d_in, const int* in_sizes, int n_in,
                              void* d_out, int out_size)
{
    (void)in_sizes; (void)n_in; (void)out_size;
    const float* x1   = (const float*)d_in[0];
    const float* x2   = (const float*)d_in[1];
    const float* q1_w = (const float*)d_in[2];
    const float* q1_b = (const float*)d_in[3];
    const float* q2_w = (const float*)d_in[4];
    const float* q2_b = (const float*)d_in[5];
    const float* k1_w = (const float*)d_in[6];
    const float* k1_b = (const float*)d_in[7];
    const float* k2_w = (const float*)d_in[8];
    const float* k2_b = (const float*)d_in[9];
    const float* v1_w = (const float*)d_in[10];
    const float* v1_b = (const float*)d_in[11];
    const float* v2_w = (const float*)d_in[12];
    const float* v2_b = (const float*)d_in[13];
    const float* r_w  = (const float*)d_in[14];
    const float* r_b  = (const float*)d_in[15];
    const float* m1_w = (const float*)d_in[16];
    const float* m1_b = (const float*)d_in[17];
    const float* m2_w = (const float*)d_in[18];
    const float* m2_b = (const float*)d_in[19];
    const float* m3_w = (const float*)d_in[20];
    const float* m3_b = (const float*)d_in[21];
    float* out = (float*)d_out;

    float *qs0, *ks0, *vpre, *qs, *ks, *vs, *kinv, *part, *ctx, *ma, *mb;
    __nv_bfloat16 *attsTh, *attsTl, *rw5h, *rw5l, *m1wh, *m1wl, *m3wh, *m3wl;
    __nv_bfloat16 *q1wh, *q1wl, *k1wh, *k1wl, *v1wh, *v1wl;
    cudaGetSymbolAddress((void**)&qs0,  g_qs0);
    cudaGetSymbolAddress((void**)&ks0,  g_ks0);
    cudaGetSymbolAddress((void**)&vpre, g_vpre);
    cudaGetSymbolAddress((void**)&qs,   g_qs);
    cudaGetSymbolAddress((void**)&ks,   g_ks);
    cudaGetSymbolAddress((void**)&vs,   g_vs);
    cudaGetSymbolAddress((void**)&kinv, g_kinv);
    cudaGetSymbolAddress((void**)&part, g_ctx_part);
    cudaGetSymbolAddress((void**)&ctx,  g_ctx);
    cudaGetSymbolAddress((void**)&ma,   g_ma);
    cudaGetSymbolAddress((void**)&mb,   g_mb);
    cudaGetSymbolAddress((void**)&attsTh, g_attsTh);
    cudaGetSymbolAddress((void**)&attsTl, g_attsTl);
    cudaGetSymbolAddress((void**)&rw5h, g_rw5h);
    cudaGetSymbolAddress((void**)&rw5l, g_rw5l);
    cudaGetSymbolAddress((void**)&m1wh, g_m1wh);
    cudaGetSymbolAddress((void**)&m1wl, g_m1wl);
    cudaGetSymbolAddress((void**)&m3wh, g_m3wh);
    cudaGetSymbolAddress((void**)&m3wl, g_m3wl);
    cudaGetSymbolAddress((void**)&q1wh, g_q1wh);
    cudaGetSymbolAddress((void**)&q1wl, g_q1wl);
    cudaGetSymbolAddress((void**)&k1wh, g_k1wh);
    cudaGetSymbolAddress((void**)&k1wl, g_k1wl);
    cudaGetSymbolAddress((void**)&v1wh, g_v1wh);
    cudaGetSymbolAddress((void**)&v1wl, g_v1wl);

    cudaFuncSetAttribute(k_gemm_mma<C2, C4, true, false>,
                         cudaFuncAttributeMaxDynamicSharedMemorySize, SM_GEMM_BYTES);
    cudaFuncSetAttribute(k_gemm_mma<C4, C2, false, true>,
                         cudaFuncAttributeMaxDynamicSharedMemorySize, SM_GEMM_BYTES);
    cudaFuncSetAttribute(k_conv5x5_mma,
                         cudaFuncAttributeMaxDynamicSharedMemorySize, SM_C5_BYTES);
    cudaFuncSetAttribute(k_conv1x1_mma<0>,
                         cudaFuncAttributeMaxDynamicSharedMemorySize, SM_QKV_BYTES);
    cudaFuncSetAttribute(k_conv1x1_mma<1>,
                         cudaFuncAttributeMaxDynamicSharedMemorySize, SM_QKV_BYTES);
    cudaFuncSetAttribute(k_conv1x1_mma<2>,
                         cudaFuncAttributeMaxDynamicSharedMemorySize, SM_QKV_BYTES);

    // weight prep (tiny)
    k_prep_rw5<<<800, 256>>>(r_w, rw5h, rw5l);
    k_prep_w<<<(C4*C2 + 255)/256, 256>>>(m1_w, m1wh, m1wl, C4*C2);
    k_prep_w<<<(C2*C4 + 255)/256, 256>>>(m3_w, m3wh, m3wl, C2*C4);
    k_prep_w<<<16, 256>>>(q1_w, q1wh, q1wl, Cc*Cc);
    k_prep_w<<<16, 256>>>(k1_w, k1wh, k1wl, Cc*Cc);
    k_prep_w<<<16, 256>>>(v1_w, v1wh, v1wl, Cc*Cc);

    // qkv 1x1 convs (HMMA)
    k_conv1x1_mma<0><<<dim3(NS/256,  Bq), 256, SM_QKV_BYTES>>>(x1, q1wh, q1wl, q1_b, qs0);
    k_conv1x1_mma<1><<<dim3(NS/256,  Bq), 256, SM_QKV_BYTES>>>(x1, k1wh, k1wl, k1_b, ks0);
    k_conv1x1_mma<2><<<dim3(NPIX/256, Bq), 256, SM_QKV_BYTES>>>(x2, v1wh, v1wl, v1_b, vpre);

    k_dw3x3_qk<<<(Bq*Cc*NS)/256, 256>>>(qs0, q2_w, q2_b, q1_b, qs, 0);
    k_dw3x3_qk<<<(Bq*Cc*NS)/256, 256>>>(ks0, k2_w, k2_b, k1_b, ks, 1);
    k_dw3x3_v <<<(Bq*Cc*NS)/256, 256>>>(vpre, v2_w, v2_b, vs);

    k_softmax_n_exp<<<Bq*Cc, 256>>>(ks, kinv);

    k_ctx_part<<<dim3(32, Bq*NHEAD), 512>>>(ks, vs, part);
    k_ctx_reduce<<<Bq*NHEAD, 256>>>(part, kinv, ctx);

    k_att<<<dim3(NS/128, Bq*NHEAD), 128>>>(qs, ctx, attsTh, attsTl);

    // conv5x5 v2: halo + pipelined A (HMMA split-bf16)
    k_conv5x5_mma<<<dim3(256, Bq*2), 256, SM_C5_BYTES>>>(attsTh, attsTl, rw5h, rw5l, r_b, out);

    // m1: 128 -> 256 + gelu (HMMA split-bf16)
    k_gemm_mma<C2, C4, true, false><<<dim3(Bq*(NPIX/128), C4/128), 256, SM_GEMM_BYTES>>>(out, m1wh, m1wl, m1_b, ma);
    k_dw3x3_gelu<<<(Bq*C4*NPIX)/256, 256>>>(ma, m2_w, m2_b, mb);
    // m3: 256 -> 128 + residual into out (HMMA split-bf16)
    k_gemm_mma<C4, C2, false, true><<<dim3(Bq*(NPIX/128), C2/128), 256, SM_GEMM_BYTES>>>(mb, m3wh, m3wl, m3_b, out);
}

// round 15
// speedup vs baseline: 3.2267x; 1.0150x over previous
#include <cuda_runtime.h>
#include <cuda_bf16.h>
#include <math.h>
#include <stdint.h>

#define Bq    4
#define Cc    64
#define Hh    256
#define Ww    256
#define W2    128
#define NPIX  65536   // Hh*Ww
#define NS    32768   // Hh*W2
#define NHEAD 4
#define Dd    16
#define C2    128
#define C4    256

// ---------------- scratch (device globals; no runtime allocation) ----------------
__device__ float g_qs0 [(size_t)Bq*Cc*NS];
__device__ float g_ks0 [(size_t)Bq*Cc*NS];
__device__ float g_vpre[(size_t)Bq*Cc*NPIX];
__device__ float g_qs  [(size_t)Bq*Cc*NS];
__device__ float g_ks  [(size_t)Bq*Cc*NS];
__device__ float g_vs  [(size_t)Bq*Cc*NS];
__device__ float g_kinv[Bq*Cc];
__device__ float g_ctx_part[16*32*16*16];
__device__ float g_ctx[16*256];
__device__ float g_ma[(size_t)Bq*C4*NPIX];
__device__ __nv_bfloat16 g_mbh[(size_t)Bq*C4*NPIX];
__device__ __nv_bfloat16 g_mbl[(size_t)Bq*C4*NPIX];
// bf16 hi/lo staging sources
__device__ __nv_bfloat16 g_attsTh[(size_t)Bq*NS*64];   // [b][n][ci]
__device__ __nv_bfloat16 g_attsTl[(size_t)Bq*NS*64];
__device__ __nv_bfloat16 g_rw5h[25*128*64];            // [tap][co][ci]
__device__ __nv_bfloat16 g_rw5l[25*128*64];
__device__ __nv_bfloat16 g_m1wh[C4*C2];
__device__ __nv_bfloat16 g_m1wl[C4*C2];
__device__ __nv_bfloat16 g_m3wh[C2*C4];
__device__ __nv_bfloat16 g_m3wl[C2*C4];
__device__ __nv_bfloat16 g_q1wh[Cc*Cc];
__device__ __nv_bfloat16 g_q1wl[Cc*Cc];
__device__ __nv_bfloat16 g_k1wh[Cc*Cc];
__device__ __nv_bfloat16 g_k1wl[Cc*Cc];
__device__ __nv_bfloat16 g_v1wh[Cc*Cc];
__device__ __nv_bfloat16 g_v1wl[Cc*Cc];

// tap tables: class 0 = (ky+kx) even (13 taps), class 1 = odd (12 taps)
__device__ __constant__ int8_t TAPS_E[13][2] = {
    {0,0},{0,2},{0,4},{1,1},{1,3},{2,0},{2,2},{2,4},{3,1},{3,3},{4,0},{4,2},{4,4}};
__device__ __constant__ int8_t TAPS_O[12][2] = {
    {0,1},{0,3},{1,0},{1,2},{1,4},{2,1},{2,3},{3,0},{3,2},{3,4},{4,1},{4,3}};

__device__ __forceinline__ float gelu_f(float x){
    return 0.5f * x * (1.0f + erff(x * 0.70710678118654752f));
}

// ================= mma.sync + cp.async helpers (baseline ISA) =================
__device__ __forceinline__ void ldsm4(uint32_t &r0, uint32_t &r1, uint32_t &r2, uint32_t &r3, uint32_t addr){
    asm volatile("ldmatrix.sync.aligned.m8n8.x4.shared.b16 {%0,%1,%2,%3}, [%4];"
                 : "=r"(r0), "=r"(r1), "=r"(r2), "=r"(r3) : "r"(addr));
}
__device__ __forceinline__ void mma16816(float* c, const uint32_t* a, uint32_t b0, uint32_t b1){
    asm volatile(
        "mma.sync.aligned.m16n8k16.row.col.f32.bf16.bf16.f32 "
        "{%0,%1,%2,%3}, {%4,%5,%6,%7}, {%8,%9}, {%0,%1,%2,%3};"
        : "+f"(c[0]), "+f"(c[1]), "+f"(c[2]), "+f"(c[3])
        : "r"(a[0]), "r"(a[1]), "r"(a[2]), "r"(a[3]), "r"(b0), "r"(b1));
}
__device__ __forceinline__ void cpasync16(uint32_t smem_addr, const void* gptr, int src_bytes){
    asm volatile("cp.async.cg.shared.global [%0], [%1], 16, %2;"
                 :: "r"(smem_addr), "l"(gptr), "r"(src_bytes) : "memory");
}
#define CPASYNC_WAIT_ALL() asm volatile("cp.async.commit_group;\ncp.async.wait_group 0;" ::: "memory")
#define CPASYNC_COMMIT()   asm volatile("cp.async.commit_group;" ::: "memory")
#define CPASYNC_WAIT1()    asm volatile("cp.async.wait_group 1;" ::: "memory")
#define CPASYNC_WAIT0()    asm volatile("cp.async.wait_group 0;" ::: "memory")

#define KC    64
#define PAD   72                              // bf16 per smem row (144B stride, 16B aligned)
#define PADB  144
#define SMEM_OP (128*PAD)
#define SM_GEMM_BYTES (4*SMEM_OP*2)           // Ah, Al, Bh, Bl

#define QKV_A_BYTES (64*PADB)                 // 9216
#define QKV_B_BYTES (256*PADB)                // 36864
#define SM_QKV_BYTES (2*QKV_A_BYTES + 2*QKV_B_BYTES)  // 92160

#define C5_A_BYTES (128*PADB)                 // 18432
#define C5_B_ROWS  216
#define C5_B_BYTES (C5_B_ROWS*PADB)           // 31104
#define SM_C5_BYTES (4*C5_A_BYTES + 2*C5_B_BYTES)   // 135936

// ================= merged prep kernel: one launch, all weights -> bf16 hi/lo =================
__device__ __forceinline__ void split_store(__nv_bfloat16* h, __nv_bfloat16* l, int i, float v){
    __nv_bfloat16 hh = __float2bfloat16(v);
    h[i] = hh;
    l[i] = __float2bfloat16(v - __bfloat162float(hh));
}
__global__ void k_prep_all(const float* __restrict__ rw, const float* __restrict__ m1w,
                           const float* __restrict__ m3w, const float* __restrict__ q1w,
                           const float* __restrict__ k1w, const float* __restrict__ v1w,
                           __nv_bfloat16* rw5h, __nv_bfloat16* rw5l,
                           __nv_bfloat16* m1wh, __nv_bfloat16* m1wl,
                           __nv_bfloat16* m3wh, __nv_bfloat16* m3wl,
                           __nv_bfloat16* q1wh, __nv_bfloat16* q1wl,
                           __nv_bfloat16* k1wh, __nv_bfloat16* k1wl,
                           __nv_bfloat16* v1wh, __nv_bfloat16* v1wl)
{
    int i = blockIdx.x*256 + threadIdx.x;
    if (i < 204800){                           // rw5: tap-major transpose
        int tap = i >> 13, rem = i & 8191;
        split_store(rw5h, rw5l, i, rw[(size_t)rem*25 + tap]);
        return;
    }
    int j = i - 204800;
    if (j < 32768){ split_store(m1wh, m1wl, j, m1w[j]); return; }
    j -= 32768;
    if (j < 32768){ split_store(m3wh, m3wl, j, m3w[j]); return; }
    j -= 32768;
    if (j < 4096){ split_store(q1wh, q1wl, j, q1w[j]); return; }
    j -= 4096;
    if (j < 4096){ split_store(k1wh, k1wl, j, k1w[j]); return; }
    j -= 4096;
    if (j < 4096){ split_store(v1wh, v1wl, j, v1w[j]); return; }
}

// ================= qkv 1x1 conv as HMMA GEMM: tile 64co x 256pos, K=64 =================
template<int MODE>
__global__ void __launch_bounds__(256)
k_conv1x1_mma(const float* __restrict__ x,
              const __nv_bfloat16* __restrict__ wh, const __nv_bfloat16* __restrict__ wl,
              const float* __restrict__ bias, float* __restrict__ outp)
{
    const int OSTR = (MODE == 2) ? NPIX : NS;
    extern __shared__ __align__(16) __nv_bfloat16 sm[];
    uint32_t aBaseH = (uint32_t)__cvta_generic_to_shared(sm);
    uint32_t aBaseL = aBaseH + QKV_A_BYTES;
    uint32_t bBaseH = aBaseH + 2*QKV_A_BYTES;
    uint32_t bBaseL = bBaseH + QKV_B_BYTES;
    __nv_bfloat16* Bh = sm + 2*QKV_A_BYTES/2;
    __nv_bfloat16* Bl = sm + (2*QKV_A_BYTES + QKV_B_BYTES)/2;

    int tid = threadIdx.x;
    int b = blockIdx.y;
    int posBase = blockIdx.x*256;
    int lane = tid & 31, warp = tid >> 5;
    int wco = (warp & 1)*32;
    int wpos = (warp >> 1)*64;

    for (int i = tid; i < 512; i += 256){
        int co = i >> 3, ch = i & 7;
        uint32_t d = co*PADB + ch*16;
        cpasync16(aBaseH + d, wh + co*64 + ch*8, 16);
        cpasync16(aBaseL + d, wl + co*64 + ch*8, 16);
    }
    if (MODE == 2){
        // contiguous: float4 = 4 positions per load
        for (int i = tid; i < 4096; i += 256){
            int ci = i >> 6, pb = i & 63;
            float4 v = *(const float4*)(x + ((size_t)(b*Cc + ci))*NPIX + posBase + pb*4);
            float arr[4] = {v.x, v.y, v.z, v.w};
            int p0 = pb*4;
#pragma unroll
            for (int e = 0; e < 4; e++){
                __nv_bfloat16 h = __float2bfloat16(arr[e]);
                Bh[(p0+e)*PAD + ci] = h;
                Bl[(p0+e)*PAD + ci] = __float2bfloat16(arr[e] - __bfloat162float(h));
            }
        }
    } else {
        // parity gather: aligned quad at 4*q4 holds kept pixels at offsets {o, o+2}
        int r0 = posBase >> 7;
        for (int i = tid; i < 8192; i += 256){
            int q4 = i & 63;
            int rl = (i >> 6) & 1;
            int ci = i >> 7;
            int r = r0 + rl;
            int o = (MODE == 1) ? (1 - (r & 1)) : (r & 1);
            float4 v = *(const float4*)(x + ((size_t)(b*Cc + ci))*NPIX + r*Ww + q4*4);
            float arr[4] = {v.x, v.y, v.z, v.w};
            float a0 = arr[o], a1 = arr[o+2];
            int p = rl*128 + 2*q4;
            __nv_bfloat16 h0 = __float2bfloat16(a0);
            __nv_bfloat16 h1 = __float2bfloat16(a1);
            Bh[p*PAD + ci]     = h0;
            Bl[p*PAD + ci]     = __float2bfloat16(a0 - __bfloat162float(h0));
            Bh[(p+1)*PAD + ci] = h1;
            Bl[(p+1)*PAD + ci] = __float2bfloat16(a1 - __bfloat162float(h1));
        }
    }
    CPASYNC_WAIT_ALL();
    __syncthreads();

    float acc[2][8][4];
#pragma unroll
    for (int mt = 0; mt < 2; mt++)
#pragma unroll
        for (int nt = 0; nt < 8; nt++)
#pragma unroll
            for (int r = 0; r < 4; r++) acc[mt][nt][r] = 0.f;

#pragma unroll
    for (int ks = 0; ks < 4; ks++){
        int k0 = ks*16;
        int g = lane >> 3;
        int rofs = (lane & 7) + ((g & 1) ? 8 : 0);
        int cofs = k0 + ((g >> 1) ? 8 : 0);
        uint32_t ah[2][4], al[2][4];
#pragma unroll
        for (int mt = 0; mt < 2; mt++){
            uint32_t off = ((wco + mt*16 + rofs)*PAD + cofs)*2;
            ldsm4(ah[mt][0], ah[mt][1], ah[mt][2], ah[mt][3], aBaseH + off);
            ldsm4(al[mt][0], al[mt][1], al[mt][2], al[mt][3], aBaseL + off);
        }
        uint32_t bh[4][4], bl[4][4];
#pragma unroll
        for (int ntp = 0; ntp < 4; ntp++){
            uint32_t off = ((wpos + ntp*16 + rofs)*PAD + cofs)*2;
            ldsm4(bh[ntp][0], bh[ntp][1], bh[ntp][2], bh[ntp][3], bBaseH + off);
            ldsm4(bl[ntp][0], bl[ntp][1], bl[ntp][2], bl[ntp][3], bBaseL + off);
        }
#pragma unroll
        for (int mt = 0; mt < 2; mt++){
#pragma unroll
            for (int ntp = 0; ntp < 4; ntp++){
#pragma unroll
                for (int sub = 0; sub < 2; sub++){
                    int nt = ntp*2 + sub;
                    uint32_t h0 = bh[ntp][sub], h1 = bh[ntp][sub+2];
                    uint32_t l0 = bl[ntp][sub], l1 = bl[ntp][sub+2];
                    mma16816(acc[mt][nt], ah[mt], h0, h1);
                    mma16816(acc[mt][nt], ah[mt], l0, l1);
                    mma16816(acc[mt][nt], al[mt], h0, h1);
                }
            }
        }
    }

    {
        int r = lane >> 2, cc = (lane & 3)*2;
#pragma unroll
        for (int mt = 0; mt < 2; mt++){
            int co0 = wco + mt*16 + r;
            float bv0 = bias[co0], bv8 = bias[co0 + 8];
            float* op0 = outp + ((size_t)(b*Cc + co0    ))*OSTR + posBase + wpos + cc;
            float* op8 = outp + ((size_t)(b*Cc + co0 + 8))*OSTR + posBase + wpos + cc;
#pragma unroll
            for (int nt = 0; nt < 8; nt++){
                float2 v0, v8;
                v0.x = acc[mt][nt][0] + bv0;  v0.y = acc[mt][nt][1] + bv0;
                v8.x = acc[mt][nt][2] + bv8;  v8.y = acc[mt][nt][3] + bv8;
                *(float2*)(op0 + nt*8) = v0;
                *(float2*)(op8 + nt*8) = v8;
            }
        }
    }
}

// ================= m1 GEMM (float input, float4 B-stage) =================
template<int CIN, int COUT, bool GELU, bool RES>
__global__ void __launch_bounds__(256, 1)
k_gemm_mma(const float* __restrict__ in,
           const __nv_bfloat16* __restrict__ wh, const __nv_bfloat16* __restrict__ wl,
           const float* __restrict__ bias, float* __restrict__ out)
{
    extern __shared__ __align__(16) __nv_bfloat16 sm[];
    __nv_bfloat16* Bh = sm + 2*SMEM_OP;
    __nv_bfloat16* Bl = sm + 3*SMEM_OP;
    uint32_t aBaseH = (uint32_t)__cvta_generic_to_shared(sm);
    uint32_t aBaseL = aBaseH + SMEM_OP*2;
    uint32_t bBaseH = aBaseH + 2*SMEM_OP*2;
    uint32_t bBaseL = aBaseH + 3*SMEM_OP*2;

    int tid = threadIdx.x;
    int b = blockIdx.x >> 9;
    int posBase = (blockIdx.x & 511)*128;
    int coBase = blockIdx.y*128;
    int lane = tid & 31, warp = tid >> 5;
    int wco = (warp & 3)*32;
    int wpos = (warp >> 2)*64;

    float acc[2][8][4];
#pragma unroll
    for (int mt = 0; mt < 2; mt++)
#pragma unroll
        for (int nt = 0; nt < 8; nt++)
#pragma unroll
            for (int r = 0; r < 4; r++) acc[mt][nt][r] = 0.f;

    const int KO = CIN/KC;
#pragma unroll 1
    for (int ko = 0; ko < KO; ko++){
        __syncthreads();
        for (int i = tid; i < 1024; i += 256){
            int co = i >> 3, ch = i & 7;
            uint32_t d = co*PADB + ch*16;
            cpasync16(aBaseH + d, wh + (size_t)(coBase + co)*CIN + ko*KC + ch*8, 16);
            cpasync16(aBaseL + d, wl + (size_t)(coBase + co)*CIN + ko*KC + ch*8, 16);
        }
        for (int i = tid; i < 2048; i += 256){
            int ci = i >> 5, pb = i & 31;
            float4 v = *(const float4*)(in + ((size_t)(b*CIN + ko*KC + ci))*NPIX + posBase + pb*4);
            float arr[4] = {v.x, v.y, v.z, v.w};
            int p0 = pb*4;
#pragma unroll
            for (int e = 0; e < 4; e++){
                __nv_bfloat16 h = __float2bfloat16(arr[e]);
                Bh[(p0+e)*PAD + ci] = h;
                Bl[(p0+e)*PAD + ci] = __float2bfloat16(arr[e] - __bfloat162float(h));
            }
        }
        CPASYNC_WAIT_ALL();
        __syncthreads();

#pragma unroll
        for (int ks = 0; ks < KC/16; ks++){
            int k0 = ks*16;
            int g = lane >> 3;
            int rofs = (lane & 7) + ((g & 1) ? 8 : 0);
            int cofs = k0 + ((g >> 1) ? 8 : 0);
            uint32_t ah[2][4], al[2][4];
#pragma unroll
            for (int mt = 0; mt < 2; mt++){
                uint32_t off = ((wco + mt*16 + rofs)*PAD + cofs)*2;
                ldsm4(ah[mt][0], ah[mt][1], ah[mt][2], ah[mt][3], aBaseH + off);
                ldsm4(al[mt][0], al[mt][1], al[mt][2], al[mt][3], aBaseL + off);
            }
            uint32_t bh[4][4], bl[4][4];
#pragma unroll
            for (int ntp = 0; ntp < 4; ntp++){
                uint32_t off = ((wpos + ntp*16 + rofs)*PAD + cofs)*2;
                ldsm4(bh[ntp][0], bh[ntp][1], bh[ntp][2], bh[ntp][3], bBaseH + off);
                ldsm4(bl[ntp][0], bl[ntp][1], bl[ntp][2], bl[ntp][3], bBaseL + off);
            }
#pragma unroll
            for (int mt = 0; mt < 2; mt++){
#pragma unroll
                for (int ntp = 0; ntp < 4; ntp++){
#pragma unroll
                    for (int sub = 0; sub < 2; sub++){
                        int nt = ntp*2 + sub;
                        uint32_t h0 = bh[ntp][sub], h1 = bh[ntp][sub+2];
                        uint32_t l0 = bl[ntp][sub], l1 = bl[ntp][sub+2];
                        mma16816(acc[mt][nt], ah[mt], h0, h1);
                        mma16816(acc[mt][nt], ah[mt], l0, l1);
                        mma16816(acc[mt][nt], al[mt], h0, h1);
                    }
                }
            }
        }
    }

    {
        int r = lane >> 2, cc = (lane & 3)*2;
#pragma unroll
        for (int mt = 0; mt < 2; mt++){
            int co0 = coBase + wco + mt*16 + r;
            float bv0 = bias[co0], bv8 = bias[co0 + 8];
            float* op0 = out + ((size_t)(b*COUT + co0    ))*NPIX + posBase + wpos + cc;
            float* op8 = out + ((size_t)(b*COUT + co0 + 8))*NPIX + posBase + wpos + cc;
#pragma unroll
            for (int nt = 0; nt < 8; nt++){
                float2 v0, v8;
                v0.x = acc[mt][nt][0] + bv0;  v0.y = acc[mt][nt][1] + bv0;
                v8.x = acc[mt][nt][2] + bv8;  v8.y = acc[mt][nt][3] + bv8;
                if (GELU){
                    v0.x = gelu_f(v0.x); v0.y = gelu_f(v0.y);
                    v8.x = gelu_f(v8.x); v8.y = gelu_f(v8.y);
                }
                if (RES){
                    float2 o0 = *(const float2*)(op0 + nt*8);
                    float2 o8 = *(const float2*)(op8 + nt*8);
                    v0.x += o0.x; v0.y += o0.y;
                    v8.x += o8.x; v8.y += o8.y;
                }
                *(float2*)(op0 + nt*8) = v0;
                *(float2*)(op8 + nt*8) = v8;
            }
        }
    }
}

// ================= m3 GEMM (bf16 h/l input, no conversions in B-stage) =================
__global__ void __launch_bounds__(256, 1)
k_gemm_mma_bf16in(const __nv_bfloat16* __restrict__ inh, const __nv_bfloat16* __restrict__ inl,
                  const __nv_bfloat16* __restrict__ wh, const __nv_bfloat16* __restrict__ wl,
                  const float* __restrict__ bias, float* __restrict__ out)
{
    const int CIN = C4, COUT = C2;
    extern __shared__ __align__(16) __nv_bfloat16 sm[];
    __nv_bfloat16* Bh = sm + 2*SMEM_OP;
    __nv_bfloat16* Bl = sm + 3*SMEM_OP;
    uint32_t aBaseH = (uint32_t)__cvta_generic_to_shared(sm);
    uint32_t aBaseL = aBaseH + SMEM_OP*2;
    uint32_t bBaseH = aBaseH + 2*SMEM_OP*2;
    uint32_t bBaseL = aBaseH + 3*SMEM_OP*2;

    int tid = threadIdx.x;
    int b = blockIdx.x >> 9;
    int posBase = (blockIdx.x & 511)*128;
    int coBase = blockIdx.y*128;
    int lane = tid & 31, warp = tid >> 5;
    int wco = (warp & 3)*32;
    int wpos = (warp >> 2)*64;

    float acc[2][8][4];
#pragma unroll
    for (int mt = 0; mt < 2; mt++)
#pragma unroll
        for (int nt = 0; nt < 8; nt++)
#pragma unroll
            for (int r = 0; r < 4; r++) acc[mt][nt][r] = 0.f;

    const int KO = CIN/KC;
#pragma unroll 1
    for (int ko = 0; ko < KO; ko++){
        __syncthreads();
        for (int i = tid; i < 1024; i += 256){
            int co = i >> 3, ch = i & 7;
            uint32_t d = co*PADB + ch*16;
            cpasync16(aBaseH + d, wh + (size_t)(coBase + co)*CIN + ko*KC + ch*8, 16);
            cpasync16(aBaseL + d, wl + (size_t)(coBase + co)*CIN + ko*KC + ch*8, 16);
        }
        // B-stage: uint4 loads of prepped bf16, scalar transpose stores, zero cvt
        for (int i = tid; i < 1024; i += 256){
            int ci = i >> 4, pc8 = i & 15;
            size_t goff = ((size_t)(b*CIN + ko*KC + ci))*NPIX + posBase + pc8*8;
            union { uint4 u; __nv_bfloat16 e[8]; } vh, vl;
            vh.u = *(const uint4*)(inh + goff);
            vl.u = *(const uint4*)(inl + goff);
            int p0 = pc8*8;
#pragma unroll
            for (int e = 0; e < 8; e++){
                Bh[(p0+e)*PAD + ci] = vh.e[e];
                Bl[(p0+e)*PAD + ci] = vl.e[e];
            }
        }
        CPASYNC_WAIT_ALL();
        __syncthreads();

#pragma unroll
        for (int ks = 0; ks < KC/16; ks++){
            int k0 = ks*16;
            int g = lane >> 3;
            int rofs = (lane & 7) + ((g & 1) ? 8 : 0);
            int cofs = k0 + ((g >> 1) ? 8 : 0);
            uint32_t ah[2][4], al[2][4];
#pragma unroll
            for (int mt = 0; mt < 2; mt++){
                uint32_t off = ((wco + mt*16 + rofs)*PAD + cofs)*2;
                ldsm4(ah[mt][0], ah[mt][1], ah[mt][2], ah[mt][3], aBaseH + off);
                ldsm4(al[mt][0], al[mt][1], al[mt][2], al[mt][3], aBaseL + off);
            }
            uint32_t bh[4][4], bl[4][4];
#pragma unroll
            for (int ntp = 0; ntp < 4; ntp++){
                uint32_t off = ((wpos + ntp*16 + rofs)*PAD + cofs)*2;
                ldsm4(bh[ntp][0], bh[ntp][1], bh[ntp][2], bh[ntp][3], bBaseH + off);
                ldsm4(bl[ntp][0], bl[ntp][1], bl[ntp][2], bl[ntp][3], bBaseL + off);
            }
#pragma unroll
            for (int mt = 0; mt < 2; mt++){
#pragma unroll
                for (int ntp = 0; ntp < 4; ntp++){
#pragma unroll
                    for (int sub = 0; sub < 2; sub++){
                        int nt = ntp*2 + sub;
                        uint32_t h0 = bh[ntp][sub], h1 = bh[ntp][sub+2];
                        uint32_t l0 = bl[ntp][sub], l1 = bl[ntp][sub+2];
                        mma16816(acc[mt][nt], ah[mt], h0, h1);
                        mma16816(acc[mt][nt], ah[mt], l0, l1);
                        mma16816(acc[mt][nt], al[mt], h0, h1);
                    }
                }
            }
        }
    }

    {   // epilogue: residual add into out
        int r = lane >> 2, cc = (lane & 3)*2;
#pragma unroll
        for (int mt = 0; mt < 2; mt++){
            int co0 = coBase + wco + mt*16 + r;
            float bv0 = bias[co0], bv8 = bias[co0 + 8];
            float* op0 = out + ((size_t)(b*COUT + co0    ))*NPIX + posBase + wpos + cc;
            float* op8 = out + ((size_t)(b*COUT + co0 + 8))*NPIX + posBase + wpos + cc;
#pragma unroll
            for (int nt = 0; nt < 8; nt++){
                float2 v0, v8;
                v0.x = acc[mt][nt][0] + bv0;  v0.y = acc[mt][nt][1] + bv0;
                v8.x = acc[mt][nt][2] + bv8;  v8.y = acc[mt][nt][3] + bv8;
                float2 o0 = *(const float2*)(op0 + nt*8);
                float2 o8 = *(const float2*)(op8 + nt*8);
                v0.x += o0.x; v0.y += o0.y;
                v8.x += o8.x; v8.y += o8.y;
                *(float2*)(op0 + nt*8) = v0;
                *(float2*)(op8 + nt*8) = v8;
            }
        }
    }
}

// ================= conv5x5 v2: halo B staged once, A double-buffered pipeline =================
__global__ void __launch_bounds__(256, 1)
k_conv5x5_mma(const __nv_bfloat16* __restrict__ attsTh, const __nv_bfloat16* __restrict__ attsTl,
              const __nv_bfloat16* __restrict__ rw5h, const __nv_bfloat16* __restrict__ rw5l,
              const float* __restrict__ rb, float* __restrict__ out)
{
    extern __shared__ __align__(16) __nv_bfloat16 sm[];
    uint32_t smb = (uint32_t)__cvta_generic_to_shared(sm);
    uint32_t aB0 = smb;
    uint32_t aB1 = smb + 2*C5_A_BYTES;
    uint32_t bBaseH = smb + 4*C5_A_BYTES;
    uint32_t bBaseL = bBaseH + C5_B_BYTES;

    int tid = threadIdx.x;
    int tx = blockIdx.x;
    int z = blockIdx.y;
    int b = z >> 1, pc = z & 1;
    int jBase = (tx & 7)*16;
    int yBase = (tx >> 3)*8;
    int NT = pc ? 12 : 13;
    int lane = tid & 31, warp = tid >> 5;
    int wco = (warp & 3)*32;
    int wpos = (warp >> 2)*64;

    for (int i = tid; i < C5_B_ROWS*8; i += 256){
        int row = i >> 3, ch = i & 7;
        int hy = row/18, hj = row - hy*18;
        int yy = yBase - 2 + hy;
        int jj = jBase - 1 + hj;
        bool inb = ((unsigned)yy < Hh) && ((unsigned)jj < W2);
        size_t go = inb ? (((size_t)b*NS + yy*W2 + jj)*64 + ch*8) : 0;
        int nb = inb ? 16 : 0;
        uint32_t d = row*PADB + ch*16;
        cpasync16(bBaseH + d, attsTh + go, nb);
        cpasync16(bBaseL + d, attsTl + go, nb);
    }
    {
        int tap0 = pc ? (TAPS_O[0][0]*5 + TAPS_O[0][1]) : (TAPS_E[0][0]*5 + TAPS_E[0][1]);
        const __nv_bfloat16* ah = rw5h + tap0*8192;
        const __nv_bfloat16* al = rw5l + tap0*8192;
        for (int i = tid; i < 1024; i += 256){
            int co = i >> 3, ch = i & 7;
            uint32_t d = co*PADB + ch*16;
            cpasync16(aB0 + d,              ah + co*64 + ch*8, 16);
            cpasync16(aB0 + C5_A_BYTES + d, al + co*64 + ch*8, 16);
        }
    }
    CPASYNC_COMMIT();

    int g = lane >> 3;
    int rofs = (lane & 7) + ((g & 1) ? 8 : 0);
    int cofsk = (g >> 1) ? 8 : 0;
    int pyl[4], pjx[4], spar[4];
#pragma unroll
    for (int ntp = 0; ntp < 4; ntp++){
        int p = wpos + ntp*16 + rofs;
        pyl[ntp] = p >> 4;
        pjx[ntp] = p & 15;
        spar[ntp] = (pyl[ntp] & 1) ^ pc;
    }

    float acc[2][8][4];
#pragma unroll
    for (int mt = 0; mt < 2; mt++)
#pragma unroll
        for (int nt = 0; nt < 8; nt++)
#pragma unroll
            for (int r = 0; r < 4; r++) acc[mt][nt][r] = 0.f;

#pragma unroll 1
    for (int t = 0; t < NT; t++){
        int ky = pc ? TAPS_O[t][0] : TAPS_E[t][0];
        int kx = pc ? TAPS_O[t][1] : TAPS_E[t][1];
        if (t + 1 < NT){
            __syncthreads();
            int tapn = pc ? (TAPS_O[t+1][0]*5 + TAPS_O[t+1][1]) : (TAPS_E[t+1][0]*5 + TAPS_E[t+1][1]);
            uint32_t aDst = ((t+1) & 1) ? aB1 : aB0;
            const __nv_bfloat16* ah = rw5h + tapn*8192;
            const __nv_bfloat16* al = rw5l + tapn*8192;
            for (int i = tid; i < 1024; i += 256){
                int co = i >> 3, ch = i & 7;
                uint32_t d = co*PADB + ch*16;
                cpasync16(aDst + d,              ah + co*64 + ch*8, 16);
                cpasync16(aDst + C5_A_BYTES + d, al + co*64 + ch*8, 16);
            }
            CPASYNC_COMMIT();
            CPASYNC_WAIT1();
        } else {
            CPASYNC_WAIT0();
        }
        __syncthreads();

        uint32_t aH = (t & 1) ? aB1 : aB0;
        uint32_t aL = aH + C5_A_BYTES;
        uint32_t bro[4];
#pragma unroll
        for (int ntp = 0; ntp < 4; ntp++){
            int shift = (spar[ntp] + kx - 2) >> 1;
            int hr = (pyl[ntp] + ky)*18 + pjx[ntp] + 1 + shift;
            bro[ntp] = (uint32_t)hr*PADB;
        }

#pragma unroll
        for (int ks = 0; ks < 4; ks++){
            int cofs = ks*16 + cofsk;
            uint32_t ah[2][4], al[2][4];
#pragma unroll
            for (int mt = 0; mt < 2; mt++){
                uint32_t off = ((wco + mt*16 + rofs)*PAD + cofs)*2;
                ldsm4(ah[mt][0], ah[mt][1], ah[mt][2], ah[mt][3], aH + off);
                ldsm4(al[mt][0], al[mt][1], al[mt][2], al[mt][3], aL + off);
            }
            uint32_t bh[4][4], bl[4][4];
#pragma unroll
            for (int ntp = 0; ntp < 4; ntp++){
                uint32_t off = bro[ntp] + (uint32_t)cofs*2;
                ldsm4(bh[ntp][0], bh[ntp][1], bh[ntp][2], bh[ntp][3], bBaseH + off);
                ldsm4(bl[ntp][0], bl[ntp][1], bl[ntp][2], bl[ntp][3], bBaseL + off);
            }
#pragma unroll
            for (int mt = 0; mt < 2; mt++){
#pragma unroll
                for (int ntp = 0; ntp < 4; ntp++){
#pragma unroll
                    for (int sub = 0; sub < 2; sub++){
                        int nt = ntp*2 + sub;
                        uint32_t h0 = bh[ntp][sub], h1 = bh[ntp][sub+2];
                        uint32_t l0 = bl[ntp][sub], l1 = bl[ntp][sub+2];
                        mma16816(acc[mt][nt], ah[mt], h0, h1);
                        mma16816(acc[mt][nt], ah[mt], l0, l1);
                        mma16816(acc[mt][nt], al[mt], h0, h1);
                    }
                }
            }
        }
    }

    {
        int r = lane >> 2, cc = (lane & 3)*2;
#pragma unroll
        for (int mt = 0; mt < 2; mt++){
            int co0 = wco + mt*16 + r;
            float bv0 = rb[co0], bv8 = rb[co0 + 8];
#pragma unroll
            for (int nt = 0; nt < 8; nt++){
                int p = wpos + nt*8 + cc;
                int yl = p >> 4, jx = p & 15;
                int y = yBase + yl;
                int s = (y & 1) ^ pc;
                int x0 = 2*(jBase + jx) + s;
                size_t r0 = ((size_t)(b*C2 + co0    ))*NPIX + y*Ww + x0;
                size_t r8 = ((size_t)(b*C2 + co0 + 8))*NPIX + y*Ww + x0;
                out[r0]     = acc[mt][nt][0] + bv0;
                out[r0 + 2] = acc[mt][nt][1] + bv0;
                out[r8]     = acc[mt][nt][2] + bv8;
                out[r8 + 2] = acc[mt][nt][3] + bv8;
            }
        }
    }
}

// ---------------- K2a: depthwise 3x3 for q/k on squeezed pre-buffer ----------------
__global__ void k_dw3x3_qk(const float* __restrict__ in, const float* __restrict__ w,
                           const float* __restrict__ bias, const float* __restrict__ pbias,
                           float* __restrict__ out, int anchorSel)
{
    int idx = blockIdx.x*256 + threadIdx.x;
    int j = idx & (W2-1);
    int r = (idx >> 7) & (Hh-1);
    int c = (idx >> 15) & (Cc-1);
    int o = anchorSel ? (1 - (r & 1)) : (r & 1);
    int col = 2*j + o;
    const float* ip = in + (size_t)(idx >> 15) * NS;
    const float* wp = w + c*9;

    float s = bias[c] + wp[4]*ip[r*W2 + j];
    float cb = pbias[c];
    float bw = 0.f;
    if (r > 0)       bw += wp[1];
    if (r < Hh-1)    bw += wp[7];
    if (col > 0)     bw += wp[3];
    if (col < Ww-1)  bw += wp[5];
    s += cb * bw;
    int jm = j - 1 + o, jp = j + o;
    if (r > 0){
        const float* rp = ip + (r-1)*W2;
        if ((unsigned)jm < W2) s += wp[0]*rp[jm];
        if ((unsigned)jp < W2) s += wp[2]*rp[jp];
    }
    if (r < Hh-1){
        const float* rp = ip + (r+1)*W2;
        if ((unsigned)jm < W2) s += wp[6]*rp[jm];
        if ((unsigned)jp < W2) s += wp[8]*rp[jp];
    }
    out[idx] = s;
}

// ---------------- K2b: depthwise 3x3 for v ----------------
__global__ void k_dw3x3_v(const float* __restrict__ in, const float* __restrict__ w,
                          const float* __restrict__ bias, float* __restrict__ out)
{
    int idx = blockIdx.x*256 + threadIdx.x;
    int j = idx & (W2-1);
    int r = (idx >> 7) & (Hh-1);
    int c = (idx >> 15) & (Cc-1);
    int col = 2*j + (1 - (r & 1));
    const float* ip = in + (size_t)(idx >> 15) * NPIX;
    const float* wp = w + c*9;
    float s = bias[c];
#pragma unroll
    for (int dy = -1; dy <= 1; dy++){
        int rr = r + dy;
        if ((unsigned)rr < Hh){
#pragma unroll
            for (int dx = -1; dx <= 1; dx++){
                int cc = col + dx;
                if ((unsigned)cc < Ww)
                    s += wp[(dy+1)*3 + (dx+1)] * ip[rr*Ww + cc];
            }
        }
    }
    out[idx] = s;
}

// ---------------- K4: k softmax (max + exp; normalization deferred) ----------------
__global__ void k_softmax_n_exp(float* __restrict__ kk, float* __restrict__ kinv)
{
    int row = blockIdx.x;
    float* p = kk + (size_t)row*NS;
    int tid = threadIdx.x;
    __shared__ float red[256];
    float mx = -1e30f;
    for (int i = tid; i < NS; i += 256) mx = fmaxf(mx, p[i]);
    red[tid] = mx; __syncthreads();
    for (int s = 128; s > 0; s >>= 1){ if (tid < s) red[tid] = fmaxf(red[tid], red[tid+s]); __syncthreads(); }
    mx = red[0]; __syncthreads();
    float sum = 0.f;
    for (int i = tid; i < NS; i += 256){
        float e = __expf(p[i]-mx);
        p[i] = e;
        sum += e;
    }
    red[tid] = sum; __syncthreads();
    for (int s = 128; s > 0; s >>= 1){ if (tid < s) red[tid] += red[tid+s]; __syncthreads(); }
    if (tid == 0) kinv[row] = 1.f/red[0];
}

// ---------------- K5: ctx partials ----------------
__global__ void k_ctx_part(const float* __restrict__ ks, const float* __restrict__ vs,
                           float* __restrict__ part)
{
    int bh = blockIdx.y;
    int chunk = blockIdx.x;
    int e    = threadIdx.x >> 5;
    int lane = threadIdx.x & 31;
    int b = bh >> 2, hd = bh & 3;
    const float* kp = ks + ((size_t)(b*Cc + hd*Dd))*NS;
    const float* vp = vs + ((size_t)(b*Cc + hd*Dd + e))*NS;
    float acc[16];
#pragma unroll
    for (int d = 0; d < 16; d++) acc[d] = 0.f;
    int n0 = chunk*1024;
    for (int n = n0 + lane; n < n0 + 1024; n += 32){
        float vv = vp[n];
#pragma unroll
        for (int d = 0; d < 16; d++) acc[d] += kp[(size_t)d*NS + n]*vv;
    }
#pragma unroll
    for (int d = 0; d < 16; d++){
#pragma unroll
        for (int off = 16; off; off >>= 1) acc[d] += __shfl_xor_sync(0xffffffffu, acc[d], off);
    }
    if (lane == 0){
#pragma unroll
        for (int d = 0; d < 16; d++)
            part[(((size_t)bh*32 + chunk)*16 + e)*16 + d] = acc[d];
    }
}

__global__ void k_ctx_reduce(const float* __restrict__ part, const float* __restrict__ kinv,
                             float* __restrict__ ctx)
{
    int bh = blockIdx.x, t = threadIdx.x;
    int e = t >> 4, d = t & 15;
    float s = 0.f;
    for (int ch = 0; ch < 32; ch++) s += part[(((size_t)bh*32 + ch)*16 + e)*16 + d];
    int b = bh >> 2, hd = bh & 3;
    s *= kinv[b*Cc + hd*Dd + d];
    ctx[bh*256 + d*16 + e] = s;
}

// ---------------- K6: att (q softmax fused), writes transposed bf16 hi/lo ----------------
__global__ void k_att(const float* __restrict__ q, const float* __restrict__ ctx,
                      __nv_bfloat16* __restrict__ attsTh, __nv_bfloat16* __restrict__ attsTl)
{
    int bh = blockIdx.y;
    __shared__ float csm[256];
    for (int i = threadIdx.x; i < 256; i += 128) csm[i] = ctx[bh*256 + i];
    __syncthreads();
    int n = blockIdx.x*128 + threadIdx.x;
    int b = bh >> 2, hd = bh & 3;
    const float* qp = q + ((size_t)(b*Cc + hd*Dd))*NS + n;
    float qv[16];
    float mx = -1e30f;
#pragma unroll
    for (int d = 0; d < 16; d++){ qv[d] = qp[(size_t)d*NS]; mx = fmaxf(mx, qv[d]); }
    float ssum = 0.f;
#pragma unroll
    for (int d = 0; d < 16; d++){ qv[d] = __expf(qv[d]-mx); ssum += qv[d]; }
    float inv = 1.f/ssum;
    float o[16];
#pragma unroll
    for (int e = 0; e < 16; e++) o[e] = 0.f;
#pragma unroll
    for (int d = 0; d < 16; d++){
        float qd = qv[d]*inv;
#pragma unroll
        for (int e = 0; e < 16; e++) o[e] += csm[d*16 + e]*qd;
    }
    size_t base = ((size_t)b*NS + n)*64 + hd*16;
#pragma unroll
    for (int e = 0; e < 16; e++){
        __nv_bfloat16 h = __float2bfloat16(o[e]);
        attsTh[base + e] = h;
        attsTl[base + e] = __float2bfloat16(o[e] - __bfloat162float(h));
    }
}

// ---------------- K9: m2 depthwise 3x3 + gelu, float4-vectorized, writes bf16 h/l ----------------
__global__ void k_dw3x3_gelu4(const float* __restrict__ in, const float* __restrict__ w,
                              const float* __restrict__ bias,
                              __nv_bfloat16* __restrict__ outh, __nv_bfloat16* __restrict__ outl)
{
    int idx = blockIdx.x*256 + threadIdx.x;        // over B*C4*NPIX/4 = 2^24
    int xq = idx & 63;
    int y  = (idx >> 6) & 255;
    int c  = (idx >> 14) & 255;
    const float* ip = in + (size_t)(idx >> 14) * NPIX;
    const float* wp = w + c*9;
    int x0 = xq*4;

    float bv = bias[c];
    float s0 = bv, s1 = bv, s2 = bv, s3 = bv;
#pragma unroll
    for (int dy = -1; dy <= 1; dy++){
        int rr = y + dy;
        if ((unsigned)rr < Hh){
            const float* rp = ip + rr*Ww;
            float4 m = *(const float4*)(rp + x0);
            float lft = (x0 > 0)      ? rp[x0-1] : 0.f;
            float rgt = (x0+4 < Ww)   ? rp[x0+4] : 0.f;
            float w0 = wp[(dy+1)*3+0], w1 = wp[(dy+1)*3+1], w2 = wp[(dy+1)*3+2];
            s0 += w0*lft + w1*m.x + w2*m.y;
            s1 += w0*m.x + w1*m.y + w2*m.z;
            s2 += w0*m.y + w1*m.z + w2*m.w;
            s3 += w0*m.z + w1*m.w + w2*rgt;
        }
    }
    s0 = gelu_f(s0); s1 = gelu_f(s1); s2 = gelu_f(s2); s3 = gelu_f(s3);
    union { __nv_bfloat16 b[4]; uint2 u; } uh, ul;
    float ss[4] = {s0, s1, s2, s3};
#pragma unroll
    for (int e = 0; e < 4; e++){
        __nv_bfloat16 h = __float2bfloat16(ss[e]);
        uh.b[e] = h;
        ul.b[e] = __float2bfloat16(ss[e] - __bfloat162float(h));
    }
    size_t o = (size_t)(idx >> 14)*NPIX + y*Ww + x0;
    *(uint2*)(outh + o) = uh.u;
    *(uint2*)(outl + o) = ul.u;
}

// ---------------- launch ----------------
extern "C" void kernel_launch(void* const* d_in, const int* in_sizes, int n_in,
                              void* d_out, int out_size)
{
    (void)in_sizes; (void)n_in; (void)out_size;
    const float* x1   = (const float*)d_in[0];
    const float* x2   = (const float*)d_in[1];
    const float* q1_w = (const float*)d_in[2];
    const float* q1_b = (const float*)d_in[3];
    const float* q2_w = (const float*)d_in[4];
    const float* q2_b = (const float*)d_in[5];
    const float* k1_w = (const float*)d_in[6];
    const float* k1_b = (const float*)d_in[7];
    const float* k2_w = (const float*)d_in[8];
    const float* k2_b = (const float*)d_in[9];
    const float* v1_w = (const float*)d_in[10];
    const float* v1_b = (const float*)d_in[11];
    const float* v2_w = (const float*)d_in[12];
    const float* v2_b = (const float*)d_in[13];
    const float* r_w  = (const float*)d_in[14];
    const float* r_b  = (const float*)d_in[15];
    const float* m1_w = (const float*)d_in[16];
    const float* m1_b = (const float*)d_in[17];
    const float* m2_w = (const float*)d_in[18];
    const float* m2_b = (const float*)d_in[19];
    const float* m3_w = (const float*)d_in[20];
    const float* m3_b = (const float*)d_in[21];
    float* out = (float*)d_out;

    float *qs0, *ks0, *vpre, *qs, *ks, *vs, *kinv, *part, *ctx, *ma;
    __nv_bfloat16 *mbh, *mbl;
    __nv_bfloat16 *attsTh, *attsTl, *rw5h, *rw5l, *m1wh, *m1wl, *m3wh, *m3wl;
    __nv_bfloat16 *q1wh, *q1wl, *k1wh, *k1wl, *v1wh, *v1wl;
    cudaGetSymbolAddress((void**)&qs0,  g_qs0);
    cudaGetSymbolAddress((void**)&ks0,  g_ks0);
    cudaGetSymbolAddress((void**)&vpre, g_vpre);
    cudaGetSymbolAddress((void**)&qs,   g_qs);
    cudaGetSymbolAddress((void**)&ks,   g_ks);
    cudaGetSymbolAddress((void**)&vs,   g_vs);
    cudaGetSymbolAddress((void**)&kinv, g_kinv);
    cudaGetSymbolAddress((void**)&part, g_ctx_part);
    cudaGetSymbolAddress((void**)&ctx,  g_ctx);
    cudaGetSymbolAddress((void**)&ma,   g_ma);
    cudaGetSymbolAddress((void**)&mbh,  g_mbh);
    cudaGetSymbolAddress((void**)&mbl,  g_mbl);
    cudaGetSymbolAddress((void**)&attsTh, g_attsTh);
    cudaGetSymbolAddress((void**)&attsTl, g_attsTl);
    cudaGetSymbolAddress((void**)&rw5h, g_rw5h);
    cudaGetSymbolAddress((void**)&rw5l, g_rw5l);
    cudaGetSymbolAddress((void**)&m1wh, g_m1wh);
    cudaGetSymbolAddress((void**)&m1wl, g_m1wl);
    cudaGetSymbolAddress((void**)&m3wh, g_m3wh);
    cudaGetSymbolAddress((void**)&m3wl, g_m3wl);
    cudaGetSymbolAddress((void**)&q1wh, g_q1wh);
    cudaGetSymbolAddress((void**)&q1wl, g_q1wl);
    cudaGetSymbolAddress((void**)&k1wh, g_k1wh);
    cudaGetSymbolAddress((void**)&k1wl, g_k1wl);
    cudaGetSymbolAddress((void**)&v1wh, g_v1wh);
    cudaGetSymbolAddress((void**)&v1wl, g_v1wl);

    cudaFuncSetAttribute(k_gemm_mma<C2, C4, true, false>,
                         cudaFuncAttributeMaxDynamicSharedMemorySize, SM_GEMM_BYTES);
    cudaFuncSetAttribute(k_gemm_mma_bf16in,
                         cudaFuncAttributeMaxDynamicSharedMemorySize, SM_GEMM_BYTES);
    cudaFuncSetAttribute(k_conv5x5_mma,
                         cudaFuncAttributeMaxDynamicSharedMemorySize, SM_C5_BYTES);
    cudaFuncSetAttribute(k_conv1x1_mma<0>,
                         cudaFuncAttributeMaxDynamicSharedMemorySize, SM_QKV_BYTES);
    cudaFuncSetAttribute(k_conv1x1_mma<1>,
                         cudaFuncAttributeMaxDynamicSharedMemorySize, SM_QKV_BYTES);
    cudaFuncSetAttribute(k_conv1x1_mma<2>,
                         cudaFuncAttributeMaxDynamicSharedMemorySize, SM_QKV_BYTES);

    // single merged weight prep
    k_prep_all<<<1104, 256>>>(r_w, m1_w, m3_w, q1_w, k1_w, v1_w,
                              rw5h, rw5l, m1wh, m1wl, m3wh, m3wl,
                              q1wh, q1wl, k1wh, k1wl, v1wh, v1wl);

    // qkv 1x1 convs (HMMA)
    k_conv1x1_mma<0><<<dim3(NS/256,  Bq), 256, SM_QKV_BYTES>>>(x1, q1wh, q1wl, q1_b, qs0);
    k_conv1x1_mma<1><<<dim3(NS/256,  Bq), 256, SM_QKV_BYTES>>>(x1, k1wh, k1wl, k1_b, ks0);
    k_conv1x1_mma<2><<<dim3(NPIX/256, Bq), 256, SM_QKV_BYTES>>>(x2, v1wh, v1wl, v1_b, vpre);

    k_dw3x3_qk<<<(Bq*Cc*NS)/256, 256>>>(qs0, q2_w, q2_b, q1_b, qs, 0);
    k_dw3x3_qk<<<(Bq*Cc*NS)/256, 256>>>(ks0, k2_w, k2_b, k1_b, ks, 1);
    k_dw3x3_v <<<(Bq*Cc*NS)/256, 256>>>(vpre, v2_w, v2_b, vs);

    k_softmax_n_exp<<<Bq*Cc, 256>>>(ks, kinv);

    k_ctx_part<<<dim3(32, Bq*NHEAD), 512>>>(ks, vs, part);
    k_ctx_reduce<<<Bq*NHEAD, 256>>>(part, kinv, ctx);

    k_att<<<dim3(NS/128, Bq*NHEAD), 128>>>(qs, ctx, attsTh, attsTl);

    // conv5x5: halo + pipelined A (HMMA split-bf16)
    k_conv5x5_mma<<<dim3(256, Bq*2), 256, SM_C5_BYTES>>>(attsTh, attsTl, rw5h, rw5l, r_b, out);

    // m1: 128 -> 256 + gelu (HMMA split-bf16, float4 staging)
    k_gemm_mma<C2, C4, true, false><<<dim3(Bq*(NPIX/128), C4/128), 256, SM_GEMM_BYTES>>>(out, m1wh, m1wl, m1_b, ma);
    // m2: dw3x3 + gelu, vectorized, bf16 h/l output
    k_dw3x3_gelu4<<<(Bq*C4*NPIX/4)/256, 256>>>(ma, m2_w, m2_b, mbh, mbl);
    // m3: 256 -> 128 + residual into out (bf16-in HMMA, conversion-free staging)
    k_gemm_mma_bf16in<<<dim3(Bq*(NPIX/128), C2/128), 256, SM_GEMM_BYTES>>>(mbh, mbl, m3wh, m3wl, m3_b, out);
}

// round 16
// speedup vs baseline: 4.2360x; 1.3128x over previous
#include <cuda_runtime.h>
#include <cuda_bf16.h>
#include <math.h>
#include <stdint.h>

#define Bq    4
#define Cc    64
#define Hh    256
#define Ww    256
#define W2    128
#define NPIX  65536   // Hh*Ww
#define NS    32768   // Hh*W2
#define NHEAD 4
#define Dd    16
#define C2    128
#define C4    256

// ---------------- scratch (device globals; no runtime allocation) ----------------
__device__ float g_qs0 [(size_t)Bq*Cc*NS];
__device__ float g_ks0 [(size_t)Bq*Cc*NS];
__device__ float g_vpre[(size_t)Bq*Cc*NPIX];
__device__ float g_qs  [(size_t)Bq*Cc*NS];
__device__ float g_ks  [(size_t)Bq*Cc*NS];
__device__ float g_vs  [(size_t)Bq*Cc*NS];
__device__ float g_kinv[Bq*Cc];
__device__ float g_ctx_part[16*32*16*16];
__device__ float g_ctx[16*256];
__device__ float g_ma[(size_t)Bq*C4*NPIX];
__device__ __nv_bfloat16 g_mbh[(size_t)Bq*C4*NPIX];
__device__ __nv_bfloat16 g_mbl[(size_t)Bq*C4*NPIX];
// bf16 hi/lo staging sources
__device__ __nv_bfloat16 g_attsTh[(size_t)Bq*NS*64];   // [b][n][ci]
__device__ __nv_bfloat16 g_attsTl[(size_t)Bq*NS*64];
__device__ __nv_bfloat16 g_rw5h[25*128*64];            // [tap][co][ci]
__device__ __nv_bfloat16 g_rw5l[25*128*64];
__device__ __nv_bfloat16 g_m1wh[C4*C2];
__device__ __nv_bfloat16 g_m1wl[C4*C2];
__device__ __nv_bfloat16 g_m3wh[C2*C4];
__device__ __nv_bfloat16 g_m3wl[C2*C4];
__device__ __nv_bfloat16 g_q1wh[Cc*Cc];
__device__ __nv_bfloat16 g_q1wl[Cc*Cc];
__device__ __nv_bfloat16 g_k1wh[Cc*Cc];
__device__ __nv_bfloat16 g_k1wl[Cc*Cc];
__device__ __nv_bfloat16 g_v1wh[Cc*Cc];
__device__ __nv_bfloat16 g_v1wl[Cc*Cc];

// tap tables: class 0 = (ky+kx) even (13 taps), class 1 = odd (12 taps)
__device__ __constant__ int8_t TAPS_E[13][2] = {
    {0,0},{0,2},{0,4},{1,1},{1,3},{2,0},{2,2},{2,4},{3,1},{3,3},{4,0},{4,2},{4,4}};
__device__ __constant__ int8_t TAPS_O[12][2] = {
    {0,1},{0,3},{1,0},{1,2},{1,4},{2,1},{2,3},{3,0},{3,2},{3,4},{4,1},{4,3}};

__device__ __forceinline__ float gelu_f(float x){
    return 0.5f * x * (1.0f + erff(x * 0.70710678118654752f));
}

// ================= mma.sync + cp.async helpers (baseline ISA) =================
__device__ __forceinline__ void ldsm4(uint32_t &r0, uint32_t &r1, uint32_t &r2, uint32_t &r3, uint32_t addr){
    asm volatile("ldmatrix.sync.aligned.m8n8.x4.shared.b16 {%0,%1,%2,%3}, [%4];"
                 : "=r"(r0), "=r"(r1), "=r"(r2), "=r"(r3) : "r"(addr));
}
__device__ __forceinline__ void mma16816(float* c, const uint32_t* a, uint32_t b0, uint32_t b1){
    asm volatile(
        "mma.sync.aligned.m16n8k16.row.col.f32.bf16.bf16.f32 "
        "{%0,%1,%2,%3}, {%4,%5,%6,%7}, {%8,%9}, {%0,%1,%2,%3};"
        : "+f"(c[0]), "+f"(c[1]), "+f"(c[2]), "+f"(c[3])
        : "r"(a[0]), "r"(a[1]), "r"(a[2]), "r"(a[3]), "r"(b0), "r"(b1));
}
__device__ __forceinline__ void cpasync16(uint32_t smem_addr, const void* gptr, int src_bytes){
    asm volatile("cp.async.cg.shared.global [%0], [%1], 16, %2;"
                 :: "r"(smem_addr), "l"(gptr), "r"(src_bytes) : "memory");
}
#define CPASYNC_WAIT_ALL() asm volatile("cp.async.commit_group;\ncp.async.wait_group 0;" ::: "memory")
#define CPASYNC_COMMIT()   asm volatile("cp.async.commit_group;" ::: "memory")
#define CPASYNC_WAIT1()    asm volatile("cp.async.wait_group 1;" ::: "memory")
#define CPASYNC_WAIT0()    asm volatile("cp.async.wait_group 0;" ::: "memory")

#define KC    64
#define PAD   72                              // bf16 per smem row (144B stride, 16B aligned)
#define PADB  144
#define SMEM_OP (128*PAD)
#define SM_GEMM_BYTES (4*SMEM_OP*2)           // Ah, Al, Bh, Bl

#define QKV_A_BYTES (64*PADB)                 // 9216
#define QKV_B_BYTES (256*PADB)                // 36864
#define SM_QKV_BYTES (2*QKV_A_BYTES + 2*QKV_B_BYTES)  // 92160

#define C5_A_BYTES (128*PADB)                 // 18432
#define C5_B_ROWS  216
#define C5_B_BYTES (C5_B_ROWS*PADB)           // 31104
#define SM_C5_BYTES (4*C5_A_BYTES + 2*C5_B_BYTES)   // 135936

// ================= merged prep kernel =================
__device__ __forceinline__ void split_store(__nv_bfloat16* h, __nv_bfloat16* l, int i, float v){
    __nv_bfloat16 hh = __float2bfloat16(v);
    h[i] = hh;
    l[i] = __float2bfloat16(v - __bfloat162float(hh));
}
__global__ void k_prep_all(const float* __restrict__ rw, const float* __restrict__ m1w,
                           const float* __restrict__ m3w, const float* __restrict__ q1w,
                           const float* __restrict__ k1w, const float* __restrict__ v1w,
                           __nv_bfloat16* rw5h, __nv_bfloat16* rw5l,
                           __nv_bfloat16* m1wh, __nv_bfloat16* m1wl,
                           __nv_bfloat16* m3wh, __nv_bfloat16* m3wl,
                           __nv_bfloat16* q1wh, __nv_bfloat16* q1wl,
                           __nv_bfloat16* k1wh, __nv_bfloat16* k1wl,
                           __nv_bfloat16* v1wh, __nv_bfloat16* v1wl)
{
    int i = blockIdx.x*256 + threadIdx.x;
    if (i < 204800){
        int tap = i >> 13, rem = i & 8191;
        split_store(rw5h, rw5l, i, rw[(size_t)rem*25 + tap]);
        return;
    }
    int j = i - 204800;
    if (j < 32768){ split_store(m1wh, m1wl, j, m1w[j]); return; }
    j -= 32768;
    if (j < 32768){ split_store(m3wh, m3wl, j, m3w[j]); return; }
    j -= 32768;
    if (j < 4096){ split_store(q1wh, q1wl, j, q1w[j]); return; }
    j -= 4096;
    if (j < 4096){ split_store(k1wh, k1wl, j, k1w[j]); return; }
    j -= 4096;
    if (j < 4096){ split_store(v1wh, v1wl, j, v1w[j]); return; }
}

// ================= qkv 1x1 conv as HMMA GEMM: tile 64co x 256pos, K=64 =================
template<int MODE>
__global__ void __launch_bounds__(256)
k_conv1x1_mma(const float* __restrict__ x,
              const __nv_bfloat16* __restrict__ wh, const __nv_bfloat16* __restrict__ wl,
              const float* __restrict__ bias, float* __restrict__ outp)
{
    const int OSTR = (MODE == 2) ? NPIX : NS;
    extern __shared__ __align__(16) __nv_bfloat16 sm[];
    uint32_t aBaseH = (uint32_t)__cvta_generic_to_shared(sm);
    uint32_t aBaseL = aBaseH + QKV_A_BYTES;
    uint32_t bBaseH = aBaseH + 2*QKV_A_BYTES;
    uint32_t bBaseL = bBaseH + QKV_B_BYTES;
    __nv_bfloat16* Bh = sm + 2*QKV_A_BYTES/2;
    __nv_bfloat16* Bl = sm + (2*QKV_A_BYTES + QKV_B_BYTES)/2;

    int tid = threadIdx.x;
    int b = blockIdx.y;
    int posBase = blockIdx.x*256;
    int lane = tid & 31, warp = tid >> 5;
    int wco = (warp & 1)*32;
    int wpos = (warp >> 1)*64;

    for (int i = tid; i < 512; i += 256){
        int co = i >> 3, ch = i & 7;
        uint32_t d = co*PADB + ch*16;
        cpasync16(aBaseH + d, wh + co*64 + ch*8, 16);
        cpasync16(aBaseL + d, wl + co*64 + ch*8, 16);
    }
    // B-stage: chunk-per-thread transpose (STS.128, conflict-light)
#pragma unroll
    for (int it = 0; it < 8; it++){
        int item = it*8 + warp;                // 64 items: 8 ci-chunks x 8 p-groups
        int cch = item & 7, pg = item >> 3;
        int p = pg*32 + lane;
        int ci0 = cch*8;
        const float* xp;
        if (MODE == 2){
            xp = x + (size_t)(b*Cc + ci0)*NPIX + posBase + p;
        } else {
            int ps = posBase + p;
            int r = ps >> 7;
            int j = ps & 127;
            int o = (MODE == 1) ? (1 - (r & 1)) : (r & 1);
            xp = x + (size_t)(b*Cc + ci0)*NPIX + r*Ww + 2*j + o;
        }
        union { __nv_bfloat16 bb[8]; uint4 u; } hh, ll;
#pragma unroll
        for (int e = 0; e < 8; e++){
            float v = xp[(size_t)e*NPIX];
            __nv_bfloat16 h = __float2bfloat16(v);
            hh.bb[e] = h;
            ll.bb[e] = __float2bfloat16(v - __bfloat162float(h));
        }
        *(uint4*)(Bh + p*PAD + ci0) = hh.u;
        *(uint4*)(Bl + p*PAD + ci0) = ll.u;
    }
    CPASYNC_WAIT_ALL();
    __syncthreads();

    float acc[2][8][4];
#pragma unroll
    for (int mt = 0; mt < 2; mt++)
#pragma unroll
        for (int nt = 0; nt < 8; nt++)
#pragma unroll
            for (int r = 0; r < 4; r++) acc[mt][nt][r] = 0.f;

#pragma unroll
    for (int ks = 0; ks < 4; ks++){
        int k0 = ks*16;
        int g = lane >> 3;
        int rofs = (lane & 7) + ((g & 1) ? 8 : 0);
        int cofs = k0 + ((g >> 1) ? 8 : 0);
        uint32_t ah[2][4], al[2][4];
#pragma unroll
        for (int mt = 0; mt < 2; mt++){
            uint32_t off = ((wco + mt*16 + rofs)*PAD + cofs)*2;
            ldsm4(ah[mt][0], ah[mt][1], ah[mt][2], ah[mt][3], aBaseH + off);
            ldsm4(al[mt][0], al[mt][1], al[mt][2], al[mt][3], aBaseL + off);
        }
        uint32_t bh[4][4], bl[4][4];
#pragma unroll
        for (int ntp = 0; ntp < 4; ntp++){
            uint32_t off = ((wpos + ntp*16 + rofs)*PAD + cofs)*2;
            ldsm4(bh[ntp][0], bh[ntp][1], bh[ntp][2], bh[ntp][3], bBaseH + off);
            ldsm4(bl[ntp][0], bl[ntp][1], bl[ntp][2], bl[ntp][3], bBaseL + off);
        }
#pragma unroll
        for (int mt = 0; mt < 2; mt++){
#pragma unroll
            for (int ntp = 0; ntp < 4; ntp++){
#pragma unroll
                for (int sub = 0; sub < 2; sub++){
                    int nt = ntp*2 + sub;
                    uint32_t h0 = bh[ntp][sub], h1 = bh[ntp][sub+2];
                    uint32_t l0 = bl[ntp][sub], l1 = bl[ntp][sub+2];
                    mma16816(acc[mt][nt], ah[mt], h0, h1);
                    mma16816(acc[mt][nt], ah[mt], l0, l1);
                    mma16816(acc[mt][nt], al[mt], h0, h1);
                }
            }
        }
    }

    {
        int r = lane >> 2, cc = (lane & 3)*2;
#pragma unroll
        for (int mt = 0; mt < 2; mt++){
            int co0 = wco + mt*16 + r;
            float bv0 = bias[co0], bv8 = bias[co0 + 8];
            float* op0 = outp + ((size_t)(b*Cc + co0    ))*OSTR + posBase + wpos + cc;
            float* op8 = outp + ((size_t)(b*Cc + co0 + 8))*OSTR + posBase + wpos + cc;
#pragma unroll
            for (int nt = 0; nt < 8; nt++){
                float2 v0, v8;
                v0.x = acc[mt][nt][0] + bv0;  v0.y = acc[mt][nt][1] + bv0;
                v8.x = acc[mt][nt][2] + bv8;  v8.y = acc[mt][nt][3] + bv8;
                *(float2*)(op0 + nt*8) = v0;
                *(float2*)(op8 + nt*8) = v8;
            }
        }
    }
}

// ================= m1 GEMM (float input, chunk-per-thread B-stage) =================
template<int CIN, int COUT, bool GELU, bool RES>
__global__ void __launch_bounds__(256, 1)
k_gemm_mma(const float* __restrict__ in,
           const __nv_bfloat16* __restrict__ wh, const __nv_bfloat16* __restrict__ wl,
           const float* __restrict__ bias, float* __restrict__ out)
{
    extern __shared__ __align__(16) __nv_bfloat16 sm[];
    __nv_bfloat16* Bh = sm + 2*SMEM_OP;
    __nv_bfloat16* Bl = sm + 3*SMEM_OP;
    uint32_t aBaseH = (uint32_t)__cvta_generic_to_shared(sm);
    uint32_t aBaseL = aBaseH + SMEM_OP*2;
    uint32_t bBaseH = aBaseH + 2*SMEM_OP*2;
    uint32_t bBaseL = aBaseH + 3*SMEM_OP*2;

    int tid = threadIdx.x;
    int b = blockIdx.x >> 9;
    int posBase = (blockIdx.x & 511)*128;
    int coBase = blockIdx.y*128;
    int lane = tid & 31, warp = tid >> 5;
    int wco = (warp & 3)*32;
    int wpos = (warp >> 2)*64;

    float acc[2][8][4];
#pragma unroll
    for (int mt = 0; mt < 2; mt++)
#pragma unroll
        for (int nt = 0; nt < 8; nt++)
#pragma unroll
            for (int r = 0; r < 4; r++) acc[mt][nt][r] = 0.f;

    const int KO = CIN/KC;
#pragma unroll 1
    for (int ko = 0; ko < KO; ko++){
        __syncthreads();
        for (int i = tid; i < 1024; i += 256){
            int co = i >> 3, ch = i & 7;
            uint32_t d = co*PADB + ch*16;
            cpasync16(aBaseH + d, wh + (size_t)(coBase + co)*CIN + ko*KC + ch*8, 16);
            cpasync16(aBaseL + d, wl + (size_t)(coBase + co)*CIN + ko*KC + ch*8, 16);
        }
        // B-stage: chunk-per-thread (8 ci per thread, one STS.128 per buffer)
#pragma unroll
        for (int it = 0; it < 4; it++){
            int item = it*8 + warp;            // 32 items: 8 cch x 4 pg
            int cch = item & 7, pg = item >> 3;
            int p = pg*32 + lane;
            int ci0 = cch*8;
            const float* xp = in + (size_t)(b*CIN + ko*KC + ci0)*NPIX + posBase + p;
            union { __nv_bfloat16 bb[8]; uint4 u; } hh, ll;
#pragma unroll
            for (int e = 0; e < 8; e++){
                float v = xp[(size_t)e*NPIX];
                __nv_bfloat16 h = __float2bfloat16(v);
                hh.bb[e] = h;
                ll.bb[e] = __float2bfloat16(v - __bfloat162float(h));
            }
            *(uint4*)(Bh + p*PAD + ci0) = hh.u;
            *(uint4*)(Bl + p*PAD + ci0) = ll.u;
        }
        CPASYNC_WAIT_ALL();
        __syncthreads();

#pragma unroll
        for (int ks = 0; ks < KC/16; ks++){
            int k0 = ks*16;
            int g = lane >> 3;
            int rofs = (lane & 7) + ((g & 1) ? 8 : 0);
            int cofs = k0 + ((g >> 1) ? 8 : 0);
            uint32_t ah[2][4], al[2][4];
#pragma unroll
            for (int mt = 0; mt < 2; mt++){
                uint32_t off = ((wco + mt*16 + rofs)*PAD + cofs)*2;
                ldsm4(ah[mt][0], ah[mt][1], ah[mt][2], ah[mt][3], aBaseH + off);
                ldsm4(al[mt][0], al[mt][1], al[mt][2], al[mt][3], aBaseL + off);
            }
            uint32_t bh[4][4], bl[4][4];
#pragma unroll
            for (int ntp = 0; ntp < 4; ntp++){
                uint32_t off = ((wpos + ntp*16 + rofs)*PAD + cofs)*2;
                ldsm4(bh[ntp][0], bh[ntp][1], bh[ntp][2], bh[ntp][3], bBaseH + off);
                ldsm4(bl[ntp][0], bl[ntp][1], bl[ntp][2], bl[ntp][3], bBaseL + off);
            }
#pragma unroll
            for (int mt = 0; mt < 2; mt++){
#pragma unroll
                for (int ntp = 0; ntp < 4; ntp++){
#pragma unroll
                    for (int sub = 0; sub < 2; sub++){
                        int nt = ntp*2 + sub;
                        uint32_t h0 = bh[ntp][sub], h1 = bh[ntp][sub+2];
                        uint32_t l0 = bl[ntp][sub], l1 = bl[ntp][sub+2];
                        mma16816(acc[mt][nt], ah[mt], h0, h1);
                        mma16816(acc[mt][nt], ah[mt], l0, l1);
                        mma16816(acc[mt][nt], al[mt], h0, h1);
                    }
                }
            }
        }
    }

    {
        int r = lane >> 2, cc = (lane & 3)*2;
#pragma unroll
        for (int mt = 0; mt < 2; mt++){
            int co0 = coBase + wco + mt*16 + r;
            float bv0 = bias[co0], bv8 = bias[co0 + 8];
            float* op0 = out + ((size_t)(b*COUT + co0    ))*NPIX + posBase + wpos + cc;
            float* op8 = out + ((size_t)(b*COUT + co0 + 8))*NPIX + posBase + wpos + cc;
#pragma unroll
            for (int nt = 0; nt < 8; nt++){
                float2 v0, v8;
                v0.x = acc[mt][nt][0] + bv0;  v0.y = acc[mt][nt][1] + bv0;
                v8.x = acc[mt][nt][2] + bv8;  v8.y = acc[mt][nt][3] + bv8;
                if (GELU){
                    v0.x = gelu_f(v0.x); v0.y = gelu_f(v0.y);
                    v8.x = gelu_f(v8.x); v8.y = gelu_f(v8.y);
                }
                if (RES){
                    float2 o0 = *(const float2*)(op0 + nt*8);
                    float2 o8 = *(const float2*)(op8 + nt*8);
                    v0.x += o0.x; v0.y += o0.y;
                    v8.x += o8.x; v8.y += o8.y;
                }
                *(float2*)(op0 + nt*8) = v0;
                *(float2*)(op8 + nt*8) = v8;
            }
        }
    }
}

// ================= m3 GEMM (bf16 h/l input, chunk-per-thread B-stage) =================
__global__ void __launch_bounds__(256, 1)
k_gemm_mma_bf16in(const __nv_bfloat16* __restrict__ inh, const __nv_bfloat16* __restrict__ inl,
                  const __nv_bfloat16* __restrict__ wh, const __nv_bfloat16* __restrict__ wl,
                  const float* __restrict__ bias, float* __restrict__ out)
{
    const int CIN = C4, COUT = C2;
    extern __shared__ __align__(16) __nv_bfloat16 sm[];
    __nv_bfloat16* Bh = sm + 2*SMEM_OP;
    __nv_bfloat16* Bl = sm + 3*SMEM_OP;
    uint32_t aBaseH = (uint32_t)__cvta_generic_to_shared(sm);
    uint32_t aBaseL = aBaseH + SMEM_OP*2;
    uint32_t bBaseH = aBaseH + 2*SMEM_OP*2;
    uint32_t bBaseL = aBaseH + 3*SMEM_OP*2;

    int tid = threadIdx.x;
    int b = blockIdx.x >> 9;
    int posBase = (blockIdx.x & 511)*128;
    int coBase = blockIdx.y*128;
    int lane = tid & 31, warp = tid >> 5;
    int wco = (warp & 3)*32;
    int wpos = (warp >> 2)*64;

    float acc[2][8][4];
#pragma unroll
    for (int mt = 0; mt < 2; mt++)
#pragma unroll
        for (int nt = 0; nt < 8; nt++)
#pragma unroll
            for (int r = 0; r < 4; r++) acc[mt][nt][r] = 0.f;

    const int KO = CIN/KC;
#pragma unroll 1
    for (int ko = 0; ko < KO; ko++){
        __syncthreads();
        for (int i = tid; i < 1024; i += 256){
            int co = i >> 3, ch = i & 7;
            uint32_t d = co*PADB + ch*16;
            cpasync16(aBaseH + d, wh + (size_t)(coBase + co)*CIN + ko*KC + ch*8, 16);
            cpasync16(aBaseL + d, wl + (size_t)(coBase + co)*CIN + ko*KC + ch*8, 16);
        }
        // B-stage: chunk-per-thread, scalar bf16 loads coalesced across lanes
#pragma unroll
        for (int it = 0; it < 4; it++){
            int item = it*8 + warp;
            int cch = item & 7, pg = item >> 3;
            int p = pg*32 + lane;
            int ci0 = cch*8;
            const __nv_bfloat16* ph = inh + (size_t)(b*CIN + ko*KC + ci0)*NPIX + posBase + p;
            const __nv_bfloat16* pl = inl + (size_t)(b*CIN + ko*KC + ci0)*NPIX + posBase + p;
            union { __nv_bfloat16 bb[8]; uint4 u; } hh, ll;
#pragma unroll
            for (int e = 0; e < 8; e++){
                hh.bb[e] = ph[(size_t)e*NPIX];
                ll.bb[e] = pl[(size_t)e*NPIX];
            }
            *(uint4*)(Bh + p*PAD + ci0) = hh.u;
            *(uint4*)(Bl + p*PAD + ci0) = ll.u;
        }
        CPASYNC_WAIT_ALL();
        __syncthreads();

#pragma unroll
        for (int ks = 0; ks < KC/16; ks++){
            int k0 = ks*16;
            int g = lane >> 3;
            int rofs = (lane & 7) + ((g & 1) ? 8 : 0);
            int cofs = k0 + ((g >> 1) ? 8 : 0);
            uint32_t ah[2][4], al[2][4];
#pragma unroll
            for (int mt = 0; mt < 2; mt++){
                uint32_t off = ((wco + mt*16 + rofs)*PAD + cofs)*2;
                ldsm4(ah[mt][0], ah[mt][1], ah[mt][2], ah[mt][3], aBaseH + off);
                ldsm4(al[mt][0], al[mt][1], al[mt][2], al[mt][3], aBaseL + off);
            }
            uint32_t bh[4][4], bl[4][4];
#pragma unroll
            for (int ntp = 0; ntp < 4; ntp++){
                uint32_t off = ((wpos + ntp*16 + rofs)*PAD + cofs)*2;
                ldsm4(bh[ntp][0], bh[ntp][1], bh[ntp][2], bh[ntp][3], bBaseH + off);
                ldsm4(bl[ntp][0], bl[ntp][1], bl[ntp][2], bl[ntp][3], bBaseL + off);
            }
#pragma unroll
            for (int mt = 0; mt < 2; mt++){
#pragma unroll
                for (int ntp = 0; ntp < 4; ntp++){
#pragma unroll
                    for (int sub = 0; sub < 2; sub++){
                        int nt = ntp*2 + sub;
                        uint32_t h0 = bh[ntp][sub], h1 = bh[ntp][sub+2];
                        uint32_t l0 = bl[ntp][sub], l1 = bl[ntp][sub+2];
                        mma16816(acc[mt][nt], ah[mt], h0, h1);
                        mma16816(acc[mt][nt], ah[mt], l0, l1);
                        mma16816(acc[mt][nt], al[mt], h0, h1);
                    }
                }
            }
        }
    }

    {
        int r = lane >> 2, cc = (lane & 3)*2;
#pragma unroll
        for (int mt = 0; mt < 2; mt++){
            int co0 = coBase + wco + mt*16 + r;
            float bv0 = bias[co0], bv8 = bias[co0 + 8];
            float* op0 = out + ((size_t)(b*COUT + co0    ))*NPIX + posBase + wpos + cc;
            float* op8 = out + ((size_t)(b*COUT + co0 + 8))*NPIX + posBase + wpos + cc;
#pragma unroll
            for (int nt = 0; nt < 8; nt++){
                float2 v0, v8;
                v0.x = acc[mt][nt][0] + bv0;  v0.y = acc[mt][nt][1] + bv0;
                v8.x = acc[mt][nt][2] + bv8;  v8.y = acc[mt][nt][3] + bv8;
                float2 o0 = *(const float2*)(op0 + nt*8);
                float2 o8 = *(const float2*)(op8 + nt*8);
                v0.x += o0.x; v0.y += o0.y;
                v8.x += o8.x; v8.y += o8.y;
                *(float2*)(op0 + nt*8) = v0;
                *(float2*)(op8 + nt*8) = v8;
            }
        }
    }
}

// ================= conv5x5: halo B staged once, A double-buffered pipeline =================
__global__ void __launch_bounds__(256, 1)
k_conv5x5_mma(const __nv_bfloat16* __restrict__ attsTh, const __nv_bfloat16* __restrict__ attsTl,
              const __nv_bfloat16* __restrict__ rw5h, const __nv_bfloat16* __restrict__ rw5l,
              const float* __restrict__ rb, float* __restrict__ out)
{
    extern __shared__ __align__(16) __nv_bfloat16 sm[];
    uint32_t smb = (uint32_t)__cvta_generic_to_shared(sm);
    uint32_t aB0 = smb;
    uint32_t aB1 = smb + 2*C5_A_BYTES;
    uint32_t bBaseH = smb + 4*C5_A_BYTES;
    uint32_t bBaseL = bBaseH + C5_B_BYTES;

    int tid = threadIdx.x;
    int tx = blockIdx.x;
    int z = blockIdx.y;
    int b = z >> 1, pc = z & 1;
    int jBase = (tx & 7)*16;
    int yBase = (tx >> 3)*8;
    int NT = pc ? 12 : 13;
    int lane = tid & 31, warp = tid >> 5;
    int wco = (warp & 3)*32;
    int wpos = (warp >> 2)*64;

    for (int i = tid; i < C5_B_ROWS*8; i += 256){
        int row = i >> 3, ch = i & 7;
        int hy = row/18, hj = row - hy*18;
        int yy = yBase - 2 + hy;
        int jj = jBase - 1 + hj;
        bool inb = ((unsigned)yy < Hh) && ((unsigned)jj < W2);
        size_t go = inb ? (((size_t)b*NS + yy*W2 + jj)*64 + ch*8) : 0;
        int nb = inb ? 16 : 0;
        uint32_t d = row*PADB + ch*16;
        cpasync16(bBaseH + d, attsTh + go, nb);
        cpasync16(bBaseL + d, attsTl + go, nb);
    }
    {
        int tap0 = pc ? (TAPS_O[0][0]*5 + TAPS_O[0][1]) : (TAPS_E[0][0]*5 + TAPS_E[0][1]);
        const __nv_bfloat16* ah = rw5h + tap0*8192;
        const __nv_bfloat16* al = rw5l + tap0*8192;
        for (int i = tid; i < 1024; i += 256){
            int co = i >> 3, ch = i & 7;
            uint32_t d = co*PADB + ch*16;
            cpasync16(aB0 + d,              ah + co*64 + ch*8, 16);
            cpasync16(aB0 + C5_A_BYTES + d, al + co*64 + ch*8, 16);
        }
    }
    CPASYNC_COMMIT();

    int g = lane >> 3;
    int rofs = (lane & 7) + ((g & 1) ? 8 : 0);
    int cofsk = (g >> 1) ? 8 : 0;
    int pyl[4], pjx[4], spar[4];
#pragma unroll
    for (int ntp = 0; ntp < 4; ntp++){
        int p = wpos + ntp*16 + rofs;
        pyl[ntp] = p >> 4;
        pjx[ntp] = p & 15;
        spar[ntp] = (pyl[ntp] & 1) ^ pc;
    }

    float acc[2][8][4];
#pragma unroll
    for (int mt = 0; mt < 2; mt++)
#pragma unroll
        for (int nt = 0; nt < 8; nt++)
#pragma unroll
            for (int r = 0; r < 4; r++) acc[mt][nt][r] = 0.f;

#pragma unroll 1
    for (int t = 0; t < NT; t++){
        int ky = pc ? TAPS_O[t][0] : TAPS_E[t][0];
        int kx = pc ? TAPS_O[t][1] : TAPS_E[t][1];
        if (t + 1 < NT){
            __syncthreads();
            int tapn = pc ? (TAPS_O[t+1][0]*5 + TAPS_O[t+1][1]) : (TAPS_E[t+1][0]*5 + TAPS_E[t+1][1]);
            uint32_t aDst = ((t+1) & 1) ? aB1 : aB0;
            const __nv_bfloat16* ah = rw5h + tapn*8192;
            const __nv_bfloat16* al = rw5l + tapn*8192;
            for (int i = tid; i < 1024; i += 256){
                int co = i >> 3, ch = i & 7;
                uint32_t d = co*PADB + ch*16;
                cpasync16(aDst + d,              ah + co*64 + ch*8, 16);
                cpasync16(aDst + C5_A_BYTES + d, al + co*64 + ch*8, 16);
            }
            CPASYNC_COMMIT();
            CPASYNC_WAIT1();
        } else {
            CPASYNC_WAIT0();
        }
        __syncthreads();

        uint32_t aH = (t & 1) ? aB1 : aB0;
        uint32_t aL = aH + C5_A_BYTES;
        uint32_t bro[4];
#pragma unroll
        for (int ntp = 0; ntp < 4; ntp++){
            int shift = (spar[ntp] + kx - 2) >> 1;
            int hr = (pyl[ntp] + ky)*18 + pjx[ntp] + 1 + shift;
            bro[ntp] = (uint32_t)hr*PADB;
        }

#pragma unroll
        for (int ks = 0; ks < 4; ks++){
            int cofs = ks*16 + cofsk;
            uint32_t ah[2][4], al[2][4];
#pragma unroll
            for (int mt = 0; mt < 2; mt++){
                uint32_t off = ((wco + mt*16 + rofs)*PAD + cofs)*2;
                ldsm4(ah[mt][0], ah[mt][1], ah[mt][2], ah[mt][3], aH + off);
                ldsm4(al[mt][0], al[mt][1], al[mt][2], al[mt][3], aL + off);
            }
            uint32_t bh[4][4], bl[4][4];
#pragma unroll
            for (int ntp = 0; ntp < 4; ntp++){
                uint32_t off = bro[ntp] + (uint32_t)cofs*2;
                ldsm4(bh[ntp][0], bh[ntp][1], bh[ntp][2], bh[ntp][3], bBaseH + off);
                ldsm4(bl[ntp][0], bl[ntp][1], bl[ntp][2], bl[ntp][3], bBaseL + off);
            }
#pragma unroll
            for (int mt = 0; mt < 2; mt++){
#pragma unroll
                for (int ntp = 0; ntp < 4; ntp++){
#pragma unroll
                    for (int sub = 0; sub < 2; sub++){
                        int nt = ntp*2 + sub;
                        uint32_t h0 = bh[ntp][sub], h1 = bh[ntp][sub+2];
                        uint32_t l0 = bl[ntp][sub], l1 = bl[ntp][sub+2];
                        mma16816(acc[mt][nt], ah[mt], h0, h1);
                        mma16816(acc[mt][nt], ah[mt], l0, l1);
                        mma16816(acc[mt][nt], al[mt], h0, h1);
                    }
                }
            }
        }
    }

    {
        int r = lane >> 2, cc = (lane & 3)*2;
#pragma unroll
        for (int mt = 0; mt < 2; mt++){
            int co0 = wco + mt*16 + r;
            float bv0 = rb[co0], bv8 = rb[co0 + 8];
#pragma unroll
            for (int nt = 0; nt < 8; nt++){
                int p = wpos + nt*8 + cc;
                int yl = p >> 4, jx = p & 15;
                int y = yBase + yl;
                int s = (y & 1) ^ pc;
                int x0 = 2*(jBase + jx) + s;
                size_t r0 = ((size_t)(b*C2 + co0    ))*NPIX + y*Ww + x0;
                size_t r8 = ((size_t)(b*C2 + co0 + 8))*NPIX + y*Ww + x0;
                out[r0]     = acc[mt][nt][0] + bv0;
                out[r0 + 2] = acc[mt][nt][1] + bv0;
                out[r8]     = acc[mt][nt][2] + bv8;
                out[r8 + 2] = acc[mt][nt][3] + bv8;
            }
        }
    }
}

// ---------------- K2a: depthwise 3x3 for q/k on squeezed pre-buffer ----------------
__global__ void k_dw3x3_qk(const float* __restrict__ in, const float* __restrict__ w,
                           const float* __restrict__ bias, const float* __restrict__ pbias,
                           float* __restrict__ out, int anchorSel)
{
    int idx = blockIdx.x*256 + threadIdx.x;
    int j = idx & (W2-1);
    int r = (idx >> 7) & (Hh-1);
    int c = (idx >> 15) & (Cc-1);
    int o = anchorSel ? (1 - (r & 1)) : (r & 1);
    int col = 2*j + o;
    const float* ip = in + (size_t)(idx >> 15) * NS;
    const float* wp = w + c*9;

    float s = bias[c] + wp[4]*ip[r*W2 + j];
    float cb = pbias[c];
    float bw = 0.f;
    if (r > 0)       bw += wp[1];
    if (r < Hh-1)    bw += wp[7];
    if (col > 0)     bw += wp[3];
    if (col < Ww-1)  bw += wp[5];
    s += cb * bw;
    int jm = j - 1 + o, jp = j + o;
    if (r > 0){
        const float* rp = ip + (r-1)*W2;
        if ((unsigned)jm < W2) s += wp[0]*rp[jm];
        if ((unsigned)jp < W2) s += wp[2]*rp[jp];
    }
    if (r < Hh-1){
        const float* rp = ip + (r+1)*W2;
        if ((unsigned)jm < W2) s += wp[6]*rp[jm];
        if ((unsigned)jp < W2) s += wp[8]*rp[jp];
    }
    out[idx] = s;
}

// ---------------- K2b: depthwise 3x3 for v ----------------
__global__ void k_dw3x3_v(const float* __restrict__ in, const float* __restrict__ w,
                          const float* __restrict__ bias, float* __restrict__ out)
{
    int idx = blockIdx.x*256 + threadIdx.x;
    int j = idx & (W2-1);
    int r = (idx >> 7) & (Hh-1);
    int c = (idx >> 15) & (Cc-1);
    int col = 2*j + (1 - (r & 1));
    const float* ip = in + (size_t)(idx >> 15) * NPIX;
    const float* wp = w + c*9;
    float s = bias[c];
#pragma unroll
    for (int dy = -1; dy <= 1; dy++){
        int rr = r + dy;
        if ((unsigned)rr < Hh){
#pragma unroll
            for (int dx = -1; dx <= 1; dx++){
                int cc = col + dx;
                if ((unsigned)cc < Ww)
                    s += wp[(dy+1)*3 + (dx+1)] * ip[rr*Ww + cc];
            }
        }
    }
    out[idx] = s;
}

// ---------------- K4: k softmax (max + exp; normalization deferred) ----------------
__global__ void k_softmax_n_exp(float* __restrict__ kk, float* __restrict__ kinv)
{
    int row = blockIdx.x;
    float* p = kk + (size_t)row*NS;
    int tid = threadIdx.x;
    __shared__ float red[256];
    float mx = -1e30f;
    for (int i = tid; i < NS; i += 256) mx = fmaxf(mx, p[i]);
    red[tid] = mx; __syncthreads();
    for (int s = 128; s > 0; s >>= 1){ if (tid < s) red[tid] = fmaxf(red[tid], red[tid+s]); __syncthreads(); }
    mx = red[0]; __syncthreads();
    float sum = 0.f;
    for (int i = tid; i < NS; i += 256){
        float e = __expf(p[i]-mx);
        p[i] = e;
        sum += e;
    }
    red[tid] = sum; __syncthreads();
    for (int s = 128; s > 0; s >>= 1){ if (tid < s) red[tid] += red[tid+s]; __syncthreads(); }
    if (tid == 0) kinv[row] = 1.f/red[0];
}

// ---------------- K5: ctx partials ----------------
__global__ void k_ctx_part(const float* __restrict__ ks, const float* __restrict__ vs,
                           float* __restrict__ part)
{
    int bh = blockIdx.y;
    int chunk = blockIdx.x;
    int e    = threadIdx.x >> 5;
    int lane = threadIdx.x & 31;
    int b = bh >> 2, hd = bh & 3;
    const float* kp = ks + ((size_t)(b*Cc + hd*Dd))*NS;
    const float* vp = vs + ((size_t)(b*Cc + hd*Dd + e))*NS;
    float acc[16];
#pragma unroll
    for (int d = 0; d < 16; d++) acc[d] = 0.f;
    int n0 = chunk*1024;
    for (int n = n0 + lane; n < n0 + 1024; n += 32){
        float vv = vp[n];
#pragma unroll
        for (int d = 0; d < 16; d++) acc[d] += kp[(size_t)d*NS + n]*vv;
    }
#pragma unroll
    for (int d = 0; d < 16; d++){
#pragma unroll
        for (int off = 16; off; off >>= 1) acc[d] += __shfl_xor_sync(0xffffffffu, acc[d], off);
    }
    if (lane == 0){
#pragma unroll
        for (int d = 0; d < 16; d++)
            part[(((size_t)bh*32 + chunk)*16 + e)*16 + d] = acc[d];
    }
}

__global__ void k_ctx_reduce(const float* __restrict__ part, const float* __restrict__ kinv,
                             float* __restrict__ ctx)
{
    int bh = blockIdx.x, t = threadIdx.x;
    int e = t >> 4, d = t & 15;
    float s = 0.f;
    for (int ch = 0; ch < 32; ch++) s += part[(((size_t)bh*32 + ch)*16 + e)*16 + d];
    int b = bh >> 2, hd = bh & 3;
    s *= kinv[b*Cc + hd*Dd + d];
    ctx[bh*256 + d*16 + e] = s;
}

// ---------------- K6: att (q softmax fused), writes transposed bf16 hi/lo ----------------
__global__ void k_att(const float* __restrict__ q, const float* __restrict__ ctx,
                      __nv_bfloat16* __restrict__ attsTh, __nv_bfloat16* __restrict__ attsTl)
{
    int bh = blockIdx.y;
    __shared__ float csm[256];
    for (int i = threadIdx.x; i < 256; i += 128) csm[i] = ctx[bh*256 + i];
    __syncthreads();
    int n = blockIdx.x*128 + threadIdx.x;
    int b = bh >> 2, hd = bh & 3;
    const float* qp = q + ((size_t)(b*Cc + hd*Dd))*NS + n;
    float qv[16];
    float mx = -1e30f;
#pragma unroll
    for (int d = 0; d < 16; d++){ qv[d] = qp[(size_t)d*NS]; mx = fmaxf(mx, qv[d]); }
    float ssum = 0.f;
#pragma unroll
    for (int d = 0; d < 16; d++){ qv[d] = __expf(qv[d]-mx); ssum += qv[d]; }
    float inv = 1.f/ssum;
    float o[16];
#pragma unroll
    for (int e = 0; e < 16; e++) o[e] = 0.f;
#pragma unroll
    for (int d = 0; d < 16; d++){
        float qd = qv[d]*inv;
#pragma unroll
        for (int e = 0; e < 16; e++) o[e] += csm[d*16 + e]*qd;
    }
    size_t base = ((size_t)b*NS + n)*64 + hd*16;
    union { __nv_bfloat16 bb[8]; uint4 u; } h0, h1, l0, l1;
#pragma unroll
    for (int e = 0; e < 8; e++){
        __nv_bfloat16 h = __float2bfloat16(o[e]);
        h0.bb[e] = h;
        l0.bb[e] = __float2bfloat16(o[e] - __bfloat162float(h));
        __nv_bfloat16 hb = __float2bfloat16(o[e+8]);
        h1.bb[e] = hb;
        l1.bb[e] = __float2bfloat16(o[e+8] - __bfloat162float(hb));
    }
    *(uint4*)(attsTh + base)     = h0.u;
    *(uint4*)(attsTh + base + 8) = h1.u;
    *(uint4*)(attsTl + base)     = l0.u;
    *(uint4*)(attsTl + base + 8) = l1.u;
}

// ---------------- K9: m2 depthwise 3x3 + gelu, float4-vectorized, writes bf16 h/l ----------------
__global__ void k_dw3x3_gelu4(const float* __restrict__ in, const float* __restrict__ w,
                              const float* __restrict__ bias,
                              __nv_bfloat16* __restrict__ outh, __nv_bfloat16* __restrict__ outl)
{
    int idx = blockIdx.x*256 + threadIdx.x;        // over B*C4*NPIX/4 = 2^24
    int xq = idx & 63;
    int y  = (idx >> 6) & 255;
    int c  = (idx >> 14) & 255;
    const float* ip = in + (size_t)(idx >> 14) * NPIX;
    const float* wp = w + c*9;
    int x0 = xq*4;

    float bv = bias[c];
    float s0 = bv, s1 = bv, s2 = bv, s3 = bv;
#pragma unroll
    for (int dy = -1; dy <= 1; dy++){
        int rr = y + dy;
        if ((unsigned)rr < Hh){
            const float* rp = ip + rr*Ww;
            float4 m = *(const float4*)(rp + x0);
            float lft = (x0 > 0)      ? rp[x0-1] : 0.f;
            float rgt = (x0+4 < Ww)   ? rp[x0+4] : 0.f;
            float w0 = wp[(dy+1)*3+0], w1 = wp[(dy+1)*3+1], w2 = wp[(dy+1)*3+2];
            s0 += w0*lft + w1*m.x + w2*m.y;
            s1 += w0*m.x + w1*m.y + w2*m.z;
            s2 += w0*m.y + w1*m.z + w2*m.w;
            s3 += w0*m.z + w1*m.w + w2*rgt;
        }
    }
    s0 = gelu_f(s0); s1 = gelu_f(s1); s2 = gelu_f(s2); s3 = gelu_f(s3);
    union { __nv_bfloat16 b[4]; uint2 u; } uh, ul;
    float ss[4] = {s0, s1, s2, s3};
#pragma unroll
    for (int e = 0; e < 4; e++){
        __nv_bfloat16 h = __float2bfloat16(ss[e]);
        uh.b[e] = h;
        ul.b[e] = __float2bfloat16(ss[e] - __bfloat162float(h));
    }
    size_t o = (size_t)(idx >> 14)*NPIX + y*Ww + x0;
    *(uint2*)(outh + o) = uh.u;
    *(uint2*)(outl + o) = ul.u;
}

// ---------------- launch ----------------
extern "C" void kernel_launch(void* const* d_in, const int* in_sizes, int n_in,
                              void* d_out, int out_size)
{
    (void)in_sizes; (void)n_in; (void)out_size;
    const float* x1   = (const float*)d_in[0];
    const float* x2   = (const float*)d_in[1];
    const float* q1_w = (const float*)d_in[2];
    const float* q1_b = (const float*)d_in[3];
    const float* q2_w = (const float*)d_in[4];
    const float* q2_b = (const float*)d_in[5];
    const float* k1_w = (const float*)d_in[6];
    const float* k1_b = (const float*)d_in[7];
    const float* k2_w = (const float*)d_in[8];
    const float* k2_b = (const float*)d_in[9];
    const float* v1_w = (const float*)d_in[10];
    const float* v1_b = (const float*)d_in[11];
    const float* v2_w = (const float*)d_in[12];
    const float* v2_b = (const float*)d_in[13];
    const float* r_w  = (const float*)d_in[14];
    const float* r_b  = (const float*)d_in[15];
    const float* m1_w = (const float*)d_in[16];
    const float* m1_b = (const float*)d_in[17];
    const float* m2_w = (const float*)d_in[18];
    const float* m2_b = (const float*)d_in[19];
    const float* m3_w = (const float*)d_in[20];
    const float* m3_b = (const float*)d_in[21];
    float* out = (float*)d_out;

    float *qs0, *ks0, *vpre, *qs, *ks, *vs, *kinv, *part, *ctx, *ma;
    __nv_bfloat16 *mbh, *mbl;
    __nv_bfloat16 *attsTh, *attsTl, *rw5h, *rw5l, *m1wh, *m1wl, *m3wh, *m3wl;
    __nv_bfloat16 *q1wh, *q1wl, *k1wh, *k1wl, *v1wh, *v1wl;
    cudaGetSymbolAddress((void**)&qs0,  g_qs0);
    cudaGetSymbolAddress((void**)&ks0,  g_ks0);
    cudaGetSymbolAddress((void**)&vpre, g_vpre);
    cudaGetSymbolAddress((void**)&qs,   g_qs);
    cudaGetSymbolAddress((void**)&ks,   g_ks);
    cudaGetSymbolAddress((void**)&vs,   g_vs);
    cudaGetSymbolAddress((void**)&kinv, g_kinv);
    cudaGetSymbolAddress((void**)&part, g_ctx_part);
    cudaGetSymbolAddress((void**)&ctx,  g_ctx);
    cudaGetSymbolAddress((void**)&ma,   g_ma);
    cudaGetSymbolAddress((void**)&mbh,  g_mbh);
    cudaGetSymbolAddress((void**)&mbl,  g_mbl);
    cudaGetSymbolAddress((void**)&attsTh, g_attsTh);
    cudaGetSymbolAddress((void**)&attsTl, g_attsTl);
    cudaGetSymbolAddress((void**)&rw5h, g_rw5h);
    cudaGetSymbolAddress((void**)&rw5l, g_rw5l);
    cudaGetSymbolAddress((void**)&m1wh, g_m1wh);
    cudaGetSymbolAddress((void**)&m1wl, g_m1wl);
    cudaGetSymbolAddress((void**)&m3wh, g_m3wh);
    cudaGetSymbolAddress((void**)&m3wl, g_m3wl);
    cudaGetSymbolAddress((void**)&q1wh, g_q1wh);
    cudaGetSymbolAddress((void**)&q1wl, g_q1wl);
    cudaGetSymbolAddress((void**)&k1wh, g_k1wh);
    cudaGetSymbolAddress((void**)&k1wl, g_k1wl);
    cudaGetSymbolAddress((void**)&v1wh, g_v1wh);
    cudaGetSymbolAddress((void**)&v1wl, g_v1wl);

    cudaFuncSetAttribute(k_gemm_mma<C2, C4, true, false>,
                         cudaFuncAttributeMaxDynamicSharedMemorySize, SM_GEMM_BYTES);
    cudaFuncSetAttribute(k_gemm_mma_bf16in,
                         cudaFuncAttributeMaxDynamicSharedMemorySize, SM_GEMM_BYTES);
    cudaFuncSetAttribute(k_conv5x5_mma,
                         cudaFuncAttributeMaxDynamicSharedMemorySize, SM_C5_BYTES);
    cudaFuncSetAttribute(k_conv1x1_mma<0>,
                         cudaFuncAttributeMaxDynamicSharedMemorySize, SM_QKV_BYTES);
    cudaFuncSetAttribute(k_conv1x1_mma<1>,
                         cudaFuncAttributeMaxDynamicSharedMemorySize, SM_QKV_BYTES);
    cudaFuncSetAttribute(k_conv1x1_mma<2>,
                         cudaFuncAttributeMaxDynamicSharedMemorySize, SM_QKV_BYTES);

    // single merged weight prep
    k_prep_all<<<1104, 256>>>(r_w, m1_w, m3_w, q1_w, k1_w, v1_w,
                              rw5h, rw5l, m1wh, m1wl, m3wh, m3wl,
                              q1wh, q1wl, k1wh, k1wl, v1wh, v1wl);

    // qkv 1x1 convs (HMMA)
    k_conv1x1_mma<0><<<dim3(NS/256,  Bq), 256, SM_QKV_BYTES>>>(x1, q1wh, q1wl, q1_b, qs0);
    k_conv1x1_mma<1><<<dim3(NS/256,  Bq), 256, SM_QKV_BYTES>>>(x1, k1wh, k1wl, k1_b, ks0);
    k_conv1x1_mma<2><<<dim3(NPIX/256, Bq), 256, SM_QKV_BYTES>>>(x2, v1wh, v1wl, v1_b, vpre);

    k_dw3x3_qk<<<(Bq*Cc*NS)/256, 256>>>(qs0, q2_w, q2_b, q1_b, qs, 0);
    k_dw3x3_qk<<<(Bq*Cc*NS)/256, 256>>>(ks0, k2_w, k2_b, k1_b, ks, 1);
    k_dw3x3_v <<<(Bq*Cc*NS)/256, 256>>>(vpre, v2_w, v2_b, vs);

    k_softmax_n_exp<<<Bq*Cc, 256>>>(ks, kinv);

    k_ctx_part<<<dim3(32, Bq*NHEAD), 512>>>(ks, vs, part);
    k_ctx_reduce<<<Bq*NHEAD, 256>>>(part, kinv, ctx);

    k_att<<<dim3(NS/128, Bq*NHEAD), 128>>>(qs, ctx, attsTh, attsTl);

    // conv5x5: halo + pipelined A (HMMA split-bf16)
    k_conv5x5_mma<<<dim3(256, Bq*2), 256, SM_C5_BYTES>>>(attsTh, attsTl, rw5h, rw5l, r_b, out);

    // m1: 128 -> 256 + gelu (HMMA split-bf16)
    k_gemm_mma<C2, C4, true, false><<<dim3(Bq*(NPIX/128), C4/128), 256, SM_GEMM_BYTES>>>(out, m1wh, m1wl, m1_b, ma);
    // m2: dw3x3 + gelu, vectorized, bf16 h/l output
    k_dw3x3_gelu4<<<(Bq*C4*NPIX/4)/256, 256>>>(ma, m2_w, m2_b, mbh, mbl);
    // m3: 256 -> 128 + residual into out (bf16-in HMMA, conversion-free staging)
    k_gemm_mma_bf16in<<<dim3(Bq*(NPIX/128), C2/128), 256, SM_GEMM_BYTES>>>(mbh, mbl, m3wh, m3wl, m3_b, out);
}